// round 1
// baseline (speedup 1.0000x reference)
#include <cuda_runtime.h>
#include <math.h>

#define Bdim 128
#define Tdim 32
#define Edim 512
#define Hdim 512
#define Vdim 10000
#define LFdim 49
#define G4 (4*Hdim)      // 2048
#define MT (Bdim*Tdim)   // 4096

// ---- scratch (allocation-free rule: __device__ globals) ----
__device__ float g_mf[Bdim*Edim];
__device__ float g_h[Bdim*Hdim];
__device__ float g_c[Bdim*Hdim];
__device__ float g_emb[MT*Edim];         // gathered embeddings, row m = t*B+b
__device__ float g_gx[(size_t)Tdim*Bdim*G4]; // precomputed x-projection + bias
__device__ float g_gates[Bdim*G4];       // per-step gates
__device__ float g_hall[(size_t)MT*Hdim];// all hidden states, row m = t*B+b

// ---------------------------------------------------------------------------
// mean pool over LF image features
__global__ void meanpool_kernel(const float* __restrict__ features) {
    int b = blockIdx.x, k = threadIdx.x;  // block 512
    const float* p = features + (size_t)b*LFdim*512 + k;
    float s = 0.f;
    #pragma unroll
    for (int l = 0; l < LFdim; l++) s += p[l*512];
    g_mf[b*512 + k] = s * (1.0f/LFdim);
}

// gather embedding rows into [T*B, E] (row m = t*B + b)
__global__ void gather_kernel(const float* __restrict__ embedding,
                              const int* __restrict__ captions) {
    int m = blockIdx.x;               // 0..4095
    int t = m >> 7, b = m & 127;
    int tok = captions[b*Tdim + t];
    const float4* src = (const float4*)(embedding + (size_t)tok*Edim);
    float4* dst = (float4*)(g_emb + (size_t)m*Edim);
    dst[threadIdx.x] = src[threadIdx.x];  // block = 128 (512 floats)
}

// ---------------------------------------------------------------------------
// Tiled fp32 GEMM: C[M,N] = A[M,K] @ W[N,K]^T + epilogue
//   MODE 0: C[m*N+n] = acc + b1[n] (+ b2[n] if b2)
//   MODE 1: C[m*N+n] = acc + addm[m*N+n]
//   MODE 2: t=m>>7, b=m&127; out[(b*T+t)*V+n] = (t<len[b]) ? acc+b1[n] : 0
// Assumes: M % 64 == 0, K % 16 == 0 (true for all uses). N guarded.
#define BM 64
#define BN 64
#define BK 16
#define PAD 68   // row stride of shared tiles (multiple of 4 for float4 LDS)

template<int MODE>
__global__ __launch_bounds__(256)
void gemm_kernel(const float* __restrict__ A, const float* __restrict__ W,
                 float* __restrict__ C, int M, int N, int K,
                 const float* __restrict__ b1, const float* __restrict__ b2,
                 const float* __restrict__ addm,
                 const int* __restrict__ lengths) {
    __shared__ float As[BK][PAD];
    __shared__ float Ws[BK][PAD];

    int tid = threadIdx.x;
    int n0 = blockIdx.x * BN;
    int m0 = blockIdx.y * BM;

    int lr  = tid >> 2;          // 0..63 (tile row for loads)
    int lc4 = (tid & 3) * 4;     // k offset within tile, float4

    int tx = tid & 15;           // n micro-tile
    int ty = tid >> 4;           // m micro-tile

    float acc[4][4];
    #pragma unroll
    for (int i = 0; i < 4; i++)
        #pragma unroll
        for (int j = 0; j < 4; j++) acc[i][j] = 0.f;

    for (int k0 = 0; k0 < K; k0 += BK) {
        // load A tile [BM x BK] -> As[k][m]
        {
            const float4 v = *(const float4*)(A + (size_t)(m0 + lr)*K + k0 + lc4);
            As[lc4+0][lr] = v.x; As[lc4+1][lr] = v.y;
            As[lc4+2][lr] = v.z; As[lc4+3][lr] = v.w;
        }
        // load W tile [BN x BK] -> Ws[k][n] (guard n<N)
        {
            int n = n0 + lr;
            float4 v = make_float4(0.f,0.f,0.f,0.f);
            if (n < N) v = *(const float4*)(W + (size_t)n*K + k0 + lc4);
            Ws[lc4+0][lr] = v.x; Ws[lc4+1][lr] = v.y;
            Ws[lc4+2][lr] = v.z; Ws[lc4+3][lr] = v.w;
        }
        __syncthreads();

        #pragma unroll
        for (int k = 0; k < BK; k++) {
            float4 a = *(const float4*)&As[k][ty*4];
            float4 w = *(const float4*)&Ws[k][tx*4];
            float av[4] = {a.x, a.y, a.z, a.w};
            float wv[4] = {w.x, w.y, w.z, w.w};
            #pragma unroll
            for (int i = 0; i < 4; i++)
                #pragma unroll
                for (int j = 0; j < 4; j++)
                    acc[i][j] = fmaf(av[i], wv[j], acc[i][j]);
        }
        __syncthreads();
    }

    // epilogue
    #pragma unroll
    for (int i = 0; i < 4; i++) {
        int m = m0 + ty*4 + i;
        #pragma unroll
        for (int j = 0; j < 4; j++) {
            int n = n0 + tx*4 + j;
            if (n >= N) continue;
            float v = acc[i][j];
            if (MODE == 0) {
                v += b1[n];
                if (b2) v += b2[n];
                C[(size_t)m*N + n] = v;
            } else if (MODE == 1) {
                C[(size_t)m*N + n] = v + addm[(size_t)m*N + n];
            } else { // MODE 2: fc with remap + length mask
                int t = m >> 7, b = m & 127;
                float o = (t < lengths[b]) ? (v + b1[n]) : 0.f;
                C[((size_t)b*Tdim + t)*Vdim + n] = o;
            }
        }
    }
}

// ---------------------------------------------------------------------------
__device__ __forceinline__ float sigf(float x) { return 1.0f / (1.0f + expf(-x)); }

__global__ void lstm_cell_kernel(int t) {
    int idx = blockIdx.x * blockDim.x + threadIdx.x;  // 0..65535
    int b = idx >> 9;
    int j = idx & 511;
    const float* g = g_gates + b*G4;
    float gi = g[j];
    float gf = g[512 + j];
    float gg = g[1024 + j];
    float go = g[1536 + j];
    float c = g_c[idx];
    c = sigf(gf)*c + sigf(gi)*tanhf(gg);
    float h = sigf(go)*tanhf(c);
    g_c[idx] = c;
    g_h[idx] = h;
    g_hall[(size_t)t*Bdim*Hdim + idx] = h;
}

// ---------------------------------------------------------------------------
extern "C" void kernel_launch(void* const* d_in, const int* in_sizes, int n_in,
                              void* d_out, int out_size) {
    const float* features  = (const float*)d_in[0];
    const int*   captions  = (const int*)  d_in[1];
    const int*   lengths   = (const int*)  d_in[2];
    const float* embedding = (const float*)d_in[3];
    const float* W_ih      = (const float*)d_in[4];
    const float* W_hh      = (const float*)d_in[5];
    const float* b_ih      = (const float*)d_in[6];
    const float* b_hh      = (const float*)d_in[7];
    const float* fc_w      = (const float*)d_in[8];
    const float* fc_b      = (const float*)d_in[9];
    const float* ihw       = (const float*)d_in[10];
    const float* ihb       = (const float*)d_in[11];
    const float* icw       = (const float*)d_in[12];
    const float* icb       = (const float*)d_in[13];
    float* out = (float*)d_out;

    float *mf, *h, *c, *emb, *gx, *gates, *hall;
    cudaGetSymbolAddress((void**)&mf,    g_mf);
    cudaGetSymbolAddress((void**)&h,     g_h);
    cudaGetSymbolAddress((void**)&c,     g_c);
    cudaGetSymbolAddress((void**)&emb,   g_emb);
    cudaGetSymbolAddress((void**)&gx,    g_gx);
    cudaGetSymbolAddress((void**)&gates, g_gates);
    cudaGetSymbolAddress((void**)&hall,  g_hall);

    // 1. mean pool
    meanpool_kernel<<<Bdim, 512>>>(features);

    // 2. h0 / c0: [128,512] = mf @ init_w^T + init_b
    {
        dim3 grid((Hdim+BN-1)/BN, Bdim/BM);
        gemm_kernel<0><<<grid, 256>>>(mf, ihw, h, Bdim, Hdim, Edim, ihb, nullptr, nullptr, nullptr);
        gemm_kernel<0><<<grid, 256>>>(mf, icw, c, Bdim, Hdim, Edim, icb, nullptr, nullptr, nullptr);
    }

    // 3. gather embeddings, then gx = emb @ W_ih^T + (b_ih + b_hh)
    gather_kernel<<<MT, 128>>>(embedding, captions);
    {
        dim3 grid((G4+BN-1)/BN, MT/BM);
        gemm_kernel<0><<<grid, 256>>>(emb, W_ih, gx, MT, G4, Edim, b_ih, b_hh, nullptr, nullptr);
    }

    // 4. recurrence
    for (int t = 0; t < Tdim; t++) {
        dim3 grid((G4+BN-1)/BN, Bdim/BM);
        gemm_kernel<1><<<grid, 256>>>(h, W_hh, gates, Bdim, G4, Hdim,
                                      nullptr, nullptr, gx + (size_t)t*Bdim*G4, nullptr);
        lstm_cell_kernel<<<(Bdim*Hdim)/256, 256>>>(t);
    }

    // 5. vocab projection with mask + [b,t,v] remap
    {
        dim3 grid((Vdim+BN-1)/BN, MT/BM);
        gemm_kernel<2><<<grid, 256>>>(hall, fc_w, out, MT, Vdim, Hdim,
                                      fc_b, nullptr, nullptr, lengths);
    }
}

// round 3
// speedup vs baseline: 1.7917x; 1.7917x over previous
#include <cuda_runtime.h>
#include <cuda_bf16.h>
#include <cstdint>
#include <math.h>

#define Bdim 128
#define Tdim 32
#define Edim 512
#define Hdim 512
#define Vdim 10000
#define LFdim 49
#define G4 2048
#define MT 4096
#define Kdim 512

// ---------------- scratch (__device__ globals; no allocs allowed) ----------
__device__ float g_mf[Bdim*Edim];
__device__ float g_h[Bdim*Hdim];
__device__ float g_c[Bdim*Hdim];
__device__ float g_gx[(size_t)Tdim*Bdim*G4];
__device__ float g_gates[Bdim*G4];

__device__ __nv_bfloat16 g_hh[Bdim*Hdim],  g_hl[Bdim*Hdim];
__device__ __nv_bfloat16 g_embh[(size_t)MT*Edim], g_embl[(size_t)MT*Edim];
__device__ __nv_bfloat16 g_wihh[(size_t)G4*Edim], g_wihl[(size_t)G4*Edim];
__device__ __nv_bfloat16 g_whhh[(size_t)G4*Hdim], g_whhl[(size_t)G4*Hdim];
__device__ __nv_bfloat16 g_fwh[(size_t)Vdim*Hdim], g_fwl[(size_t)Vdim*Hdim];
__device__ __nv_bfloat16 g_hallh[(size_t)MT*Hdim], g_halll[(size_t)MT*Hdim];

// ---------------- PTX helpers (sm_80-era: legal on base sm_100) ------------
__device__ __forceinline__ uint32_t smem_to_u32(const void* p) {
    uint32_t a;
    asm("{ .reg .u64 t; cvta.to.shared.u64 t, %1; cvt.u32.u64 %0, t; }" : "=r"(a) : "l"(p));
    return a;
}
__device__ __forceinline__ void cp16(uint32_t dst, const void* src, bool pred) {
    int sz = pred ? 16 : 0;
    asm volatile("cp.async.cg.shared.global [%0], [%1], 16, %2;"
                 :: "r"(dst), "l"(src), "r"(sz) : "memory");
}
#define CP_COMMIT() asm volatile("cp.async.commit_group;" ::: "memory")
#define CP_WAIT1()  asm volatile("cp.async.wait_group 1;" ::: "memory")
#define CP_WAIT0()  asm volatile("cp.async.wait_group 0;" ::: "memory")
#define LDSM4(r, addr) \
    asm volatile("ldmatrix.sync.aligned.m8n8.x4.shared.b16 {%0,%1,%2,%3}, [%4];" \
        : "=r"((r)[0]), "=r"((r)[1]), "=r"((r)[2]), "=r"((r)[3]) : "r"(addr))

__device__ __forceinline__ void mma16816(float* c, const uint32_t* a, const uint32_t* b) {
    asm volatile("mma.sync.aligned.m16n8k16.row.col.f32.bf16.bf16.f32 "
        "{%0,%1,%2,%3}, {%4,%5,%6,%7}, {%8,%9}, {%0,%1,%2,%3};"
        : "+f"(c[0]), "+f"(c[1]), "+f"(c[2]), "+f"(c[3])
        : "r"(a[0]), "r"(a[1]), "r"(a[2]), "r"(a[3]), "r"(b[0]), "r"(b[1]));
}

// XOR swizzle for 64B-row tiles: row r, 16B chunk q -> conflict-free for
// both STS.128 stores and ldmatrix reads.
__device__ __forceinline__ uint32_t sw_off(int r, int q) {
    return (uint32_t)(r*64 + ((q ^ ((r >> 1) & 3)) << 4));
}

// ---------------------------------------------------------------------------
// bf16x3 GEMM via mma.sync: C[M,N] = (Ah+Al)[M,512] @ ((Bh+Bl)[N,512])^T
// Block 128x128, BK=32, 8 warps (2m x 4n), warp tile 64x32, double-buffered.
// MODE 0: + b1[n] + b2[n]
// MODE 1: + addm[m*N+n]
// MODE 2: fc: t=m>>7,b=m&127; out[(b*T+t)*V+n] = t<len[b] ? acc+b1[n] : 0
#define TILE_B 8192           // one 128x32 bf16 tile
#define STAGE_B (4*TILE_B)    // Ah,Al,Bh,Bl
#define DSM_BYTES (2*STAGE_B) // 64 KB

template<int MODE>
__global__ void __launch_bounds__(256)
mma_gemm(const __nv_bfloat16* __restrict__ Ah, const __nv_bfloat16* __restrict__ Al,
         const __nv_bfloat16* __restrict__ Bh, const __nv_bfloat16* __restrict__ Bl,
         float* __restrict__ C, int M, int N,
         const float* __restrict__ b1, const float* __restrict__ b2,
         const float* __restrict__ addm, const int* __restrict__ lengths)
{
    extern __shared__ char smem[];
    const uint32_t sbase = smem_to_u32(smem);
    const int tid = threadIdx.x;
    const int lane = tid & 31, wid = tid >> 5;
    const int wm = wid >> 2, wn = wid & 3;          // 2 x 4 warp grid
    const int n0 = blockIdx.x * 128, m0 = blockIdx.y * 128;

    float c[4][4][4];
    #pragma unroll
    for (int i = 0; i < 4; i++)
        #pragma unroll
        for (int j = 0; j < 4; j++)
            { c[i][j][0]=0.f; c[i][j][1]=0.f; c[i][j][2]=0.f; c[i][j][3]=0.f; }

    auto load_stage = [&](int kc, int stage) {
        const int k0 = kc * 32;
        const uint32_t st = sbase + stage * STAGE_B;
        #pragma unroll
        for (int i = 0; i < 2; i++) {
            int chunk = tid + 256*i;
            int r = chunk >> 2, q = chunk & 3;       // row 0..127, 16B quarter
            uint32_t off = sw_off(r, q);
            size_t ao = (size_t)(m0 + r)*Kdim + k0 + q*8;
            cp16(st + off,            Ah + ao, true);
            cp16(st + TILE_B + off,   Al + ao, true);
            int nr = n0 + r;
            bool bp = nr < N;
            size_t bo = (size_t)(bp ? nr : (N-1))*Kdim + k0 + q*8;
            cp16(st + 2*TILE_B + off, Bh + bo, bp);
            cp16(st + 3*TILE_B + off, Bl + bo, bp);
        }
        CP_COMMIT();
    };

    const int NK = Kdim / 32;   // 16
    load_stage(0, 0);
    for (int kc = 0; kc < NK; kc++) {
        int stage = kc & 1;
        if (kc + 1 < NK) { load_stage(kc + 1, stage ^ 1); CP_WAIT1(); }
        else             { CP_WAIT0(); }
        __syncthreads();
        const uint32_t sa = sbase + stage * STAGE_B;

        #pragma unroll
        for (int kh = 0; kh < 2; kh++) {            // two k16 halves of BK=32
            uint32_t aH[4][4], aL[4][4];
            #pragma unroll
            for (int mf = 0; mf < 4; mf++) {
                int row  = wm*64 + mf*16 + (lane & 7) + ((lane >> 3) & 1)*8;
                int kcol = kh*16 + ((lane >> 4) & 1)*8;
                uint32_t off = sw_off(row, kcol >> 3);
                LDSM4(aH[mf], sa + off);
                LDSM4(aL[mf], sa + TILE_B + off);
            }
            uint32_t bH[4][2], bL[4][2];
            #pragma unroll
            for (int np = 0; np < 2; np++) {
                int row  = wn*32 + np*16 + (lane & 7) + ((lane >> 4) & 1)*8;
                int kcol = ((lane >> 3) & 1)*8 + kh*16;
                uint32_t off = sw_off(row, kcol >> 3);
                uint32_t r4[4];
                LDSM4(r4, sa + 2*TILE_B + off);
                bH[np*2][0]=r4[0]; bH[np*2][1]=r4[1];
                bH[np*2+1][0]=r4[2]; bH[np*2+1][1]=r4[3];
                LDSM4(r4, sa + 3*TILE_B + off);
                bL[np*2][0]=r4[0]; bL[np*2][1]=r4[1];
                bL[np*2+1][0]=r4[2]; bL[np*2+1][1]=r4[3];
            }
            #pragma unroll
            for (int mf = 0; mf < 4; mf++)
                #pragma unroll
                for (int nf = 0; nf < 4; nf++) {
                    mma16816(c[mf][nf], aH[mf], bH[nf]);
                    mma16816(c[mf][nf], aH[mf], bL[nf]);
                    mma16816(c[mf][nf], aL[mf], bH[nf]);
                }
        }
        __syncthreads();
    }

    // ---- epilogue: direct float2 stores (4-lane groups give 32B sectors) ----
    #pragma unroll
    for (int mf = 0; mf < 4; mf++) {
        #pragma unroll
        for (int nf = 0; nf < 4; nf++) {
            int m = m0 + wm*64 + mf*16 + (lane >> 2);
            int n = n0 + wn*32 + nf*8 + 2*(lane & 3);
            if (n >= N) continue;
            #pragma unroll
            for (int half = 0; half < 2; half++) {
                int mm = m + half*8;
                float v0 = c[mf][nf][half*2], v1 = c[mf][nf][half*2+1];
                if (MODE == 0) {
                    v0 += b1[n]   + b2[n];
                    v1 += b1[n+1] + b2[n+1];
                    *(float2*)(C + (size_t)mm*N + n) = make_float2(v0, v1);
                } else if (MODE == 1) {
                    const float2 am = *(const float2*)(addm + (size_t)mm*N + n);
                    *(float2*)(C + (size_t)mm*N + n) = make_float2(v0+am.x, v1+am.y);
                } else {
                    int t = mm >> 7, b = mm & 127;
                    if (t < lengths[b]) { v0 += b1[n]; v1 += b1[n+1]; }
                    else                { v0 = 0.f;    v1 = 0.f; }
                    *(float2*)(C + ((size_t)(b*Tdim + t))*Vdim + n) = make_float2(v0, v1);
                }
            }
        }
    }
}

// ---------------------------------------------------------------------------
// small fp32 GEMM for h0/c0 (exact init state; tiny cost)
#define BM 64
#define BN 64
#define BK 16
#define PAD 68
__global__ __launch_bounds__(256)
void gemm_f32(const float* __restrict__ A, const float* __restrict__ W,
              float* __restrict__ C, int M, int N, int K,
              const float* __restrict__ b1) {
    __shared__ float As[BK][PAD];
    __shared__ float Ws[BK][PAD];
    int tid = threadIdx.x;
    int n0 = blockIdx.x * BN, m0 = blockIdx.y * BM;
    int lr = tid >> 2, lc4 = (tid & 3) * 4;
    int tx = tid & 15, ty = tid >> 4;
    float acc[4][4];
    #pragma unroll
    for (int i = 0; i < 4; i++) { acc[i][0]=acc[i][1]=acc[i][2]=acc[i][3]=0.f; }
    for (int k0 = 0; k0 < K; k0 += BK) {
        {
            const float4 v = *(const float4*)(A + (size_t)(m0+lr)*K + k0 + lc4);
            As[lc4+0][lr]=v.x; As[lc4+1][lr]=v.y; As[lc4+2][lr]=v.z; As[lc4+3][lr]=v.w;
        }
        {
            int n = n0 + lr;
            float4 v = make_float4(0,0,0,0);
            if (n < N) v = *(const float4*)(W + (size_t)n*K + k0 + lc4);
            Ws[lc4+0][lr]=v.x; Ws[lc4+1][lr]=v.y; Ws[lc4+2][lr]=v.z; Ws[lc4+3][lr]=v.w;
        }
        __syncthreads();
        #pragma unroll
        for (int k = 0; k < BK; k++) {
            float4 a = *(const float4*)&As[k][ty*4];
            float4 w = *(const float4*)&Ws[k][tx*4];
            float av[4]={a.x,a.y,a.z,a.w}, wv[4]={w.x,w.y,w.z,w.w};
            #pragma unroll
            for (int i=0;i<4;i++)
                #pragma unroll
                for (int j=0;j<4;j++) acc[i][j] = fmaf(av[i], wv[j], acc[i][j]);
        }
        __syncthreads();
    }
    #pragma unroll
    for (int i=0;i<4;i++) {
        int m = m0 + ty*4 + i;
        #pragma unroll
        for (int j=0;j<4;j++) {
            int n = n0 + tx*4 + j;
            if (n < N) C[(size_t)m*N + n] = acc[i][j] + b1[n];
        }
    }
}

// ---------------------------------------------------------------------------
__global__ void meanpool_kernel(const float* __restrict__ features) {
    int b = blockIdx.x, k = threadIdx.x;
    const float* p = features + (size_t)b*LFdim*512 + k;
    float s = 0.f;
    #pragma unroll
    for (int l = 0; l < LFdim; l++) s += p[l*512];
    g_mf[b*512 + k] = s * (1.0f/LFdim);
}

__global__ void split_kernel(const float* __restrict__ s,
                             __nv_bfloat16* __restrict__ hi,
                             __nv_bfloat16* __restrict__ lo, int n) {
    int i = blockIdx.x*256 + threadIdx.x;
    if (i < n) {
        float x = s[i];
        __nv_bfloat16 h = __float2bfloat16(x);
        hi[i] = h;
        lo[i] = __float2bfloat16(x - __bfloat162float(h));
    }
}

__global__ void gather_split_kernel(const float* __restrict__ emb,
                                    const int* __restrict__ cap) {
    int m = blockIdx.x;                 // row m = t*B + b
    int t = m >> 7, b = m & 127;
    int tok = cap[b*Tdim + t];
    const float* src = emb + (size_t)tok*Edim;
    for (int k = threadIdx.x; k < Edim; k += 128) {
        float x = src[k];
        __nv_bfloat16 h = __float2bfloat16(x);
        g_embh[(size_t)m*Edim + k] = h;
        g_embl[(size_t)m*Edim + k] = __float2bfloat16(x - __bfloat162float(h));
    }
}

__device__ __forceinline__ float sigf(float x) { return 1.0f / (1.0f + expf(-x)); }

__global__ void lstm_cell_kernel(int t) {
    int idx = blockIdx.x * blockDim.x + threadIdx.x;  // 0..65535
    int b = idx >> 9, j = idx & 511;
    const float* g = g_gates + b*G4;
    float gi = g[j], gf = g[512 + j], gg = g[1024 + j], go = g[1536 + j];
    float c = g_c[idx];
    c = sigf(gf)*c + sigf(gi)*tanhf(gg);
    float h = sigf(go)*tanhf(c);
    g_c[idx] = c;
    __nv_bfloat16 hh = __float2bfloat16(h);
    __nv_bfloat16 hl = __float2bfloat16(h - __bfloat162float(hh));
    g_hh[idx] = hh; g_hl[idx] = hl;
    size_t o = (size_t)t*(Bdim*Hdim) + idx;           // hall row m = t*B + b
    g_hallh[o] = hh; g_halll[o] = hl;
}

// ---------------------------------------------------------------------------
extern "C" void kernel_launch(void* const* d_in, const int* in_sizes, int n_in,
                              void* d_out, int out_size) {
    const float* features  = (const float*)d_in[0];
    const int*   captions  = (const int*)  d_in[1];
    const int*   lengths   = (const int*)  d_in[2];
    const float* embedding = (const float*)d_in[3];
    const float* W_ih      = (const float*)d_in[4];
    const float* W_hh      = (const float*)d_in[5];
    const float* b_ih      = (const float*)d_in[6];
    const float* b_hh      = (const float*)d_in[7];
    const float* fc_w      = (const float*)d_in[8];
    const float* fc_b      = (const float*)d_in[9];
    const float* ihw       = (const float*)d_in[10];
    const float* ihb       = (const float*)d_in[11];
    const float* icw       = (const float*)d_in[12];
    const float* icb       = (const float*)d_in[13];
    float* out = (float*)d_out;

    float *mf, *h, *c, *gx, *gates;
    __nv_bfloat16 *hh, *hl, *embh, *embl, *wihh, *wihl, *whhh, *whhl, *fwh, *fwl, *hallh, *halll;
    cudaGetSymbolAddress((void**)&mf, g_mf);
    cudaGetSymbolAddress((void**)&h,  g_h);
    cudaGetSymbolAddress((void**)&c,  g_c);
    cudaGetSymbolAddress((void**)&gx, g_gx);
    cudaGetSymbolAddress((void**)&gates, g_gates);
    cudaGetSymbolAddress((void**)&hh, g_hh);   cudaGetSymbolAddress((void**)&hl, g_hl);
    cudaGetSymbolAddress((void**)&embh, g_embh); cudaGetSymbolAddress((void**)&embl, g_embl);
    cudaGetSymbolAddress((void**)&wihh, g_wihh); cudaGetSymbolAddress((void**)&wihl, g_wihl);
    cudaGetSymbolAddress((void**)&whhh, g_whhh); cudaGetSymbolAddress((void**)&whhl, g_whhl);
    cudaGetSymbolAddress((void**)&fwh, g_fwh);   cudaGetSymbolAddress((void**)&fwl, g_fwl);
    cudaGetSymbolAddress((void**)&hallh, g_hallh); cudaGetSymbolAddress((void**)&halll, g_halll);

    static bool attr_done = false;
    cudaFuncSetAttribute(mma_gemm<0>, cudaFuncAttributeMaxDynamicSharedMemorySize, DSM_BYTES);
    cudaFuncSetAttribute(mma_gemm<1>, cudaFuncAttributeMaxDynamicSharedMemorySize, DSM_BYTES);
    cudaFuncSetAttribute(mma_gemm<2>, cudaFuncAttributeMaxDynamicSharedMemorySize, DSM_BYTES);
    (void)attr_done;

    // 1. mean pool + init states (fp32, exact)
    meanpool_kernel<<<Bdim, 512>>>(features);
    {
        dim3 grid(Hdim/BN, Bdim/BM);
        gemm_f32<<<grid, 256>>>(mf, ihw, h, Bdim, Hdim, Edim, ihb);
        gemm_f32<<<grid, 256>>>(mf, icw, c, Bdim, Hdim, Edim, icb);
    }
    split_kernel<<<(Bdim*Hdim+255)/256, 256>>>(h, hh, hl, Bdim*Hdim);

    // 2. operand splits
    gather_split_kernel<<<MT, 128>>>(embedding, captions);
    split_kernel<<<(G4*Edim+255)/256, 256>>>(W_ih, wihh, wihl, G4*Edim);
    split_kernel<<<(G4*Hdim+255)/256, 256>>>(W_hh, whhh, whhl, G4*Hdim);
    split_kernel<<<((size_t)Vdim*Hdim+255)/256, 256>>>(fc_w, fwh, fwl, Vdim*Hdim);

    // 3. gx = emb @ W_ih^T + (b_ih + b_hh)   [4096 x 2048]
    {
        dim3 grid(G4/128, MT/128);
        mma_gemm<0><<<grid, 256, DSM_BYTES>>>(embh, embl, wihh, wihl, gx, MT, G4,
                                              b_ih, b_hh, nullptr, nullptr);
    }

    // 4. recurrence
    for (int t = 0; t < Tdim; t++) {
        dim3 grid(G4/128, 1);
        mma_gemm<1><<<grid, 256, DSM_BYTES>>>(hh, hl, whhh, whhl, gates, Bdim, G4,
                                              nullptr, nullptr, gx + (size_t)t*Bdim*G4, nullptr);
        lstm_cell_kernel<<<(Bdim*Hdim)/256, 256>>>(t);
    }

    // 5. vocab projection with mask + [b,t,v] remap  [4096 x 10000]
    {
        dim3 grid((Vdim + 127)/128, MT/128);
        mma_gemm<2><<<grid, 256, DSM_BYTES>>>(hallh, halll, fwh, fwl, out, MT, Vdim,
                                              fc_b, nullptr, nullptr, lengths);
    }
}

// round 4
// speedup vs baseline: 3.5600x; 1.9870x over previous
#include <cuda_runtime.h>
#include <cuda_bf16.h>
#include <cstdint>
#include <math.h>

#define Bdim 128
#define Tdim 32
#define Edim 512
#define Hdim 512
#define Vdim 10000
#define LFdim 49
#define G4 2048
#define MT 4096
#define Kdim 512

// ---------------- scratch (__device__ globals; no allocs allowed) ----------
__device__ float g_mf[Bdim*Edim];
__device__ float g_h[Bdim*Hdim];
__device__ float g_c[Bdim*Hdim];
__device__ float g_gx[(size_t)MT*G4];          // compact rows
__device__ float g_pbias[G4];                  // permuted b_ih+b_hh

__device__ int g_nact[Tdim];
__device__ int g_off[Tdim+1];
__device__ int g_Mc;
__device__ int g_map[MT];                      // compact row -> (t<<8)|b, -1 pad

__device__ __nv_bfloat16 g_hh0[Bdim*Hdim], g_hl0[Bdim*Hdim];
__device__ __nv_bfloat16 g_hh1[Bdim*Hdim], g_hl1[Bdim*Hdim];
__device__ __nv_bfloat16 g_embh[(size_t)MT*Edim], g_embl[(size_t)MT*Edim];
__device__ __nv_bfloat16 g_wihh[(size_t)G4*Edim], g_wihl[(size_t)G4*Edim]; // permuted
__device__ __nv_bfloat16 g_whhh[(size_t)G4*Hdim], g_whhl[(size_t)G4*Hdim]; // permuted
__device__ __nv_bfloat16 g_fwh[(size_t)Vdim*Hdim], g_fwl[(size_t)Vdim*Hdim];
__device__ __nv_bfloat16 g_hallh[(size_t)MT*Hdim], g_halll[(size_t)MT*Hdim]; // compact

// ---------------- PTX helpers (sm_80-era: legal on base sm_100) ------------
__device__ __forceinline__ uint32_t smem_to_u32(const void* p) {
    uint32_t a;
    asm("{ .reg .u64 t; cvta.to.shared.u64 t, %1; cvt.u32.u64 %0, t; }" : "=r"(a) : "l"(p));
    return a;
}
__device__ __forceinline__ void cp16(uint32_t dst, const void* src, bool pred) {
    int sz = pred ? 16 : 0;
    asm volatile("cp.async.cg.shared.global [%0], [%1], 16, %2;"
                 :: "r"(dst), "l"(src), "r"(sz) : "memory");
}
#define CP_COMMIT() asm volatile("cp.async.commit_group;" ::: "memory")
#define CP_WAIT1()  asm volatile("cp.async.wait_group 1;" ::: "memory")
#define CP_WAIT0()  asm volatile("cp.async.wait_group 0;" ::: "memory")
#define LDSM4(r, addr) \
    asm volatile("ldmatrix.sync.aligned.m8n8.x4.shared.b16 {%0,%1,%2,%3}, [%4];" \
        : "=r"((r)[0]), "=r"((r)[1]), "=r"((r)[2]), "=r"((r)[3]) : "r"(addr))

__device__ __forceinline__ void mma16816(float* c, const uint32_t* a, const uint32_t* b) {
    asm volatile("mma.sync.aligned.m16n8k16.row.col.f32.bf16.bf16.f32 "
        "{%0,%1,%2,%3}, {%4,%5,%6,%7}, {%8,%9}, {%0,%1,%2,%3};"
        : "+f"(c[0]), "+f"(c[1]), "+f"(c[2]), "+f"(c[3])
        : "r"(a[0]), "r"(a[1]), "r"(a[2]), "r"(a[3]), "r"(b[0]), "r"(b[1]));
}

// XOR swizzle for 64B-row tiles: row r, 16B chunk q
__device__ __forceinline__ uint32_t sw_off(int r, int q) {
    return (uint32_t)(r*64 + ((q ^ ((r >> 1) & 3)) << 4));
}

__device__ __forceinline__ float sigf(float x) { return 1.0f / (1.0f + expf(-x)); }

// ---------------------------------------------------------------------------
// setup: n_active(t), offsets, compact row map (lengths sorted descending)
__global__ void setup_kernel(const int* __restrict__ lengths) {
    __shared__ int s_len[Bdim];
    int tid = threadIdx.x;
    if (tid < Bdim) s_len[tid] = lengths[tid];
    __syncthreads();
    if (tid < Tdim) {
        int cnt = 0;
        for (int b = 0; b < Bdim; b++) cnt += (s_len[b] > tid) ? 1 : 0;
        g_nact[tid] = cnt;
    }
    __syncthreads();
    if (tid == 0) {
        int acc = 0;
        for (int t = 0; t < Tdim; t++) { g_off[t] = acc; acc += g_nact[t]; }
        g_off[Tdim] = acc;
        g_Mc = acc;
    }
    __syncthreads();
    int Mc = g_Mc;
    for (int r = tid; r < MT; r += blockDim.x) {
        if (r < Mc) {
            int t = 0;
            while (t < Tdim - 1 && r >= g_off[t+1]) t++;
            g_map[r] = (t << 8) | (r - g_off[t]);
        } else {
            g_map[r] = -1;
        }
    }
}

// ---------------------------------------------------------------------------
// gather embeddings into compact rows (+ zero pad rows of emb & hall)
__global__ void gather_split_kernel(const float* __restrict__ emb,
                                    const int* __restrict__ cap) {
    int r = blockIdx.x;
    int v = g_map[r];
    if (v < 0) {
        for (int k = threadIdx.x; k < Edim; k += 128) {
            size_t o = (size_t)r*Edim + k;
            g_embh[o] = __float2bfloat16(0.f); g_embl[o] = __float2bfloat16(0.f);
            g_hallh[o] = __float2bfloat16(0.f); g_halll[o] = __float2bfloat16(0.f);
        }
        return;
    }
    int t = v >> 8, b = v & 255;
    int tok = cap[b*Tdim + t];
    const float* src = emb + (size_t)tok*Edim;
    for (int k = threadIdx.x; k < Edim; k += 128) {
        float x = src[k];
        __nv_bfloat16 h = __float2bfloat16(x);
        g_embh[(size_t)r*Edim + k] = h;
        g_embl[(size_t)r*Edim + k] = __float2bfloat16(x - __bfloat162float(h));
    }
}

// split W with gate permutation: out row 4j+g <- in row g*512+j
__global__ void split_permute_kernel(const float* __restrict__ W,
                                     __nv_bfloat16* __restrict__ hi,
                                     __nv_bfloat16* __restrict__ lo) {
    int idx = blockIdx.x*256 + threadIdx.x;        // 2048*512 total
    int r = idx >> 9, c = idx & 511;
    int j = r >> 2, g = r & 3;
    float x = W[(size_t)(g*512 + j)*512 + c];
    __nv_bfloat16 h = __float2bfloat16(x);
    hi[(size_t)r*512 + c] = h;
    lo[(size_t)r*512 + c] = __float2bfloat16(x - __bfloat162float(h));
}

__global__ void bias_perm_kernel(const float* __restrict__ b_ih,
                                 const float* __restrict__ b_hh) {
    int r = blockIdx.x*256 + threadIdx.x;          // 2048
    int j = r >> 2, g = r & 3;
    g_pbias[r] = b_ih[g*512 + j] + b_hh[g*512 + j];
}

__global__ void split_kernel(const float* __restrict__ s,
                             __nv_bfloat16* __restrict__ hi,
                             __nv_bfloat16* __restrict__ lo, int n) {
    int i = blockIdx.x*256 + threadIdx.x;
    if (i < n) {
        float x = s[i];
        __nv_bfloat16 h = __float2bfloat16(x);
        hi[i] = h;
        lo[i] = __float2bfloat16(x - __bfloat162float(h));
    }
}

__global__ void meanpool_kernel(const float* __restrict__ features) {
    int b = blockIdx.x, k = threadIdx.x;
    const float* p = features + (size_t)b*LFdim*512 + k;
    float s = 0.f;
    #pragma unroll
    for (int l = 0; l < LFdim; l++) s += p[l*512];
    g_mf[b*512 + k] = s * (1.0f/LFdim);
}

// zero masked output slots (t >= len[b])
__global__ void zerofill_kernel(const int* __restrict__ lengths, float* __restrict__ out) {
    int b = blockIdx.x >> 5, t = blockIdx.x & 31;
    if (t < lengths[b]) return;
    float4* o = (float4*)(out + ((size_t)b*Tdim + t)*Vdim);
    float4 z = make_float4(0.f, 0.f, 0.f, 0.f);
    for (int i = threadIdx.x; i < Vdim/4; i += 256) o[i] = z;
}

// ---------------------------------------------------------------------------
// bf16x3 GEMM via mma.sync: C = (Ah+Al)[M,512] @ ((Bh+Bl)[N,512])^T
// Block 128x128, BK=32, 8 warps (2m x 4n), warp tile 64x32, double-buffered.
// MODE 0: C[m*N+n] = acc + b1[n]            (gx; early-exit m0>=Mc)
// MODE 2: fc via compact map (early-exit m0>=Mc)
#define TILE_B 8192
#define STAGE_B (4*TILE_B)
#define DSM_BYTES (2*STAGE_B)

template<int MODE>
__global__ void __launch_bounds__(256)
mma_gemm(const __nv_bfloat16* __restrict__ Ah, const __nv_bfloat16* __restrict__ Al,
         const __nv_bfloat16* __restrict__ Bh, const __nv_bfloat16* __restrict__ Bl,
         float* __restrict__ C, int M, int N,
         const float* __restrict__ b1)
{
    const int m0 = blockIdx.y * 128;
    if (m0 >= g_Mc) return;
    extern __shared__ char smem[];
    const uint32_t sbase = smem_to_u32(smem);
    const int tid = threadIdx.x;
    const int lane = tid & 31, wid = tid >> 5;
    const int wm = wid >> 2, wn = wid & 3;
    const int n0 = blockIdx.x * 128;

    float c[4][4][4];
    #pragma unroll
    for (int i = 0; i < 4; i++)
        #pragma unroll
        for (int j = 0; j < 4; j++)
            { c[i][j][0]=0.f; c[i][j][1]=0.f; c[i][j][2]=0.f; c[i][j][3]=0.f; }

    auto load_stage = [&](int kc, int stage) {
        const int k0 = kc * 32;
        const uint32_t st = sbase + stage * STAGE_B;
        #pragma unroll
        for (int i = 0; i < 2; i++) {
            int chunk = tid + 256*i;
            int r = chunk >> 2, q = chunk & 3;
            uint32_t off = sw_off(r, q);
            size_t ao = (size_t)(m0 + r)*Kdim + k0 + q*8;
            cp16(st + off,            Ah + ao, true);
            cp16(st + TILE_B + off,   Al + ao, true);
            int nr = n0 + r;
            bool bp = nr < N;
            size_t bo = (size_t)(bp ? nr : (N-1))*Kdim + k0 + q*8;
            cp16(st + 2*TILE_B + off, Bh + bo, bp);
            cp16(st + 3*TILE_B + off, Bl + bo, bp);
        }
        CP_COMMIT();
    };

    const int NK = Kdim / 32;
    load_stage(0, 0);
    for (int kc = 0; kc < NK; kc++) {
        int stage = kc & 1;
        if (kc + 1 < NK) { load_stage(kc + 1, stage ^ 1); CP_WAIT1(); }
        else             { CP_WAIT0(); }
        __syncthreads();
        const uint32_t sa = sbase + stage * STAGE_B;

        #pragma unroll
        for (int kh = 0; kh < 2; kh++) {
            uint32_t aH[4][4], aL[4][4];
            #pragma unroll
            for (int mf = 0; mf < 4; mf++) {
                int row  = wm*64 + mf*16 + (lane & 7) + ((lane >> 3) & 1)*8;
                int kcol = kh*16 + ((lane >> 4) & 1)*8;
                uint32_t off = sw_off(row, kcol >> 3);
                LDSM4(aH[mf], sa + off);
                LDSM4(aL[mf], sa + TILE_B + off);
            }
            uint32_t bH[4][2], bL[4][2];
            #pragma unroll
            for (int np = 0; np < 2; np++) {
                int row  = wn*32 + np*16 + (lane & 7) + ((lane >> 4) & 1)*8;
                int kcol = ((lane >> 3) & 1)*8 + kh*16;
                uint32_t off = sw_off(row, kcol >> 3);
                uint32_t r4[4];
                LDSM4(r4, sa + 2*TILE_B + off);
                bH[np*2][0]=r4[0]; bH[np*2][1]=r4[1];
                bH[np*2+1][0]=r4[2]; bH[np*2+1][1]=r4[3];
                LDSM4(r4, sa + 3*TILE_B + off);
                bL[np*2][0]=r4[0]; bL[np*2][1]=r4[1];
                bL[np*2+1][0]=r4[2]; bL[np*2+1][1]=r4[3];
            }
            #pragma unroll
            for (int mf = 0; mf < 4; mf++)
                #pragma unroll
                for (int nf = 0; nf < 4; nf++) {
                    mma16816(c[mf][nf], aH[mf], bH[nf]);
                    mma16816(c[mf][nf], aH[mf], bL[nf]);
                    mma16816(c[mf][nf], aL[mf], bH[nf]);
                }
        }
        __syncthreads();
    }

    #pragma unroll
    for (int mf = 0; mf < 4; mf++) {
        #pragma unroll
        for (int nf = 0; nf < 4; nf++) {
            int m = m0 + wm*64 + mf*16 + (lane >> 2);
            int n = n0 + wn*32 + nf*8 + 2*(lane & 3);
            if (n >= N) continue;
            #pragma unroll
            for (int half = 0; half < 2; half++) {
                int mm = m + half*8;
                float v0 = c[mf][nf][half*2], v1 = c[mf][nf][half*2+1];
                if (MODE == 0) {
                    v0 += b1[n]; v1 += b1[n+1];
                    *(float2*)(C + (size_t)mm*N + n) = make_float2(v0, v1);
                } else {
                    int v = g_map[mm];
                    if (v >= 0) {
                        int t = v >> 8, b = v & 255;
                        v0 += b1[n]; v1 += b1[n+1];
                        *(float2*)(C + ((size_t)(b*Tdim + t))*Vdim + n) = make_float2(v0, v1);
                    }
                }
            }
        }
    }
}

// ---------------------------------------------------------------------------
// fused recurrent step: gates = h @ Whh'^T + gx(compact); LSTM cell; h split;
// hall append.  Grid (32, 2): 64-col N-slice (16 complete hidden units thanks
// to the 4j+g gate permutation) x 64-row M-tile.  8 warps (2m x 4n), 32x16.
#define SBUF 4096          // one 64x32 bf16 tile
#define SSTG (4*SBUF)      // Ah,Al,Bh,Bl
__global__ void __launch_bounds__(256)
step_kernel(int t) {
    __shared__ char sm[2*SSTG];   // 32KB; reused for gates (64*66*4 = 16.9KB)
    int nact = g_nact[t];
    int m0 = blockIdx.y * 64;
    if (m0 >= nact) return;
    int n0 = blockIdx.x * 64;
    const uint32_t sbase = smem_to_u32(sm);
    int tid = threadIdx.x;
    int lane = tid & 31, wid = tid >> 5;
    int wm = wid >> 2, wn = wid & 3;

    const __nv_bfloat16* Ah = (t & 1) ? g_hh1 : g_hh0;
    const __nv_bfloat16* Al = (t & 1) ? g_hl1 : g_hl0;
    __nv_bfloat16* Oh = (t & 1) ? g_hh0 : g_hh1;
    __nv_bfloat16* Ol = (t & 1) ? g_hl0 : g_hl1;

    float c[2][2][4];
    #pragma unroll
    for (int i = 0; i < 2; i++)
        #pragma unroll
        for (int j = 0; j < 2; j++)
            { c[i][j][0]=0.f; c[i][j][1]=0.f; c[i][j][2]=0.f; c[i][j][3]=0.f; }

    auto load_stage = [&](int kc, int stage) {
        const int k0 = kc * 32;
        const uint32_t st = sbase + stage * SSTG;
        int r = tid >> 2, q = tid & 3;
        uint32_t off = sw_off(r, q);
        size_t ao = (size_t)(m0 + r)*Hdim + k0 + q*8;
        size_t bo = (size_t)(n0 + r)*Hdim + k0 + q*8;
        cp16(st + off,          Ah + ao, true);
        cp16(st + SBUF + off,   Al + ao, true);
        cp16(st + 2*SBUF + off, g_whhh + bo, true);
        cp16(st + 3*SBUF + off, g_whhl + bo, true);
        CP_COMMIT();
    };

    const int NK = Hdim / 32;   // 16
    load_stage(0, 0);
    for (int kc = 0; kc < NK; kc++) {
        int stage = kc & 1;
        if (kc + 1 < NK) { load_stage(kc + 1, stage ^ 1); CP_WAIT1(); }
        else             { CP_WAIT0(); }
        __syncthreads();
        const uint32_t sa = sbase + stage * SSTG;
        #pragma unroll
        for (int kh = 0; kh < 2; kh++) {
            uint32_t aH[2][4], aL[2][4];
            #pragma unroll
            for (int mf = 0; mf < 2; mf++) {
                int row  = wm*32 + mf*16 + (lane & 7) + ((lane >> 3) & 1)*8;
                int kcol = kh*16 + ((lane >> 4) & 1)*8;
                uint32_t off = sw_off(row, kcol >> 3);
                LDSM4(aH[mf], sa + off);
                LDSM4(aL[mf], sa + SBUF + off);
            }
            uint32_t bH[2][2], bL[2][2];
            {
                int row  = wn*16 + (lane & 7) + ((lane >> 4) & 1)*8;
                int kcol = ((lane >> 3) & 1)*8 + kh*16;
                uint32_t off = sw_off(row, kcol >> 3);
                uint32_t r4[4];
                LDSM4(r4, sa + 2*SBUF + off);
                bH[0][0]=r4[0]; bH[0][1]=r4[1]; bH[1][0]=r4[2]; bH[1][1]=r4[3];
                LDSM4(r4, sa + 3*SBUF + off);
                bL[0][0]=r4[0]; bL[0][1]=r4[1]; bL[1][0]=r4[2]; bL[1][1]=r4[3];
            }
            #pragma unroll
            for (int mf = 0; mf < 2; mf++)
                #pragma unroll
                for (int nf = 0; nf < 2; nf++) {
                    mma16816(c[mf][nf], aH[mf], bH[nf]);
                    mma16816(c[mf][nf], aH[mf], bL[nf]);
                    mma16816(c[mf][nf], aL[mf], bH[nf]);
                }
        }
        __syncthreads();
    }

    // gates -> smem (add gx), stride 66 floats
    float* gs = (float*)sm;
    int goff = g_off[t];
    #pragma unroll
    for (int mf = 0; mf < 2; mf++) {
        #pragma unroll
        for (int nf = 0; nf < 2; nf++) {
            int rl = wm*32 + mf*16 + (lane >> 2);
            int nl = wn*16 + nf*8 + 2*(lane & 3);
            #pragma unroll
            for (int half = 0; half < 2; half++) {
                int rr = rl + half*8;
                float2 gx2 = *(const float2*)(g_gx + (size_t)(goff + m0 + rr)*G4 + n0 + nl);
                gs[rr*66 + nl]     = c[mf][nf][half*2]   + gx2.x;
                gs[rr*66 + nl + 1] = c[mf][nf][half*2+1] + gx2.y;
            }
        }
    }
    __syncthreads();

    // cell for the 16 hidden units of this slice
    #pragma unroll
    for (int p = 0; p < 4; p++) {
        int idx = tid + 256*p;             // 1024 (row, unit) pairs
        int row = idx >> 4, u = idx & 15;
        int rg = m0 + row;
        if (rg >= nact) continue;
        float gi = gs[row*66 + u*4 + 0];
        float gf = gs[row*66 + u*4 + 1];
        float gc = gs[row*66 + u*4 + 2];
        float go = gs[row*66 + u*4 + 3];
        int jg = (n0 >> 2) + u;
        int ci = rg*Hdim + jg;
        float cc = g_c[ci];
        cc = sigf(gf)*cc + sigf(gi)*tanhf(gc);
        float hv = sigf(go)*tanhf(cc);
        g_c[ci] = cc;
        __nv_bfloat16 hhi = __float2bfloat16(hv);
        __nv_bfloat16 hlo = __float2bfloat16(hv - __bfloat162float(hhi));
        Oh[ci] = hhi; Ol[ci] = hlo;
        size_t hr = (size_t)(goff + rg)*Hdim + jg;
        g_hallh[hr] = hhi; g_halll[hr] = hlo;
    }
}

// ---------------------------------------------------------------------------
// small fp32 GEMM for h0/c0 (exact init state)
#define BM 64
#define BN 64
#define BK 16
#define PAD 68
__global__ __launch_bounds__(256)
void gemm_f32(const float* __restrict__ A, const float* __restrict__ W,
              float* __restrict__ C, int M, int N, int K,
              const float* __restrict__ b1) {
    __shared__ float As[BK][PAD];
    __shared__ float Ws[BK][PAD];
    int tid = threadIdx.x;
    int n0 = blockIdx.x * BN, m0 = blockIdx.y * BM;
    int lr = tid >> 2, lc4 = (tid & 3) * 4;
    int tx = tid & 15, ty = tid >> 4;
    float acc[4][4];
    #pragma unroll
    for (int i = 0; i < 4; i++) { acc[i][0]=acc[i][1]=acc[i][2]=acc[i][3]=0.f; }
    for (int k0 = 0; k0 < K; k0 += BK) {
        {
            const float4 v = *(const float4*)(A + (size_t)(m0+lr)*K + k0 + lc4);
            As[lc4+0][lr]=v.x; As[lc4+1][lr]=v.y; As[lc4+2][lr]=v.z; As[lc4+3][lr]=v.w;
        }
        {
            int n = n0 + lr;
            float4 v = make_float4(0,0,0,0);
            if (n < N) v = *(const float4*)(W + (size_t)n*K + k0 + lc4);
            Ws[lc4+0][lr]=v.x; Ws[lc4+1][lr]=v.y; Ws[lc4+2][lr]=v.z; Ws[lc4+3][lr]=v.w;
        }
        __syncthreads();
        #pragma unroll
        for (int k = 0; k < BK; k++) {
            float4 a = *(const float4*)&As[k][ty*4];
            float4 w = *(const float4*)&Ws[k][tx*4];
            float av[4]={a.x,a.y,a.z,a.w}, wv[4]={w.x,w.y,w.z,w.w};
            #pragma unroll
            for (int i=0;i<4;i++)
                #pragma unroll
                for (int j=0;j<4;j++) acc[i][j] = fmaf(av[i], wv[j], acc[i][j]);
        }
        __syncthreads();
    }
    #pragma unroll
    for (int i=0;i<4;i++) {
        int m = m0 + ty*4 + i;
        #pragma unroll
        for (int j=0;j<4;j++) {
            int n = n0 + tx*4 + j;
            if (n < N) C[(size_t)m*N + n] = acc[i][j] + b1[n];
        }
    }
}

// ---------------------------------------------------------------------------
extern "C" void kernel_launch(void* const* d_in, const int* in_sizes, int n_in,
                              void* d_out, int out_size) {
    const float* features  = (const float*)d_in[0];
    const int*   captions  = (const int*)  d_in[1];
    const int*   lengths   = (const int*)  d_in[2];
    const float* embedding = (const float*)d_in[3];
    const float* W_ih      = (const float*)d_in[4];
    const float* W_hh      = (const float*)d_in[5];
    const float* b_ih      = (const float*)d_in[6];
    const float* b_hh      = (const float*)d_in[7];
    const float* fc_w      = (const float*)d_in[8];
    const float* fc_b      = (const float*)d_in[9];
    const float* ihw       = (const float*)d_in[10];
    const float* ihb       = (const float*)d_in[11];
    const float* icw       = (const float*)d_in[12];
    const float* icb       = (const float*)d_in[13];
    float* out = (float*)d_out;

    float *mf, *h, *c, *gx, *pbias;
    __nv_bfloat16 *hh0, *hl0, *embh, *embl, *wihh, *wihl, *whhh, *whhl, *fwh, *fwl, *hallh, *halll;
    cudaGetSymbolAddress((void**)&mf, g_mf);
    cudaGetSymbolAddress((void**)&h,  g_h);
    cudaGetSymbolAddress((void**)&c,  g_c);
    cudaGetSymbolAddress((void**)&gx, g_gx);
    cudaGetSymbolAddress((void**)&pbias, g_pbias);
    cudaGetSymbolAddress((void**)&hh0, g_hh0); cudaGetSymbolAddress((void**)&hl0, g_hl0);
    cudaGetSymbolAddress((void**)&embh, g_embh); cudaGetSymbolAddress((void**)&embl, g_embl);
    cudaGetSymbolAddress((void**)&wihh, g_wihh); cudaGetSymbolAddress((void**)&wihl, g_wihl);
    cudaGetSymbolAddress((void**)&whhh, g_whhh); cudaGetSymbolAddress((void**)&whhl, g_whhl);
    cudaGetSymbolAddress((void**)&fwh, g_fwh);   cudaGetSymbolAddress((void**)&fwl, g_fwl);
    cudaGetSymbolAddress((void**)&hallh, g_hallh); cudaGetSymbolAddress((void**)&halll, g_halll);

    cudaFuncSetAttribute(mma_gemm<0>, cudaFuncAttributeMaxDynamicSharedMemorySize, DSM_BYTES);
    cudaFuncSetAttribute(mma_gemm<2>, cudaFuncAttributeMaxDynamicSharedMemorySize, DSM_BYTES);

    // 0. compact row map from lengths
    setup_kernel<<<1, 256>>>(lengths);

    // 1. mean pool + init states (fp32, exact)
    meanpool_kernel<<<Bdim, 512>>>(features);
    {
        dim3 grid(Hdim/BN, Bdim/BM);
        gemm_f32<<<grid, 256>>>(mf, ihw, h, Bdim, Hdim, Edim, ihb);
        gemm_f32<<<grid, 256>>>(mf, icw, c, Bdim, Hdim, Edim, icb);
    }
    split_kernel<<<(Bdim*Hdim+255)/256, 256>>>(h, hh0, hl0, Bdim*Hdim);

    // 2. operand splits (W_ih/W_hh gate-permuted)
    gather_split_kernel<<<MT, 128>>>(embedding, captions);
    split_permute_kernel<<<(G4*Edim)/256, 256>>>(W_ih, wihh, wihl);
    split_permute_kernel<<<(G4*Hdim)/256, 256>>>(W_hh, whhh, whhl);
    bias_perm_kernel<<<G4/256, 256>>>(b_ih, b_hh);
    split_kernel<<<((size_t)Vdim*Hdim+255)/256, 256>>>(fc_w, fwh, fwl, Vdim*Hdim);

    // 3. gx = emb @ W_ih'^T + pbias   (compact rows; tiles past Mc early-exit)
    {
        dim3 grid(G4/128, MT/128);
        mma_gemm<0><<<grid, 256, DSM_BYTES>>>(embh, embl, wihh, wihl, gx, MT, G4, pbias);
    }

    // 4. recurrence: fused GEMM + cell, one launch per step
    for (int t = 0; t < Tdim; t++)
        step_kernel<<<dim3(G4/64, 2), 256>>>(t);

    // 5. zero masked outputs + fc projection over compact rows
    zerofill_kernel<<<Bdim*Tdim, 256>>>(lengths, out);
    {
        dim3 grid((Vdim + 127)/128, MT/128);
        mma_gemm<2><<<grid, 256, DSM_BYTES>>>(hallh, halll, fwh, fwl, out, MT, Vdim, fc_b);
    }
}

// round 6
// speedup vs baseline: 3.8504x; 1.0816x over previous
#include <cuda_runtime.h>
#include <cuda_bf16.h>
#include <cstdint>
#include <math.h>

#define Bdim 128
#define Tdim 32
#define Edim 512
#define Hdim 512
#define Vdim 10000
#define LFdim 49
#define G4 2048
#define MT 4096
#define Kdim 512

// ---------------- scratch (__device__ globals; no allocs allowed) ----------
__device__ float g_c[Bdim*Hdim];
__device__ float g_gx[(size_t)MT*G4];          // compact rows
__device__ float g_pbias[G4];                  // permuted b_ih+b_hh
__device__ float g_ib[1024];                   // stacked ihb|icb

__device__ int g_nact[Tdim];
__device__ int g_off[Tdim+1];
__device__ int g_Mc;
__device__ int g_map[MT];                      // compact row -> (t<<8)|b, -1 pad
__device__ unsigned int g_sync;

__device__ __nv_bfloat16 g_mfh[Bdim*Edim], g_mfl[Bdim*Edim];
__device__ __nv_bfloat16 g_iwh[(size_t)1024*Edim], g_iwl[(size_t)1024*Edim];
__device__ __nv_bfloat16 g_hh0[Bdim*Hdim], g_hl0[Bdim*Hdim];
__device__ __nv_bfloat16 g_hh1[Bdim*Hdim], g_hl1[Bdim*Hdim];
__device__ __nv_bfloat16 g_embh[(size_t)MT*Edim], g_embl[(size_t)MT*Edim];
__device__ __nv_bfloat16 g_wihh[(size_t)G4*Edim], g_wihl[(size_t)G4*Edim]; // permuted
__device__ __nv_bfloat16 g_whhh[(size_t)G4*Hdim], g_whhl[(size_t)G4*Hdim]; // permuted
__device__ __nv_bfloat16 g_fwh[(size_t)Vdim*Hdim], g_fwl[(size_t)Vdim*Hdim];
__device__ __nv_bfloat16 g_hallh[(size_t)MT*Hdim], g_halll[(size_t)MT*Hdim]; // compact

// ---------------- PTX helpers (sm_80-era: legal on base sm_100) ------------
__device__ __forceinline__ uint32_t smem_to_u32(const void* p) {
    uint32_t a;
    asm("{ .reg .u64 t; cvta.to.shared.u64 t, %1; cvt.u32.u64 %0, t; }" : "=r"(a) : "l"(p));
    return a;
}
__device__ __forceinline__ void cp16(uint32_t dst, const void* src, bool pred) {
    int sz = pred ? 16 : 0;
    asm volatile("cp.async.cg.shared.global [%0], [%1], 16, %2;"
                 :: "r"(dst), "l"(src), "r"(sz) : "memory");
}
#define CP_COMMIT() asm volatile("cp.async.commit_group;" ::: "memory")
#define CP_WAIT1()  asm volatile("cp.async.wait_group 1;" ::: "memory")
#define CP_WAIT0()  asm volatile("cp.async.wait_group 0;" ::: "memory")
#define LDSM4(r, addr) \
    asm volatile("ldmatrix.sync.aligned.m8n8.x4.shared.b16 {%0,%1,%2,%3}, [%4];" \
        : "=r"((r)[0]), "=r"((r)[1]), "=r"((r)[2]), "=r"((r)[3]) : "r"(addr))

__device__ __forceinline__ void mma16816(float* c, const uint32_t* a, const uint32_t* b) {
    asm volatile("mma.sync.aligned.m16n8k16.row.col.f32.bf16.bf16.f32 "
        "{%0,%1,%2,%3}, {%4,%5,%6,%7}, {%8,%9}, {%0,%1,%2,%3};"
        : "+f"(c[0]), "+f"(c[1]), "+f"(c[2]), "+f"(c[3])
        : "r"(a[0]), "r"(a[1]), "r"(a[2]), "r"(a[3]), "r"(b[0]), "r"(b[1]));
}

// XOR swizzle for 64B-row tiles: row r, 16B chunk q
__device__ __forceinline__ uint32_t sw_off(int r, int q) {
    return (uint32_t)(r*64 + ((q ^ ((r >> 1) & 3)) << 4));
}

__device__ __forceinline__ float sigf(float x) { return 1.0f / (1.0f + expf(-x)); }

// ---------------------------------------------------------------------------
// setup: n_active(t), offsets, compact row map; resets grid-sync counter
__global__ void setup_kernel(const int* __restrict__ lengths) {
    __shared__ int s_len[Bdim];
    int tid = threadIdx.x;
    if (tid == 0) g_sync = 0u;
    if (tid < Bdim) s_len[tid] = lengths[tid];
    __syncthreads();
    if (tid < Tdim) {
        int cnt = 0;
        for (int b = 0; b < Bdim; b++) cnt += (s_len[b] > tid) ? 1 : 0;
        g_nact[tid] = cnt;
    }
    __syncthreads();
    if (tid == 0) {
        int acc = 0;
        for (int t = 0; t < Tdim; t++) { g_off[t] = acc; acc += g_nact[t]; }
        g_off[Tdim] = acc;
        g_Mc = acc;
    }
    __syncthreads();
    int Mc = g_Mc;
    for (int r = tid; r < MT; r += blockDim.x) {
        if (r < Mc) {
            int t = 0;
            while (t < Tdim - 1 && r >= g_off[t+1]) t++;
            g_map[r] = (t << 8) | (r - g_off[t]);
        } else {
            g_map[r] = -1;
        }
    }
}

// ---------------------------------------------------------------------------
__global__ void gather_split_kernel(const float* __restrict__ emb,
                                    const int* __restrict__ cap) {
    int r = blockIdx.x;
    int v = g_map[r];
    if (v < 0) {
        for (int k = threadIdx.x; k < Edim; k += 128) {
            size_t o = (size_t)r*Edim + k;
            g_embh[o] = __float2bfloat16(0.f); g_embl[o] = __float2bfloat16(0.f);
            g_hallh[o] = __float2bfloat16(0.f); g_halll[o] = __float2bfloat16(0.f);
        }
        return;
    }
    int t = v >> 8, b = v & 255;
    int tok = cap[b*Tdim + t];
    const float* src = emb + (size_t)tok*Edim;
    for (int k = threadIdx.x; k < Edim; k += 128) {
        float x = src[k];
        __nv_bfloat16 h = __float2bfloat16(x);
        g_embh[(size_t)r*Edim + k] = h;
        g_embl[(size_t)r*Edim + k] = __float2bfloat16(x - __bfloat162float(h));
    }
}

// split W with gate permutation: out row 4j+g <- in row g*512+j
__global__ void split_permute_kernel(const float* __restrict__ W,
                                     __nv_bfloat16* __restrict__ hi,
                                     __nv_bfloat16* __restrict__ lo) {
    int idx = blockIdx.x*256 + threadIdx.x;
    int r = idx >> 9, c = idx & 511;
    int j = r >> 2, g = r & 3;
    float x = W[(size_t)(g*512 + j)*512 + c];
    __nv_bfloat16 h = __float2bfloat16(x);
    hi[(size_t)r*512 + c] = h;
    lo[(size_t)r*512 + c] = __float2bfloat16(x - __bfloat162float(h));
}

__global__ void bias_perm_kernel(const float* __restrict__ b_ih,
                                 const float* __restrict__ b_hh) {
    int r = blockIdx.x*256 + threadIdx.x;
    int j = r >> 2, g = r & 3;
    g_pbias[r] = b_ih[g*512 + j] + b_hh[g*512 + j];
}

__global__ void stack_bias_kernel(const float* __restrict__ ihb,
                                  const float* __restrict__ icb) {
    int i = blockIdx.x*256 + threadIdx.x;
    if (i < 1024) g_ib[i] = (i < 512) ? ihb[i] : icb[i - 512];
}

__global__ void split_kernel(const float* __restrict__ s,
                             __nv_bfloat16* __restrict__ hi,
                             __nv_bfloat16* __restrict__ lo, int n) {
    int i = blockIdx.x*256 + threadIdx.x;
    if (i < n) {
        float x = s[i];
        __nv_bfloat16 h = __float2bfloat16(x);
        hi[i] = h;
        lo[i] = __float2bfloat16(x - __bfloat162float(h));
    }
}

// mean pool -> bf16 hi/lo split directly
__global__ void meanpool_kernel(const float* __restrict__ features) {
    int b = blockIdx.x, k = threadIdx.x;
    const float* p = features + (size_t)b*LFdim*512 + k;
    float s = 0.f;
    #pragma unroll
    for (int l = 0; l < LFdim; l++) s += p[l*512];
    s *= (1.0f/LFdim);
    __nv_bfloat16 h = __float2bfloat16(s);
    g_mfh[b*512 + k] = h;
    g_mfl[b*512 + k] = __float2bfloat16(s - __bfloat162float(h));
}

// zero masked output slots (t >= len[b])
__global__ void zerofill_kernel(const int* __restrict__ lengths, float* __restrict__ out) {
    int b = blockIdx.x >> 5, t = blockIdx.x & 31;
    if (t < lengths[b]) return;
    float4* o = (float4*)(out + ((size_t)b*Tdim + t)*Vdim);
    float4 z = make_float4(0.f, 0.f, 0.f, 0.f);
    for (int i = threadIdx.x; i < Vdim/4; i += 256) o[i] = z;
}

// ---------------------------------------------------------------------------
// bf16x3 GEMM via mma.sync: C = (Ah+Al)[M,512] @ ((Bh+Bl)[N,512])^T
// Block 128x128, BK=32, 8 warps (2m x 4n), warp tile 64x32, double-buffered.
// MODE 0: C[m*N+n] = acc + b1[n]                (gx; early-exit m0>=Mc)
// MODE 1: init h0/c0: n<512 -> split-write g_hh0/g_hl0; n>=512 -> g_c (fp32)
// MODE 2: fc via compact map (early-exit m0>=Mc)
#define TILE_B 8192
#define STAGE_B (4*TILE_B)
#define DSM_BYTES (2*STAGE_B)

template<int MODE>
__global__ void __launch_bounds__(256)
mma_gemm(const __nv_bfloat16* __restrict__ Ah, const __nv_bfloat16* __restrict__ Al,
         const __nv_bfloat16* __restrict__ Bh, const __nv_bfloat16* __restrict__ Bl,
         float* __restrict__ C, int M, int N,
         const float* __restrict__ b1)
{
    const int m0 = blockIdx.y * 128;
    if (MODE != 1 && m0 >= g_Mc) return;
    extern __shared__ char smem[];
    const uint32_t sbase = smem_to_u32(smem);
    const int tid = threadIdx.x;
    const int lane = tid & 31, wid = tid >> 5;
    const int wm = wid >> 2, wn = wid & 3;
    const int n0 = blockIdx.x * 128;

    float c[4][4][4];
    #pragma unroll
    for (int i = 0; i < 4; i++)
        #pragma unroll
        for (int j = 0; j < 4; j++)
            { c[i][j][0]=0.f; c[i][j][1]=0.f; c[i][j][2]=0.f; c[i][j][3]=0.f; }

    auto load_stage = [&](int kc, int stage) {
        const int k0 = kc * 32;
        const uint32_t st = sbase + stage * STAGE_B;
        #pragma unroll
        for (int i = 0; i < 2; i++) {
            int chunk = tid + 256*i;
            int r = chunk >> 2, q = chunk & 3;
            uint32_t off = sw_off(r, q);
            int mr = m0 + r;
            bool ap = mr < M;
            size_t ao = (size_t)(ap ? mr : (M-1))*Kdim + k0 + q*8;
            cp16(st + off,            Ah + ao, ap);
            cp16(st + TILE_B + off,   Al + ao, ap);
            int nr = n0 + r;
            bool bp = nr < N;
            size_t bo = (size_t)(bp ? nr : (N-1))*Kdim + k0 + q*8;
            cp16(st + 2*TILE_B + off, Bh + bo, bp);
            cp16(st + 3*TILE_B + off, Bl + bo, bp);
        }
        CP_COMMIT();
    };

    const int NK = Kdim / 32;
    load_stage(0, 0);
    for (int kc = 0; kc < NK; kc++) {
        int stage = kc & 1;
        if (kc + 1 < NK) { load_stage(kc + 1, stage ^ 1); CP_WAIT1(); }
        else             { CP_WAIT0(); }
        __syncthreads();
        const uint32_t sa = sbase + stage * STAGE_B;

        #pragma unroll
        for (int kh = 0; kh < 2; kh++) {
            uint32_t aH[4][4], aL[4][4];
            #pragma unroll
            for (int mf = 0; mf < 4; mf++) {
                int row  = wm*64 + mf*16 + (lane & 7) + ((lane >> 3) & 1)*8;
                int kcol = kh*16 + ((lane >> 4) & 1)*8;
                uint32_t off = sw_off(row, kcol >> 3);
                LDSM4(aH[mf], sa + off);
                LDSM4(aL[mf], sa + TILE_B + off);
            }
            uint32_t bH[4][2], bL[4][2];
            #pragma unroll
            for (int np = 0; np < 2; np++) {
                int row  = wn*32 + np*16 + (lane & 7) + ((lane >> 4) & 1)*8;
                int kcol = ((lane >> 3) & 1)*8 + kh*16;
                uint32_t off = sw_off(row, kcol >> 3);
                uint32_t r4[4];
                LDSM4(r4, sa + 2*TILE_B + off);
                bH[np*2][0]=r4[0]; bH[np*2][1]=r4[1];
                bH[np*2+1][0]=r4[2]; bH[np*2+1][1]=r4[3];
                LDSM4(r4, sa + 3*TILE_B + off);
                bL[np*2][0]=r4[0]; bL[np*2][1]=r4[1];
                bL[np*2+1][0]=r4[2]; bL[np*2+1][1]=r4[3];
            }
            #pragma unroll
            for (int mf = 0; mf < 4; mf++)
                #pragma unroll
                for (int nf = 0; nf < 4; nf++) {
                    mma16816(c[mf][nf], aH[mf], bH[nf]);
                    mma16816(c[mf][nf], aH[mf], bL[nf]);
                    mma16816(c[mf][nf], aL[mf], bH[nf]);
                }
        }
        __syncthreads();
    }

    #pragma unroll
    for (int mf = 0; mf < 4; mf++) {
        #pragma unroll
        for (int nf = 0; nf < 4; nf++) {
            int m = m0 + wm*64 + mf*16 + (lane >> 2);
            int n = n0 + wn*32 + nf*8 + 2*(lane & 3);
            if (n >= N) continue;
            #pragma unroll
            for (int half = 0; half < 2; half++) {
                int mm = m + half*8;
                if (MODE == 1 && mm >= M) continue;
                float v0 = c[mf][nf][half*2], v1 = c[mf][nf][half*2+1];
                if (MODE == 0) {
                    v0 += b1[n]; v1 += b1[n+1];
                    *(float2*)(C + (size_t)mm*N + n) = make_float2(v0, v1);
                } else if (MODE == 1) {
                    v0 += b1[n]; v1 += b1[n+1];
                    if (n < 512) {
                        __nv_bfloat16 h0 = __float2bfloat16(v0);
                        g_hh0[mm*512 + n] = h0;
                        g_hl0[mm*512 + n] = __float2bfloat16(v0 - __bfloat162float(h0));
                        __nv_bfloat16 h1 = __float2bfloat16(v1);
                        g_hh0[mm*512 + n + 1] = h1;
                        g_hl0[mm*512 + n + 1] = __float2bfloat16(v1 - __bfloat162float(h1));
                    } else {
                        g_c[mm*512 + n - 512] = v0;
                        g_c[mm*512 + n - 511] = v1;
                    }
                } else {
                    int v = g_map[mm];
                    if (v >= 0) {
                        int t = v >> 8, b = v & 255;
                        v0 += b1[n]; v1 += b1[n+1];
                        *(float2*)(C + ((size_t)(b*Tdim + t))*Vdim + n) = make_float2(v0, v1);
                    }
                }
            }
        }
    }
}

// ---------------------------------------------------------------------------
// Persistent recurrence: all 32 steps in one launch.
// 64 blocks = 32 gate-col slices (64 gates = 16 hidden units) x 2 m-tiles (64 rows).
// W_hh slice (128 KB) and c slice (4 KB) stay resident in smem.
// Grid sync between steps via atomic counter (all blocks co-resident: 1/SM).
#define PK_WH    0
#define PK_WL    65536
#define PK_AST   131072          // + stage*8192; lo at +4096
#define PK_GATES 147456          // float[64*66]
#define PK_CST   164352          // float[1024]
#define PK_BYTES 168448

__global__ void __launch_bounds__(256)
persist_step_kernel() {
    extern __shared__ char sm[];
    const uint32_t sbase = smem_to_u32(sm);
    const int tid = threadIdx.x;
    const int lane = tid & 31, wid = tid >> 5;
    const int wm = wid >> 2, wn = wid & 3;
    const int nslice = blockIdx.x & 31;
    const int mtile = blockIdx.x >> 5;
    const int n0 = nslice * 64;       // gate-col base
    const int m0 = mtile * 64;        // row (=batch) base

    // preload W_hh slice: 16 chunks of [64 rows x 32 k], hi+lo
    {
        int r = tid >> 2, q = tid & 3;
        #pragma unroll
        for (int kc = 0; kc < 16; kc++) {
            uint32_t off = (uint32_t)(kc*4096) + sw_off(r, q);
            size_t go = (size_t)(n0 + r)*Hdim + kc*32 + q*8;
            cp16(sbase + PK_WH + off, g_whhh + go, true);
            cp16(sbase + PK_WL + off, g_whhl + go, true);
        }
        CP_COMMIT();
    }
    // c slice into smem [row][unit]
    float* cst = (float*)(sm + PK_CST);
    for (int i = tid; i < 1024; i += 256) {
        int r = i >> 4, u = i & 15;
        cst[i] = g_c[(m0 + r)*Hdim + (n0 >> 2) + u];
    }
    CP_WAIT0();
    __syncthreads();

    float* gs = (float*)(sm + PK_GATES);

    for (int t = 0; t < Tdim; t++) {
        const int nact = g_nact[t];
        const __nv_bfloat16* Ah = (t & 1) ? g_hh1 : g_hh0;
        const __nv_bfloat16* Al = (t & 1) ? g_hl1 : g_hl0;
        __nv_bfloat16* Oh = (t & 1) ? g_hh0 : g_hh1;
        __nv_bfloat16* Ol = (t & 1) ? g_hl0 : g_hl1;

        if (m0 < nact) {
            float acc[2][2][4];
            #pragma unroll
            for (int i = 0; i < 2; i++)
                #pragma unroll
                for (int j = 0; j < 2; j++)
                    { acc[i][j][0]=0.f; acc[i][j][1]=0.f; acc[i][j][2]=0.f; acc[i][j][3]=0.f; }

            auto loadA = [&](int kc, int stage) {
                const uint32_t st = sbase + PK_AST + stage*8192;
                int r = tid >> 2, q = tid & 3;
                uint32_t off = sw_off(r, q);
                size_t ao = (size_t)(m0 + r)*Hdim + kc*32 + q*8;
                cp16(st + off,        Ah + ao, true);
                cp16(st + 4096 + off, Al + ao, true);
                CP_COMMIT();
            };
            loadA(0, 0);
            for (int kc = 0; kc < 16; kc++) {
                int stage = kc & 1;
                if (kc + 1 < 16) { loadA(kc + 1, stage ^ 1); CP_WAIT1(); }
                else             { CP_WAIT0(); }
                __syncthreads();
                const uint32_t sa = sbase + PK_AST + stage*8192;
                const uint32_t wbH = sbase + PK_WH + (uint32_t)(kc*4096);
                const uint32_t wbL = sbase + PK_WL + (uint32_t)(kc*4096);
                #pragma unroll
                for (int kh = 0; kh < 2; kh++) {
                    uint32_t aH[2][4], aL[2][4];
                    #pragma unroll
                    for (int mf = 0; mf < 2; mf++) {
                        int row  = wm*32 + mf*16 + (lane & 7) + ((lane >> 3) & 1)*8;
                        int kcol = kh*16 + ((lane >> 4) & 1)*8;
                        uint32_t off = sw_off(row, kcol >> 3);
                        LDSM4(aH[mf], sa + off);
                        LDSM4(aL[mf], sa + 4096 + off);
                    }
                    uint32_t bH[2][2], bL[2][2];
                    {
                        int row  = wn*16 + (lane & 7) + ((lane >> 4) & 1)*8;
                        int kcol = ((lane >> 3) & 1)*8 + kh*16;
                        uint32_t off = sw_off(row, kcol >> 3);
                        uint32_t r4[4];
                        LDSM4(r4, wbH + off);
                        bH[0][0]=r4[0]; bH[0][1]=r4[1]; bH[1][0]=r4[2]; bH[1][1]=r4[3];
                        LDSM4(r4, wbL + off);
                        bL[0][0]=r4[0]; bL[0][1]=r4[1]; bL[1][0]=r4[2]; bL[1][1]=r4[3];
                    }
                    #pragma unroll
                    for (int mf = 0; mf < 2; mf++)
                        #pragma unroll
                        for (int nf = 0; nf < 2; nf++) {
                            mma16816(acc[mf][nf], aH[mf], bH[nf]);
                            mma16816(acc[mf][nf], aH[mf], bL[nf]);
                            mma16816(acc[mf][nf], aL[mf], bH[nf]);
                        }
                }
                __syncthreads();
            }

            // gates + gx -> smem (stride 66)
            const int goff = g_off[t];
            #pragma unroll
            for (int mf = 0; mf < 2; mf++) {
                #pragma unroll
                for (int nf = 0; nf < 2; nf++) {
                    int rl = wm*32 + mf*16 + (lane >> 2);
                    int nl = wn*16 + nf*8 + 2*(lane & 3);
                    #pragma unroll
                    for (int half = 0; half < 2; half++) {
                        int rr = rl + half*8;
                        float2 gx2 = *(const float2*)(g_gx + (size_t)(goff + m0 + rr)*G4 + n0 + nl);
                        gs[rr*66 + nl]     = acc[mf][nf][half*2]   + gx2.x;
                        gs[rr*66 + nl + 1] = acc[mf][nf][half*2+1] + gx2.y;
                    }
                }
            }
            __syncthreads();

            // cell update for this block's 16 hidden units
            #pragma unroll
            for (int p = 0; p < 4; p++) {
                int idx = tid + 256*p;
                int row = idx >> 4, u = idx & 15;
                int rg = m0 + row;
                if (rg < nact) {
                    float gi = gs[row*66 + u*4 + 0];
                    float gf = gs[row*66 + u*4 + 1];
                    float gc = gs[row*66 + u*4 + 2];
                    float go = gs[row*66 + u*4 + 3];
                    float cc = cst[row*16 + u];
                    cc = sigf(gf)*cc + sigf(gi)*tanhf(gc);
                    float hv = sigf(go)*tanhf(cc);
                    cst[row*16 + u] = cc;
                    int jg = (n0 >> 2) + u;
                    __nv_bfloat16 hhi = __float2bfloat16(hv);
                    __nv_bfloat16 hlo = __float2bfloat16(hv - __bfloat162float(hhi));
                    Oh[rg*Hdim + jg] = hhi;
                    Ol[rg*Hdim + jg] = hlo;
                    size_t hr = (size_t)(goff + rg)*Hdim + jg;
                    g_hallh[hr] = hhi;
                    g_halll[hr] = hlo;
                }
            }
        }

        // grid-wide sync (CG-style)
        __syncthreads();
        if (tid == 0) {
            __threadfence();
            atomicAdd(&g_sync, 1u);
            unsigned target = 64u * (unsigned)(t + 1);
            while (atomicAdd(&g_sync, 0u) < target) { __nanosleep(32); }
            __threadfence();
        }
        __syncthreads();
    }
}

// ---------------------------------------------------------------------------
extern "C" void kernel_launch(void* const* d_in, const int* in_sizes, int n_in,
                              void* d_out, int out_size) {
    const float* features  = (const float*)d_in[0];
    const int*   captions  = (const int*)  d_in[1];
    const int*   lengths   = (const int*)  d_in[2];
    const float* embedding = (const float*)d_in[3];
    const float* W_ih      = (const float*)d_in[4];
    const float* W_hh      = (const float*)d_in[5];
    const float* b_ih      = (const float*)d_in[6];
    const float* b_hh      = (const float*)d_in[7];
    const float* fc_w      = (const float*)d_in[8];
    const float* fc_b      = (const float*)d_in[9];
    const float* ihw       = (const float*)d_in[10];
    const float* ihb       = (const float*)d_in[11];
    const float* icw       = (const float*)d_in[12];
    const float* icb       = (const float*)d_in[13];
    float* out = (float*)d_out;

    float *gx, *pbias, *ib;
    __nv_bfloat16 *mfh, *mfl, *iwh, *iwl, *embh, *embl;
    __nv_bfloat16 *wihh, *wihl, *whhh, *whhl, *fwh, *fwl, *hallh, *halll;
    cudaGetSymbolAddress((void**)&gx, g_gx);
    cudaGetSymbolAddress((void**)&pbias, g_pbias);
    cudaGetSymbolAddress((void**)&ib, g_ib);
    cudaGetSymbolAddress((void**)&mfh, g_mfh); cudaGetSymbolAddress((void**)&mfl, g_mfl);
    cudaGetSymbolAddress((void**)&iwh, g_iwh); cudaGetSymbolAddress((void**)&iwl, g_iwl);
    cudaGetSymbolAddress((void**)&embh, g_embh); cudaGetSymbolAddress((void**)&embl, g_embl);
    cudaGetSymbolAddress((void**)&wihh, g_wihh); cudaGetSymbolAddress((void**)&wihl, g_wihl);
    cudaGetSymbolAddress((void**)&whhh, g_whhh); cudaGetSymbolAddress((void**)&whhl, g_whhl);
    cudaGetSymbolAddress((void**)&fwh, g_fwh);   cudaGetSymbolAddress((void**)&fwl, g_fwl);
    cudaGetSymbolAddress((void**)&hallh, g_hallh); cudaGetSymbolAddress((void**)&halll, g_halll);

    cudaFuncSetAttribute(mma_gemm<0>, cudaFuncAttributeMaxDynamicSharedMemorySize, DSM_BYTES);
    cudaFuncSetAttribute(mma_gemm<1>, cudaFuncAttributeMaxDynamicSharedMemorySize, DSM_BYTES);
    cudaFuncSetAttribute(mma_gemm<2>, cudaFuncAttributeMaxDynamicSharedMemorySize, DSM_BYTES);
    cudaFuncSetAttribute(persist_step_kernel, cudaFuncAttributeMaxDynamicSharedMemorySize, PK_BYTES);

    // 0. compact row map + sync-counter reset
    setup_kernel<<<1, 256>>>(lengths);

    // 1. mean pool (split) + stacked init weights/bias + init GEMM (h0 split + c0)
    meanpool_kernel<<<Bdim, 512>>>(features);
    split_kernel<<<(512*512+255)/256, 256>>>(ihw, iwh, iwl, 512*512);
    split_kernel<<<(512*512+255)/256, 256>>>(icw, iwh + 512*512, iwl + 512*512, 512*512);
    stack_bias_kernel<<<4, 256>>>(ihb, icb);
    mma_gemm<1><<<dim3(8, 1), 256, DSM_BYTES>>>(mfh, mfl, iwh, iwl, nullptr, Bdim, 1024, ib);

    // 2. operand splits (W_ih/W_hh gate-permuted)
    gather_split_kernel<<<MT, 128>>>(embedding, captions);
    split_permute_kernel<<<(G4*Edim)/256, 256>>>(W_ih, wihh, wihl);
    split_permute_kernel<<<(G4*Hdim)/256, 256>>>(W_hh, whhh, whhl);
    bias_perm_kernel<<<G4/256, 256>>>(b_ih, b_hh);
    split_kernel<<<((size_t)Vdim*Hdim+255)/256, 256>>>(fc_w, fwh, fwl, Vdim*Hdim);

    // 3. gx = emb @ W_ih'^T + pbias (compact rows)
    {
        dim3 grid(G4/128, MT/128);
        mma_gemm<0><<<grid, 256, DSM_BYTES>>>(embh, embl, wihh, wihl, gx, MT, G4, pbias);
    }

    // 4. full recurrence in ONE persistent launch
    persist_step_kernel<<<64, 256, PK_BYTES>>>();

    // 5. zero masked outputs + fc projection over compact rows
    zerofill_kernel<<<Bdim*Tdim, 256>>>(lengths, out);
    {
        dim3 grid((Vdim + 127)/128, MT/128);
        mma_gemm<2><<<grid, 256, DSM_BYTES>>>(hallh, halll, fwh, fwl, out, MT, Vdim, fc_b);
    }
}

// round 7
// speedup vs baseline: 4.3191x; 1.1217x over previous
#include <cuda_runtime.h>
#include <cuda_bf16.h>
#include <cuda_fp16.h>
#include <cstdint>
#include <math.h>

#define Bdim 128
#define Tdim 32
#define Edim 512
#define Hdim 512
#define Vdim 10000
#define LFdim 49
#define G4 2048
#define MT 4096
#define Kdim 512

// ---------------- scratch (__device__ globals; no allocs allowed) ----------
__device__ float g_c[Bdim*Hdim];
__device__ float g_gx[(size_t)MT*G4];          // compact rows
__device__ float g_pbias[G4];                  // permuted b_ih+b_hh
__device__ float g_ib[1024];                   // stacked ihb|icb

__device__ int g_nact[Tdim];
__device__ int g_off[Tdim+1];
__device__ int g_Mc;
__device__ int g_map[MT];                      // compact row -> (t<<8)|b, -1 pad
__device__ unsigned int g_sync;

__device__ __nv_bfloat16 g_mfh[Bdim*Edim], g_mfl[Bdim*Edim];
__device__ __nv_bfloat16 g_iwh[(size_t)1024*Edim], g_iwl[(size_t)1024*Edim];
__device__ __nv_bfloat16 g_hh0[Bdim*Hdim], g_hl0[Bdim*Hdim];
__device__ __nv_bfloat16 g_hh1[Bdim*Hdim], g_hl1[Bdim*Hdim];
__device__ __nv_bfloat16 g_embh[(size_t)MT*Edim], g_embl[(size_t)MT*Edim];
__device__ __nv_bfloat16 g_wihh[(size_t)G4*Edim], g_wihl[(size_t)G4*Edim]; // permuted
__device__ __nv_bfloat16 g_whhh[(size_t)G4*Hdim], g_whhl[(size_t)G4*Hdim]; // permuted
__device__ __half g_fwh16[(size_t)Vdim*Hdim], g_fwl16[(size_t)Vdim*Hdim]; // 64x prescaled
__device__ __half g_hall16[(size_t)MT*Hdim];   // compact, fp16

// ---------------- PTX helpers (sm_80-era: legal on base sm_100) ------------
__device__ __forceinline__ uint32_t smem_to_u32(const void* p) {
    uint32_t a;
    asm("{ .reg .u64 t; cvta.to.shared.u64 t, %1; cvt.u32.u64 %0, t; }" : "=r"(a) : "l"(p));
    return a;
}
__device__ __forceinline__ void cp16(uint32_t dst, const void* src, bool pred) {
    int sz = pred ? 16 : 0;
    asm volatile("cp.async.cg.shared.global [%0], [%1], 16, %2;"
                 :: "r"(dst), "l"(src), "r"(sz) : "memory");
}
#define CP_COMMIT() asm volatile("cp.async.commit_group;" ::: "memory")
#define CP_WAIT1()  asm volatile("cp.async.wait_group 1;" ::: "memory")
#define CP_WAIT0()  asm volatile("cp.async.wait_group 0;" ::: "memory")
#define LDSM4(r, addr) \
    asm volatile("ldmatrix.sync.aligned.m8n8.x4.shared.b16 {%0,%1,%2,%3}, [%4];" \
        : "=r"((r)[0]), "=r"((r)[1]), "=r"((r)[2]), "=r"((r)[3]) : "r"(addr))

__device__ __forceinline__ void mma16816(float* c, const uint32_t* a, const uint32_t* b) {
    asm volatile("mma.sync.aligned.m16n8k16.row.col.f32.bf16.bf16.f32 "
        "{%0,%1,%2,%3}, {%4,%5,%6,%7}, {%8,%9}, {%0,%1,%2,%3};"
        : "+f"(c[0]), "+f"(c[1]), "+f"(c[2]), "+f"(c[3])
        : "r"(a[0]), "r"(a[1]), "r"(a[2]), "r"(a[3]), "r"(b[0]), "r"(b[1]));
}
__device__ __forceinline__ void mma16816h(float* c, const uint32_t* a, const uint32_t* b) {
    asm volatile("mma.sync.aligned.m16n8k16.row.col.f32.f16.f16.f32 "
        "{%0,%1,%2,%3}, {%4,%5,%6,%7}, {%8,%9}, {%0,%1,%2,%3};"
        : "+f"(c[0]), "+f"(c[1]), "+f"(c[2]), "+f"(c[3])
        : "r"(a[0]), "r"(a[1]), "r"(a[2]), "r"(a[3]), "r"(b[0]), "r"(b[1]));
}

// XOR swizzle for 64B-row tiles: row r, 16B chunk q
__device__ __forceinline__ uint32_t sw_off(int r, int q) {
    return (uint32_t)(r*64 + ((q ^ ((r >> 1) & 3)) << 4));
}

__device__ __forceinline__ float sigf(float x) { return 1.0f / (1.0f + expf(-x)); }

__device__ __forceinline__ uint32_t pack_bf2(float a, float b) {
    __nv_bfloat162 v = __floats2bfloat162_rn(a, b);
    return *(uint32_t*)&v;
}
__device__ __forceinline__ uint32_t pack_h2(float a, float b) {
    __half2 v = __floats2half2_rn(a, b);
    return *(uint32_t*)&v;
}

// ---------------------------------------------------------------------------
// setup: n_active(t), offsets, compact row map, permuted/stacked biases
__global__ void setup_kernel(const int* __restrict__ lengths,
                             const float* __restrict__ b_ih,
                             const float* __restrict__ b_hh,
                             const float* __restrict__ ihb,
                             const float* __restrict__ icb) {
    __shared__ int s_len[Bdim];
    int tid = threadIdx.x;
    if (tid == 0) g_sync = 0u;
    if (tid < Bdim) s_len[tid] = lengths[tid];
    __syncthreads();
    if (tid < Tdim) {
        int cnt = 0;
        for (int b = 0; b < Bdim; b++) cnt += (s_len[b] > tid) ? 1 : 0;
        g_nact[tid] = cnt;
    }
    __syncthreads();
    if (tid == 0) {
        int acc = 0;
        for (int t = 0; t < Tdim; t++) { g_off[t] = acc; acc += g_nact[t]; }
        g_off[Tdim] = acc;
        g_Mc = acc;
    }
    __syncthreads();
    int Mc = g_Mc;
    for (int r = tid; r < MT; r += 256) {
        if (r < Mc) {
            int t = 0;
            while (t < Tdim - 1 && r >= g_off[t+1]) t++;
            g_map[r] = (t << 8) | (r - g_off[t]);
        } else {
            g_map[r] = -1;
        }
    }
    for (int i = tid; i < G4; i += 256) {
        int j = i >> 2, g = i & 3;
        g_pbias[i] = b_ih[g*512 + j] + b_hh[g*512 + j];
    }
    for (int i = tid; i < 1024; i += 256)
        g_ib[i] = (i < 512) ? ihb[i] : icb[i - 512];
}

// ---------------------------------------------------------------------------
// gather embeddings into compact rows (vectorized; zero pads emb & hall16)
__global__ void gather_split_kernel(const float* __restrict__ emb,
                                    const int* __restrict__ cap) {
    int r = blockIdx.x;
    int v = g_map[r];
    int c4 = threadIdx.x * 4;          // 128 threads x 4 = 512
    if (v < 0) {
        uint2 z = make_uint2(0u, 0u);
        *(uint2*)(g_embh + (size_t)r*Edim + c4) = z;
        *(uint2*)(g_embl + (size_t)r*Edim + c4) = z;
        *(uint2*)(g_hall16 + (size_t)r*Hdim + c4) = z;
        return;
    }
    int t = v >> 8, b = v & 255;
    int tok = cap[b*Tdim + t];
    float4 x = *(const float4*)(emb + (size_t)tok*Edim + c4);
    float hx = __bfloat162float(__float2bfloat16(x.x));
    float hy = __bfloat162float(__float2bfloat16(x.y));
    float hz = __bfloat162float(__float2bfloat16(x.z));
    float hw = __bfloat162float(__float2bfloat16(x.w));
    uint2 hi = make_uint2(pack_bf2(x.x, x.y), pack_bf2(x.z, x.w));
    uint2 lo = make_uint2(pack_bf2(x.x - hx, x.y - hy), pack_bf2(x.z - hz, x.w - hw));
    *(uint2*)(g_embh + (size_t)r*Edim + c4) = hi;
    *(uint2*)(g_embl + (size_t)r*Edim + c4) = lo;
}

// split W with gate permutation, vectorized: out row 4j+g <- in row g*512+j
__global__ void split_permute_kernel(const float* __restrict__ W,
                                     __nv_bfloat16* __restrict__ hi,
                                     __nv_bfloat16* __restrict__ lo) {
    int idx = blockIdx.x*256 + threadIdx.x;   // 2048*128 total
    int r = idx >> 7, c4 = (idx & 127) * 4;
    int j = r >> 2, g = r & 3;
    float4 x = *(const float4*)(W + (size_t)(g*512 + j)*512 + c4);
    float hx = __bfloat162float(__float2bfloat16(x.x));
    float hy = __bfloat162float(__float2bfloat16(x.y));
    float hz = __bfloat162float(__float2bfloat16(x.z));
    float hw = __bfloat162float(__float2bfloat16(x.w));
    *(uint2*)(hi + (size_t)r*512 + c4) = make_uint2(pack_bf2(x.x, x.y), pack_bf2(x.z, x.w));
    *(uint2*)(lo + (size_t)r*512 + c4) =
        make_uint2(pack_bf2(x.x - hx, x.y - hy), pack_bf2(x.z - hz, x.w - hw));
}

// vectorized bf16 split (init weights)
__global__ void split4_bf16(const float* __restrict__ s,
                            __nv_bfloat16* __restrict__ hi,
                            __nv_bfloat16* __restrict__ lo, int n4) {
    int i = blockIdx.x*256 + threadIdx.x;
    if (i >= n4) return;
    float4 x = ((const float4*)s)[i];
    float hx = __bfloat162float(__float2bfloat16(x.x));
    float hy = __bfloat162float(__float2bfloat16(x.y));
    float hz = __bfloat162float(__float2bfloat16(x.z));
    float hw = __bfloat162float(__float2bfloat16(x.w));
    ((uint2*)hi)[i] = make_uint2(pack_bf2(x.x, x.y), pack_bf2(x.z, x.w));
    ((uint2*)lo)[i] = make_uint2(pack_bf2(x.x - hx, x.y - hy), pack_bf2(x.z - hz, x.w - hw));
}

// vectorized fp16 split with 64x prescale (fc_w)
__global__ void split4_f16s(const float* __restrict__ s,
                            __half* __restrict__ hi,
                            __half* __restrict__ lo, int n4) {
    int i = blockIdx.x*256 + threadIdx.x;
    if (i >= n4) return;
    float4 x = ((const float4*)s)[i];
    x.x *= 64.f; x.y *= 64.f; x.z *= 64.f; x.w *= 64.f;
    float hx = __half2float(__float2half_rn(x.x));
    float hy = __half2float(__float2half_rn(x.y));
    float hz = __half2float(__float2half_rn(x.z));
    float hw = __half2float(__float2half_rn(x.w));
    ((uint2*)hi)[i] = make_uint2(pack_h2(x.x, x.y), pack_h2(x.z, x.w));
    ((uint2*)lo)[i] = make_uint2(pack_h2(x.x - hx, x.y - hy), pack_h2(x.z - hz, x.w - hw));
}

// mean pool -> bf16 hi/lo split directly
__global__ void meanpool_kernel(const float* __restrict__ features) {
    int b = blockIdx.x, k = threadIdx.x;
    const float* p = features + (size_t)b*LFdim*512 + k;
    float s = 0.f;
    #pragma unroll
    for (int l = 0; l < LFdim; l++) s += p[l*512];
    s *= (1.0f/LFdim);
    __nv_bfloat16 h = __float2bfloat16(s);
    g_mfh[b*512 + k] = h;
    g_mfl[b*512 + k] = __float2bfloat16(s - __bfloat162float(h));
}

// zero masked output slots (t >= len[b])
__global__ void zerofill_kernel(const int* __restrict__ lengths, float* __restrict__ out) {
    int b = blockIdx.x >> 5, t = blockIdx.x & 31;
    if (t < lengths[b]) return;
    float4* o = (float4*)(out + ((size_t)b*Tdim + t)*Vdim);
    float4 z = make_float4(0.f, 0.f, 0.f, 0.f);
    for (int i = threadIdx.x; i < Vdim/4; i += 256) o[i] = z;
}

// ---------------------------------------------------------------------------
// bf16x3 GEMM via mma.sync (gx + init). Block 128x128, BK=32, 8 warps.
// MODE 0: C[m*N+n] = acc + b1[n]                (gx; early-exit m0>=Mc)
// MODE 1: init h0/c0: n<512 -> split-write g_hh0/g_hl0; n>=512 -> g_c (fp32)
#define TILE_B 8192
#define STAGE_B (4*TILE_B)
#define DSM_BYTES (2*STAGE_B)

template<int MODE>
__global__ void __launch_bounds__(256)
mma_gemm(const __nv_bfloat16* __restrict__ Ah, const __nv_bfloat16* __restrict__ Al,
         const __nv_bfloat16* __restrict__ Bh, const __nv_bfloat16* __restrict__ Bl,
         float* __restrict__ C, int M, int N,
         const float* __restrict__ b1)
{
    const int m0 = blockIdx.y * 128;
    if (MODE != 1 && m0 >= g_Mc) return;
    extern __shared__ char smem[];
    const uint32_t sbase = smem_to_u32(smem);
    const int tid = threadIdx.x;
    const int lane = tid & 31, wid = tid >> 5;
    const int wm = wid >> 2, wn = wid & 3;
    const int n0 = blockIdx.x * 128;

    float c[4][4][4];
    #pragma unroll
    for (int i = 0; i < 4; i++)
        #pragma unroll
        for (int j = 0; j < 4; j++)
            { c[i][j][0]=0.f; c[i][j][1]=0.f; c[i][j][2]=0.f; c[i][j][3]=0.f; }

    auto load_stage = [&](int kc, int stage) {
        const int k0 = kc * 32;
        const uint32_t st = sbase + stage * STAGE_B;
        #pragma unroll
        for (int i = 0; i < 2; i++) {
            int chunk = tid + 256*i;
            int r = chunk >> 2, q = chunk & 3;
            uint32_t off = sw_off(r, q);
            int mr = m0 + r;
            bool ap = mr < M;
            size_t ao = (size_t)(ap ? mr : (M-1))*Kdim + k0 + q*8;
            cp16(st + off,            Ah + ao, ap);
            cp16(st + TILE_B + off,   Al + ao, ap);
            int nr = n0 + r;
            bool bp = nr < N;
            size_t bo = (size_t)(bp ? nr : (N-1))*Kdim + k0 + q*8;
            cp16(st + 2*TILE_B + off, Bh + bo, bp);
            cp16(st + 3*TILE_B + off, Bl + bo, bp);
        }
        CP_COMMIT();
    };

    const int NK = Kdim / 32;
    load_stage(0, 0);
    for (int kc = 0; kc < NK; kc++) {
        int stage = kc & 1;
        if (kc + 1 < NK) { load_stage(kc + 1, stage ^ 1); CP_WAIT1(); }
        else             { CP_WAIT0(); }
        __syncthreads();
        const uint32_t sa = sbase + stage * STAGE_B;

        #pragma unroll
        for (int kh = 0; kh < 2; kh++) {
            uint32_t aH[4][4], aL[4][4];
            #pragma unroll
            for (int mf = 0; mf < 4; mf++) {
                int row  = wm*64 + mf*16 + (lane & 7) + ((lane >> 3) & 1)*8;
                int kcol = kh*16 + ((lane >> 4) & 1)*8;
                uint32_t off = sw_off(row, kcol >> 3);
                LDSM4(aH[mf], sa + off);
                LDSM4(aL[mf], sa + TILE_B + off);
            }
            uint32_t bH[4][2], bL[4][2];
            #pragma unroll
            for (int np = 0; np < 2; np++) {
                int row  = wn*32 + np*16 + (lane & 7) + ((lane >> 4) & 1)*8;
                int kcol = ((lane >> 3) & 1)*8 + kh*16;
                uint32_t off = sw_off(row, kcol >> 3);
                uint32_t r4[4];
                LDSM4(r4, sa + 2*TILE_B + off);
                bH[np*2][0]=r4[0]; bH[np*2][1]=r4[1];
                bH[np*2+1][0]=r4[2]; bH[np*2+1][1]=r4[3];
                LDSM4(r4, sa + 3*TILE_B + off);
                bL[np*2][0]=r4[0]; bL[np*2][1]=r4[1];
                bL[np*2+1][0]=r4[2]; bL[np*2+1][1]=r4[3];
            }
            #pragma unroll
            for (int mf = 0; mf < 4; mf++)
                #pragma unroll
                for (int nf = 0; nf < 4; nf++) {
                    mma16816(c[mf][nf], aH[mf], bH[nf]);
                    mma16816(c[mf][nf], aH[mf], bL[nf]);
                    mma16816(c[mf][nf], aL[mf], bH[nf]);
                }
        }
        __syncthreads();
    }

    #pragma unroll
    for (int mf = 0; mf < 4; mf++) {
        #pragma unroll
        for (int nf = 0; nf < 4; nf++) {
            int m = m0 + wm*64 + mf*16 + (lane >> 2);
            int n = n0 + wn*32 + nf*8 + 2*(lane & 3);
            if (n >= N) continue;
            #pragma unroll
            for (int half = 0; half < 2; half++) {
                int mm = m + half*8;
                if (MODE == 1 && mm >= M) continue;
                float v0 = c[mf][nf][half*2], v1 = c[mf][nf][half*2+1];
                if (MODE == 0) {
                    v0 += b1[n]; v1 += b1[n+1];
                    *(float2*)(C + (size_t)mm*N + n) = make_float2(v0, v1);
                } else {
                    v0 += b1[n]; v1 += b1[n+1];
                    if (n < 512) {
                        __nv_bfloat16 h0 = __float2bfloat16(v0);
                        g_hh0[mm*512 + n] = h0;
                        g_hl0[mm*512 + n] = __float2bfloat16(v0 - __bfloat162float(h0));
                        __nv_bfloat16 h1 = __float2bfloat16(v1);
                        g_hh0[mm*512 + n + 1] = h1;
                        g_hl0[mm*512 + n + 1] = __float2bfloat16(v1 - __bfloat162float(h1));
                    } else {
                        g_c[mm*512 + n - 512] = v0;
                        g_c[mm*512 + n - 511] = v1;
                    }
                }
            }
        }
    }
}

// ---------------------------------------------------------------------------
// fc GEMM: fp16 2-term. D = hall16 @ (fwh16 + fwl16)^T / 64 + fc_b, via map.
#define FC_TILE 8192
#define FC_STAGE (3*FC_TILE)
#define FC_DSM (2*FC_STAGE)     // 48 KB

__global__ void __launch_bounds__(256)
fc_gemm(const __half* __restrict__ A, const __half* __restrict__ Bh,
        const __half* __restrict__ Bl, float* __restrict__ C,
        const float* __restrict__ b1)
{
    const int m0 = blockIdx.y * 128;
    if (m0 >= g_Mc) return;
    extern __shared__ char smem[];
    const uint32_t sbase = smem_to_u32(smem);
    const int tid = threadIdx.x;
    const int lane = tid & 31, wid = tid >> 5;
    const int wm = wid >> 2, wn = wid & 3;
    const int n0 = blockIdx.x * 128;
    const int N = Vdim;

    float c[4][4][4];
    #pragma unroll
    for (int i = 0; i < 4; i++)
        #pragma unroll
        for (int j = 0; j < 4; j++)
            { c[i][j][0]=0.f; c[i][j][1]=0.f; c[i][j][2]=0.f; c[i][j][3]=0.f; }

    auto load_stage = [&](int kc, int stage) {
        const int k0 = kc * 32;
        const uint32_t st = sbase + stage * FC_STAGE;
        #pragma unroll
        for (int i = 0; i < 2; i++) {
            int chunk = tid + 256*i;
            int r = chunk >> 2, q = chunk & 3;
            uint32_t off = sw_off(r, q);
            size_t ao = (size_t)(m0 + r)*Kdim + k0 + q*8;
            cp16(st + off, A + ao, true);
            int nr = n0 + r;
            bool bp = nr < N;
            size_t bo = (size_t)(bp ? nr : (N-1))*Kdim + k0 + q*8;
            cp16(st + FC_TILE + off,   Bh + bo, bp);
            cp16(st + 2*FC_TILE + off, Bl + bo, bp);
        }
        CP_COMMIT();
    };

    const int NK = Kdim / 32;
    load_stage(0, 0);
    for (int kc = 0; kc < NK; kc++) {
        int stage = kc & 1;
        if (kc + 1 < NK) { load_stage(kc + 1, stage ^ 1); CP_WAIT1(); }
        else             { CP_WAIT0(); }
        __syncthreads();
        const uint32_t sa = sbase + stage * FC_STAGE;

        #pragma unroll
        for (int kh = 0; kh < 2; kh++) {
            uint32_t aH[4][4];
            #pragma unroll
            for (int mf = 0; mf < 4; mf++) {
                int row  = wm*64 + mf*16 + (lane & 7) + ((lane >> 3) & 1)*8;
                int kcol = kh*16 + ((lane >> 4) & 1)*8;
                LDSM4(aH[mf], sa + sw_off(row, kcol >> 3));
            }
            uint32_t bH[4][2], bL[4][2];
            #pragma unroll
            for (int np = 0; np < 2; np++) {
                int row  = wn*32 + np*16 + (lane & 7) + ((lane >> 4) & 1)*8;
                int kcol = ((lane >> 3) & 1)*8 + kh*16;
                uint32_t off = sw_off(row, kcol >> 3);
                uint32_t r4[4];
                LDSM4(r4, sa + FC_TILE + off);
                bH[np*2][0]=r4[0]; bH[np*2][1]=r4[1];
                bH[np*2+1][0]=r4[2]; bH[np*2+1][1]=r4[3];
                LDSM4(r4, sa + 2*FC_TILE + off);
                bL[np*2][0]=r4[0]; bL[np*2][1]=r4[1];
                bL[np*2+1][0]=r4[2]; bL[np*2+1][1]=r4[3];
            }
            #pragma unroll
            for (int mf = 0; mf < 4; mf++)
                #pragma unroll
                for (int nf = 0; nf < 4; nf++) {
                    mma16816h(c[mf][nf], aH[mf], bH[nf]);
                    mma16816h(c[mf][nf], aH[mf], bL[nf]);
                }
        }
        __syncthreads();
    }

    const float inv = 0.015625f;   // 1/64
    #pragma unroll
    for (int mf = 0; mf < 4; mf++) {
        #pragma unroll
        for (int nf = 0; nf < 4; nf++) {
            int m = m0 + wm*64 + mf*16 + (lane >> 2);
            int n = n0 + wn*32 + nf*8 + 2*(lane & 3);
            if (n >= N) continue;
            #pragma unroll
            for (int half = 0; half < 2; half++) {
                int mm = m + half*8;
                int v = g_map[mm];
                if (v >= 0) {
                    int t = v >> 8, b = v & 255;
                    float v0 = c[mf][nf][half*2]*inv   + b1[n];
                    float v1 = c[mf][nf][half*2+1]*inv + b1[n+1];
                    *(float2*)(C + ((size_t)(b*Tdim + t))*Vdim + n) = make_float2(v0, v1);
                }
            }
        }
    }
}

// ---------------------------------------------------------------------------
// Persistent recurrence: all 32 steps in one launch (see R6 comments).
#define PK_WH    0
#define PK_WL    65536
#define PK_AST   131072          // + stage*8192; lo at +4096
#define PK_GATES 147456          // float[64*66]
#define PK_CST   164352          // float[1024]
#define PK_BYTES 168448

__global__ void __launch_bounds__(256)
persist_step_kernel() {
    extern __shared__ char sm[];
    const uint32_t sbase = smem_to_u32(sm);
    const int tid = threadIdx.x;
    const int lane = tid & 31, wid = tid >> 5;
    const int wm = wid >> 2, wn = wid & 3;
    const int nslice = blockIdx.x & 31;
    const int mtile = blockIdx.x >> 5;
    const int n0 = nslice * 64;
    const int m0 = mtile * 64;

    {
        int r = tid >> 2, q = tid & 3;
        #pragma unroll
        for (int kc = 0; kc < 16; kc++) {
            uint32_t off = (uint32_t)(kc*4096) + sw_off(r, q);
            size_t go = (size_t)(n0 + r)*Hdim + kc*32 + q*8;
            cp16(sbase + PK_WH + off, g_whhh + go, true);
            cp16(sbase + PK_WL + off, g_whhl + go, true);
        }
        CP_COMMIT();
    }
    float* cst = (float*)(sm + PK_CST);
    for (int i = tid; i < 1024; i += 256) {
        int r = i >> 4, u = i & 15;
        cst[i] = g_c[(m0 + r)*Hdim + (n0 >> 2) + u];
    }
    CP_WAIT0();
    __syncthreads();

    float* gs = (float*)(sm + PK_GATES);

    for (int t = 0; t < Tdim; t++) {
        const int nact = g_nact[t];
        const __nv_bfloat16* Ah = (t & 1) ? g_hh1 : g_hh0;
        const __nv_bfloat16* Al = (t & 1) ? g_hl1 : g_hl0;
        __nv_bfloat16* Oh = (t & 1) ? g_hh0 : g_hh1;
        __nv_bfloat16* Ol = (t & 1) ? g_hl0 : g_hl1;

        if (m0 < nact) {
            float acc[2][2][4];
            #pragma unroll
            for (int i = 0; i < 2; i++)
                #pragma unroll
                for (int j = 0; j < 2; j++)
                    { acc[i][j][0]=0.f; acc[i][j][1]=0.f; acc[i][j][2]=0.f; acc[i][j][3]=0.f; }

            auto loadA = [&](int kc, int stage) {
                const uint32_t st = sbase + PK_AST + stage*8192;
                int r = tid >> 2, q = tid & 3;
                uint32_t off = sw_off(r, q);
                size_t ao = (size_t)(m0 + r)*Hdim + kc*32 + q*8;
                cp16(st + off,        Ah + ao, true);
                cp16(st + 4096 + off, Al + ao, true);
                CP_COMMIT();
            };
            loadA(0, 0);
            for (int kc = 0; kc < 16; kc++) {
                int stage = kc & 1;
                if (kc + 1 < 16) { loadA(kc + 1, stage ^ 1); CP_WAIT1(); }
                else             { CP_WAIT0(); }
                __syncthreads();
                const uint32_t sa = sbase + PK_AST + stage*8192;
                const uint32_t wbH = sbase + PK_WH + (uint32_t)(kc*4096);
                const uint32_t wbL = sbase + PK_WL + (uint32_t)(kc*4096);
                #pragma unroll
                for (int kh = 0; kh < 2; kh++) {
                    uint32_t aH[2][4], aL[2][4];
                    #pragma unroll
                    for (int mf = 0; mf < 2; mf++) {
                        int row  = wm*32 + mf*16 + (lane & 7) + ((lane >> 3) & 1)*8;
                        int kcol = kh*16 + ((lane >> 4) & 1)*8;
                        uint32_t off = sw_off(row, kcol >> 3);
                        LDSM4(aH[mf], sa + off);
                        LDSM4(aL[mf], sa + 4096 + off);
                    }
                    uint32_t bH[2][2], bL[2][2];
                    {
                        int row  = wn*16 + (lane & 7) + ((lane >> 4) & 1)*8;
                        int kcol = ((lane >> 3) & 1)*8 + kh*16;
                        uint32_t off = sw_off(row, kcol >> 3);
                        uint32_t r4[4];
                        LDSM4(r4, wbH + off);
                        bH[0][0]=r4[0]; bH[0][1]=r4[1]; bH[1][0]=r4[2]; bH[1][1]=r4[3];
                        LDSM4(r4, wbL + off);
                        bL[0][0]=r4[0]; bL[0][1]=r4[1]; bL[1][0]=r4[2]; bL[1][1]=r4[3];
                    }
                    #pragma unroll
                    for (int mf = 0; mf < 2; mf++)
                        #pragma unroll
                        for (int nf = 0; nf < 2; nf++) {
                            mma16816(acc[mf][nf], aH[mf], bH[nf]);
                            mma16816(acc[mf][nf], aH[mf], bL[nf]);
                            mma16816(acc[mf][nf], aL[mf], bH[nf]);
                        }
                }
                __syncthreads();
            }

            const int goff = g_off[t];
            #pragma unroll
            for (int mf = 0; mf < 2; mf++) {
                #pragma unroll
                for (int nf = 0; nf < 2; nf++) {
                    int rl = wm*32 + mf*16 + (lane >> 2);
                    int nl = wn*16 + nf*8 + 2*(lane & 3);
                    #pragma unroll
                    for (int half = 0; half < 2; half++) {
                        int rr = rl + half*8;
                        float2 gx2 = *(const float2*)(g_gx + (size_t)(goff + m0 + rr)*G4 + n0 + nl);
                        gs[rr*66 + nl]     = acc[mf][nf][half*2]   + gx2.x;
                        gs[rr*66 + nl + 1] = acc[mf][nf][half*2+1] + gx2.y;
                    }
                }
            }
            __syncthreads();

            #pragma unroll
            for (int p = 0; p < 4; p++) {
                int idx = tid + 256*p;
                int row = idx >> 4, u = idx & 15;
                int rg = m0 + row;
                if (rg < nact) {
                    float gi = gs[row*66 + u*4 + 0];
                    float gf = gs[row*66 + u*4 + 1];
                    float gc = gs[row*66 + u*4 + 2];
                    float go = gs[row*66 + u*4 + 3];
                    float cc = cst[row*16 + u];
                    cc = sigf(gf)*cc + sigf(gi)*tanhf(gc);
                    float hv = sigf(go)*tanhf(cc);
                    cst[row*16 + u] = cc;
                    int jg = (n0 >> 2) + u;
                    __nv_bfloat16 hhi = __float2bfloat16(hv);
                    __nv_bfloat16 hlo = __float2bfloat16(hv - __bfloat162float(hhi));
                    Oh[rg*Hdim + jg] = hhi;
                    Ol[rg*Hdim + jg] = hlo;
                    g_hall16[(size_t)(goff + rg)*Hdim + jg] = __float2half_rn(hv);
                }
            }
        }

        __syncthreads();
        if (tid == 0) {
            __threadfence();
            atomicAdd(&g_sync, 1u);
            unsigned target = 64u * (unsigned)(t + 1);
            while (atomicAdd(&g_sync, 0u) < target) { __nanosleep(32); }
            __threadfence();
        }
        __syncthreads();
    }
}

// ---------------------------------------------------------------------------
extern "C" void kernel_launch(void* const* d_in, const int* in_sizes, int n_in,
                              void* d_out, int out_size) {
    const float* features  = (const float*)d_in[0];
    const int*   captions  = (const int*)  d_in[1];
    const int*   lengths   = (const int*)  d_in[2];
    const float* embedding = (const float*)d_in[3];
    const float* W_ih      = (const float*)d_in[4];
    const float* W_hh      = (const float*)d_in[5];
    const float* b_ih      = (const float*)d_in[6];
    const float* b_hh      = (const float*)d_in[7];
    const float* fc_w      = (const float*)d_in[8];
    const float* fc_b      = (const float*)d_in[9];
    const float* ihw       = (const float*)d_in[10];
    const float* ihb       = (const float*)d_in[11];
    const float* icw       = (const float*)d_in[12];
    const float* icb       = (const float*)d_in[13];
    float* out = (float*)d_out;

    float *gx, *pbias, *ib;
    __nv_bfloat16 *mfh, *mfl, *iwh, *iwl, *embh, *embl;
    __nv_bfloat16 *wihh, *wihl, *whhh, *whhl;
    __half *fwh16, *fwl16, *hall16;
    cudaGetSymbolAddress((void**)&gx, g_gx);
    cudaGetSymbolAddress((void**)&pbias, g_pbias);
    cudaGetSymbolAddress((void**)&ib, g_ib);
    cudaGetSymbolAddress((void**)&mfh, g_mfh); cudaGetSymbolAddress((void**)&mfl, g_mfl);
    cudaGetSymbolAddress((void**)&iwh, g_iwh); cudaGetSymbolAddress((void**)&iwl, g_iwl);
    cudaGetSymbolAddress((void**)&embh, g_embh); cudaGetSymbolAddress((void**)&embl, g_embl);
    cudaGetSymbolAddress((void**)&wihh, g_wihh); cudaGetSymbolAddress((void**)&wihl, g_wihl);
    cudaGetSymbolAddress((void**)&whhh, g_whhh); cudaGetSymbolAddress((void**)&whhl, g_whhl);
    cudaGetSymbolAddress((void**)&fwh16, g_fwh16); cudaGetSymbolAddress((void**)&fwl16, g_fwl16);
    cudaGetSymbolAddress((void**)&hall16, g_hall16);

    cudaFuncSetAttribute(mma_gemm<0>, cudaFuncAttributeMaxDynamicSharedMemorySize, DSM_BYTES);
    cudaFuncSetAttribute(mma_gemm<1>, cudaFuncAttributeMaxDynamicSharedMemorySize, DSM_BYTES);
    cudaFuncSetAttribute(fc_gemm, cudaFuncAttributeMaxDynamicSharedMemorySize, FC_DSM);
    cudaFuncSetAttribute(persist_step_kernel, cudaFuncAttributeMaxDynamicSharedMemorySize, PK_BYTES);

    // 0. compact row map + biases + sync reset
    setup_kernel<<<1, 256>>>(lengths, b_ih, b_hh, ihb, icb);

    // 1. mean pool + init weights split + init GEMM (h0 split + c0)
    meanpool_kernel<<<Bdim, 512>>>(features);
    split4_bf16<<<(512*512/4+255)/256, 256>>>(ihw, iwh, iwl, 512*512/4);
    split4_bf16<<<(512*512/4+255)/256, 256>>>(icw, iwh + 512*512, iwl + 512*512, 512*512/4);
    mma_gemm<1><<<dim3(8, 1), 256, DSM_BYTES>>>(mfh, mfl, iwh, iwl, nullptr, Bdim, 1024, ib);

    // 2. fc_w split (fp16, 64x prescale) — position 6 for ncu sampling
    split4_f16s<<<((size_t)Vdim*Hdim/4+255)/256, 256>>>(fc_w, fwh16, fwl16, Vdim*Hdim/4);

    // 3. remaining operand prep
    gather_split_kernel<<<MT, 128>>>(embedding, captions);
    split_permute_kernel<<<(G4*128)/256, 256>>>(W_ih, wihh, wihl);
    split_permute_kernel<<<(G4*128)/256, 256>>>(W_hh, whhh, whhl);

    // 4. gx = emb @ W_ih'^T + pbias (compact rows)
    {
        dim3 grid(G4/128, MT/128);
        mma_gemm<0><<<grid, 256, DSM_BYTES>>>(embh, embl, wihh, wihl, gx, MT, G4, pbias);
    }

    // 5. full recurrence in ONE persistent launch
    persist_step_kernel<<<64, 256, PK_BYTES>>>();

    // 6. zero masked outputs + fc projection (fp16 2-term, 1/64 scale)
    zerofill_kernel<<<Bdim*Tdim, 256>>>(lengths, out);
    {
        dim3 grid((Vdim + 127)/128, MT/128);
        fc_gemm<<<grid, 256, FC_DSM>>>(hall16, fwh16, fwl16, out, fc_b);
    }
}

// round 8
// speedup vs baseline: 4.5025x; 1.0424x over previous
#include <cuda_runtime.h>
#include <cuda_bf16.h>
#include <cuda_fp16.h>
#include <cstdint>
#include <math.h>

#define Bdim 128
#define Tdim 32
#define Edim 512
#define Hdim 512
#define Vdim 10000
#define LFdim 49
#define G4 2048
#define MT 4096
#define Kdim 512

// ---------------- scratch (__device__ globals; no allocs allowed) ----------
__device__ float g_c[Bdim*Hdim];
__device__ float g_gx[(size_t)MT*G4];          // compact rows
__device__ float g_pbias[G4];                  // permuted b_ih+b_hh
__device__ float g_ib[1024];                   // stacked ihb|icb

__device__ int g_nact[Tdim];
__device__ int g_off[Tdim+1];
__device__ int g_Mc;
__device__ int g_map[MT];   // row -> (t<<8)|b ; bit16 set = masked (zero output)
__device__ unsigned int g_sync;

__device__ __nv_bfloat16 g_mfh[Bdim*Edim], g_mfl[Bdim*Edim];
__device__ __nv_bfloat16 g_iwh[(size_t)1024*Edim], g_iwl[(size_t)1024*Edim];
__device__ __nv_bfloat16 g_hh0[Bdim*Hdim], g_hl0[Bdim*Hdim];
__device__ __nv_bfloat16 g_hh1[Bdim*Hdim], g_hl1[Bdim*Hdim];
__device__ __nv_bfloat16 g_embh[(size_t)MT*Edim], g_embl[(size_t)MT*Edim];
__device__ __nv_bfloat16 g_wihh[(size_t)G4*Edim], g_wihl[(size_t)G4*Edim]; // permuted
__device__ __nv_bfloat16 g_whhh[(size_t)G4*Hdim], g_whhl[(size_t)G4*Hdim]; // permuted
__device__ __half g_fwh16[(size_t)Vdim*Hdim];  // 64x prescaled fp16
__device__ __half g_hall16[(size_t)MT*Hdim];   // compact, fp16

// ---------------- PTX helpers (sm_80-era: legal on base sm_100) ------------
__device__ __forceinline__ uint32_t smem_to_u32(const void* p) {
    uint32_t a;
    asm("{ .reg .u64 t; cvta.to.shared.u64 t, %1; cvt.u32.u64 %0, t; }" : "=r"(a) : "l"(p));
    return a;
}
__device__ __forceinline__ void cp16(uint32_t dst, const void* src, bool pred) {
    int sz = pred ? 16 : 0;
    asm volatile("cp.async.cg.shared.global [%0], [%1], 16, %2;"
                 :: "r"(dst), "l"(src), "r"(sz) : "memory");
}
#define CP_COMMIT() asm volatile("cp.async.commit_group;" ::: "memory")
#define CP_WAIT2()  asm volatile("cp.async.wait_group 2;" ::: "memory")
#define CP_WAIT1()  asm volatile("cp.async.wait_group 1;" ::: "memory")
#define CP_WAIT0()  asm volatile("cp.async.wait_group 0;" ::: "memory")
#define LDSM4(r, addr) \
    asm volatile("ldmatrix.sync.aligned.m8n8.x4.shared.b16 {%0,%1,%2,%3}, [%4];" \
        : "=r"((r)[0]), "=r"((r)[1]), "=r"((r)[2]), "=r"((r)[3]) : "r"(addr))

__device__ __forceinline__ void mma16816(float* c, const uint32_t* a, const uint32_t* b) {
    asm volatile("mma.sync.aligned.m16n8k16.row.col.f32.bf16.bf16.f32 "
        "{%0,%1,%2,%3}, {%4,%5,%6,%7}, {%8,%9}, {%0,%1,%2,%3};"
        : "+f"(c[0]), "+f"(c[1]), "+f"(c[2]), "+f"(c[3])
        : "r"(a[0]), "r"(a[1]), "r"(a[2]), "r"(a[3]), "r"(b[0]), "r"(b[1]));
}
__device__ __forceinline__ void mma16816h(float* c, const uint32_t* a, const uint32_t* b) {
    asm volatile("mma.sync.aligned.m16n8k16.row.col.f32.f16.f16.f32 "
        "{%0,%1,%2,%3}, {%4,%5,%6,%7}, {%8,%9}, {%0,%1,%2,%3};"
        : "+f"(c[0]), "+f"(c[1]), "+f"(c[2]), "+f"(c[3])
        : "r"(a[0]), "r"(a[1]), "r"(a[2]), "r"(a[3]), "r"(b[0]), "r"(b[1]));
}

// XOR swizzle for 64B-row tiles: row r, 16B chunk q
__device__ __forceinline__ uint32_t sw_off(int r, int q) {
    return (uint32_t)(r*64 + ((q ^ ((r >> 1) & 3)) << 4));
}

__device__ __forceinline__ float sigf(float x) { return 1.0f / (1.0f + expf(-x)); }

__device__ __forceinline__ uint32_t pack_bf2(float a, float b) {
    __nv_bfloat162 v = __floats2bfloat162_rn(a, b);
    return *(uint32_t*)&v;
}
__device__ __forceinline__ uint32_t pack_h2(float a, float b) {
    __half2 v = __floats2half2_rn(a, b);
    return *(uint32_t*)&v;
}

// ---------------------------------------------------------------------------
// setup: n_active(t), offsets, full row map (active + masked pads), biases
__global__ void setup_kernel(const int* __restrict__ lengths,
                             const float* __restrict__ b_ih,
                             const float* __restrict__ b_hh,
                             const float* __restrict__ ihb,
                             const float* __restrict__ icb) {
    __shared__ int s_len[Bdim];
    int tid = threadIdx.x;
    if (tid == 0) g_sync = 0u;
    if (tid < Bdim) s_len[tid] = lengths[tid];
    __syncthreads();
    if (tid < Tdim) {
        int cnt = 0;
        for (int b = 0; b < Bdim; b++) cnt += (s_len[b] > tid) ? 1 : 0;
        g_nact[tid] = cnt;
    }
    __syncthreads();
    if (tid == 0) {
        int acc = 0;
        for (int t = 0; t < Tdim; t++) { g_off[t] = acc; acc += g_nact[t]; }
        g_off[Tdim] = acc;
        g_Mc = acc;
    }
    __syncthreads();
    int Mc = g_Mc;
    for (int r = tid; r < Mc; r += 256) {
        int t = 0;
        while (t < Tdim - 1 && r >= g_off[t+1]) t++;
        g_map[r] = (t << 8) | (r - g_off[t]);
    }
    if (tid == 0) {            // pad rows -> masked (b,t) slots, flag bit16
        int rp = Mc;
        for (int b = 0; b < Bdim; b++)
            for (int t = s_len[b]; t < Tdim; t++)
                g_map[rp++] = (t << 8) | b | 0x10000;
    }
    for (int i = tid; i < G4; i += 256) {
        int j = i >> 2, g = i & 3;
        g_pbias[i] = b_ih[g*512 + j] + b_hh[g*512 + j];
    }
    for (int i = tid; i < 1024; i += 256)
        g_ib[i] = (i < 512) ? ihb[i] : icb[i - 512];
}

// ---------------------------------------------------------------------------
// gather embeddings into compact rows (vectorized; zero pads emb & hall16)
__global__ void gather_split_kernel(const float* __restrict__ emb,
                                    const int* __restrict__ cap) {
    int r = blockIdx.x;
    int v = g_map[r];
    int c4 = threadIdx.x * 4;          // 128 threads x 4 = 512
    if (v & 0x10000) {
        uint2 z = make_uint2(0u, 0u);
        *(uint2*)(g_embh + (size_t)r*Edim + c4) = z;
        *(uint2*)(g_embl + (size_t)r*Edim + c4) = z;
        *(uint2*)(g_hall16 + (size_t)r*Hdim + c4) = z;
        return;
    }
    int t = (v >> 8) & 0xFF, b = v & 0xFF;
    int tok = cap[b*Tdim + t];
    float4 x = *(const float4*)(emb + (size_t)tok*Edim + c4);
    float hx = __bfloat162float(__float2bfloat16(x.x));
    float hy = __bfloat162float(__float2bfloat16(x.y));
    float hz = __bfloat162float(__float2bfloat16(x.z));
    float hw = __bfloat162float(__float2bfloat16(x.w));
    *(uint2*)(g_embh + (size_t)r*Edim + c4) = make_uint2(pack_bf2(x.x, x.y), pack_bf2(x.z, x.w));
    *(uint2*)(g_embl + (size_t)r*Edim + c4) =
        make_uint2(pack_bf2(x.x - hx, x.y - hy), pack_bf2(x.z - hz, x.w - hw));
}

// split W with gate permutation, vectorized: out row 4j+g <- in row g*512+j
__global__ void split_permute_kernel(const float* __restrict__ W,
                                     __nv_bfloat16* __restrict__ hi,
                                     __nv_bfloat16* __restrict__ lo) {
    int idx = blockIdx.x*256 + threadIdx.x;   // 2048*128 total
    int r = idx >> 7, c4 = (idx & 127) * 4;
    int j = r >> 2, g = r & 3;
    float4 x = *(const float4*)(W + (size_t)(g*512 + j)*512 + c4);
    float hx = __bfloat162float(__float2bfloat16(x.x));
    float hy = __bfloat162float(__float2bfloat16(x.y));
    float hz = __bfloat162float(__float2bfloat16(x.z));
    float hw = __bfloat162float(__float2bfloat16(x.w));
    *(uint2*)(hi + (size_t)r*512 + c4) = make_uint2(pack_bf2(x.x, x.y), pack_bf2(x.z, x.w));
    *(uint2*)(lo + (size_t)r*512 + c4) =
        make_uint2(pack_bf2(x.x - hx, x.y - hy), pack_bf2(x.z - hz, x.w - hw));
}

// vectorized bf16 split (init weights)
__global__ void split4_bf16(const float* __restrict__ s,
                            __nv_bfloat16* __restrict__ hi,
                            __nv_bfloat16* __restrict__ lo, int n4) {
    int i = blockIdx.x*256 + threadIdx.x;
    if (i >= n4) return;
    float4 x = ((const float4*)s)[i];
    float hx = __bfloat162float(__float2bfloat16(x.x));
    float hy = __bfloat162float(__float2bfloat16(x.y));
    float hz = __bfloat162float(__float2bfloat16(x.z));
    float hw = __bfloat162float(__float2bfloat16(x.w));
    ((uint2*)hi)[i] = make_uint2(pack_bf2(x.x, x.y), pack_bf2(x.z, x.w));
    ((uint2*)lo)[i] = make_uint2(pack_bf2(x.x - hx, x.y - hy), pack_bf2(x.z - hz, x.w - hw));
}

// vectorized fp16 convert with 64x prescale (fc_w, single-term)
__global__ void conv4_f16s(const float* __restrict__ s,
                           __half* __restrict__ hi, int n4) {
    int i = blockIdx.x*256 + threadIdx.x;
    if (i >= n4) return;
    float4 x = ((const float4*)s)[i];
    ((uint2*)hi)[i] = make_uint2(pack_h2(x.x*64.f, x.y*64.f), pack_h2(x.z*64.f, x.w*64.f));
}

// mean pool -> bf16 hi/lo split directly
__global__ void meanpool_kernel(const float* __restrict__ features) {
    int b = blockIdx.x, k = threadIdx.x;
    const float* p = features + (size_t)b*LFdim*512 + k;
    float s = 0.f;
    #pragma unroll
    for (int l = 0; l < LFdim; l++) s += p[l*512];
    s *= (1.0f/LFdim);
    __nv_bfloat16 h = __float2bfloat16(s);
    g_mfh[b*512 + k] = h;
    g_mfl[b*512 + k] = __float2bfloat16(s - __bfloat162float(h));
}

// ---------------------------------------------------------------------------
// bf16x3 GEMM via mma.sync (gx + init). Block 128x128, BK=32, 8 warps.
// MODE 0: C[m*N+n] = acc + b1[n]                (gx; early-exit m0>=Mc)
// MODE 1: init h0/c0: n<512 -> split-write g_hh0/g_hl0; n>=512 -> g_c (fp32)
#define TILE_B 8192
#define STAGE_B (4*TILE_B)
#define DSM_BYTES (2*STAGE_B)

template<int MODE>
__global__ void __launch_bounds__(256)
mma_gemm(const __nv_bfloat16* __restrict__ Ah, const __nv_bfloat16* __restrict__ Al,
         const __nv_bfloat16* __restrict__ Bh, const __nv_bfloat16* __restrict__ Bl,
         float* __restrict__ C, int M, int N,
         const float* __restrict__ b1)
{
    const int m0 = blockIdx.y * 128;
    if (MODE != 1 && m0 >= g_Mc) return;
    extern __shared__ char smem[];
    const uint32_t sbase = smem_to_u32(smem);
    const int tid = threadIdx.x;
    const int lane = tid & 31, wid = tid >> 5;
    const int wm = wid >> 2, wn = wid & 3;
    const int n0 = blockIdx.x * 128;

    float c[4][4][4];
    #pragma unroll
    for (int i = 0; i < 4; i++)
        #pragma unroll
        for (int j = 0; j < 4; j++)
            { c[i][j][0]=0.f; c[i][j][1]=0.f; c[i][j][2]=0.f; c[i][j][3]=0.f; }

    auto load_stage = [&](int kc, int stage) {
        const int k0 = kc * 32;
        const uint32_t st = sbase + stage * STAGE_B;
        #pragma unroll
        for (int i = 0; i < 2; i++) {
            int chunk = tid + 256*i;
            int r = chunk >> 2, q = chunk & 3;
            uint32_t off = sw_off(r, q);
            int mr = m0 + r;
            bool ap = mr < M;
            size_t ao = (size_t)(ap ? mr : (M-1))*Kdim + k0 + q*8;
            cp16(st + off,            Ah + ao, ap);
            cp16(st + TILE_B + off,   Al + ao, ap);
            int nr = n0 + r;
            bool bp = nr < N;
            size_t bo = (size_t)(bp ? nr : (N-1))*Kdim + k0 + q*8;
            cp16(st + 2*TILE_B + off, Bh + bo, bp);
            cp16(st + 3*TILE_B + off, Bl + bo, bp);
        }
        CP_COMMIT();
    };

    const int NK = Kdim / 32;
    load_stage(0, 0);
    for (int kc = 0; kc < NK; kc++) {
        int stage = kc & 1;
        if (kc + 1 < NK) { load_stage(kc + 1, stage ^ 1); CP_WAIT1(); }
        else             { CP_WAIT0(); }
        __syncthreads();
        const uint32_t sa = sbase + stage * STAGE_B;

        #pragma unroll
        for (int kh = 0; kh < 2; kh++) {
            uint32_t aH[4][4], aL[4][4];
            #pragma unroll
            for (int mf = 0; mf < 4; mf++) {
                int row  = wm*64 + mf*16 + (lane & 7) + ((lane >> 3) & 1)*8;
                int kcol = kh*16 + ((lane >> 4) & 1)*8;
                uint32_t off = sw_off(row, kcol >> 3);
                LDSM4(aH[mf], sa + off);
                LDSM4(aL[mf], sa + TILE_B + off);
            }
            uint32_t bH[4][2], bL[4][2];
            #pragma unroll
            for (int np = 0; np < 2; np++) {
                int row  = wn*32 + np*16 + (lane & 7) + ((lane >> 4) & 1)*8;
                int kcol = ((lane >> 3) & 1)*8 + kh*16;
                uint32_t off = sw_off(row, kcol >> 3);
                uint32_t r4[4];
                LDSM4(r4, sa + 2*TILE_B + off);
                bH[np*2][0]=r4[0]; bH[np*2][1]=r4[1];
                bH[np*2+1][0]=r4[2]; bH[np*2+1][1]=r4[3];
                LDSM4(r4, sa + 3*TILE_B + off);
                bL[np*2][0]=r4[0]; bL[np*2][1]=r4[1];
                bL[np*2+1][0]=r4[2]; bL[np*2+1][1]=r4[3];
            }
            #pragma unroll
            for (int mf = 0; mf < 4; mf++)
                #pragma unroll
                for (int nf = 0; nf < 4; nf++) {
                    mma16816(c[mf][nf], aH[mf], bH[nf]);
                    mma16816(c[mf][nf], aH[mf], bL[nf]);
                    mma16816(c[mf][nf], aL[mf], bH[nf]);
                }
        }
        __syncthreads();
    }

    #pragma unroll
    for (int mf = 0; mf < 4; mf++) {
        #pragma unroll
        for (int nf = 0; nf < 4; nf++) {
            int m = m0 + wm*64 + mf*16 + (lane >> 2);
            int n = n0 + wn*32 + nf*8 + 2*(lane & 3);
            if (n >= N) continue;
            #pragma unroll
            for (int half = 0; half < 2; half++) {
                int mm = m + half*8;
                if (MODE == 1 && mm >= M) continue;
                float v0 = c[mf][nf][half*2], v1 = c[mf][nf][half*2+1];
                if (MODE == 0) {
                    v0 += b1[n]; v1 += b1[n+1];
                    *(float2*)(C + (size_t)mm*N + n) = make_float2(v0, v1);
                } else {
                    v0 += b1[n]; v1 += b1[n+1];
                    if (n < 512) {
                        __nv_bfloat16 h0 = __float2bfloat16(v0);
                        g_hh0[mm*512 + n] = h0;
                        g_hl0[mm*512 + n] = __float2bfloat16(v0 - __bfloat162float(h0));
                        __nv_bfloat16 h1 = __float2bfloat16(v1);
                        g_hh0[mm*512 + n + 1] = h1;
                        g_hl0[mm*512 + n + 1] = __float2bfloat16(v1 - __bfloat162float(h1));
                    } else {
                        g_c[mm*512 + n - 512] = v0;
                        g_c[mm*512 + n - 511] = v1;
                    }
                }
            }
        }
    }
}

// ---------------------------------------------------------------------------
// fc GEMM: fp16 single-term, 3-stage pipeline.
// D = hall16 @ fwh16^T / 64 + fc_b for active rows; zeros for masked rows.
#define FC_TILE 8192
#define FC_STAGE (2*FC_TILE)    // A + B
#define FC_DSM (3*FC_STAGE)     // 48 KB

__global__ void __launch_bounds__(256)
fc_gemm(const __half* __restrict__ A, const __half* __restrict__ Bh,
        float* __restrict__ C, const float* __restrict__ b1)
{
    const int m0 = blockIdx.y * 128;
    extern __shared__ char smem[];
    const uint32_t sbase = smem_to_u32(smem);
    const int tid = threadIdx.x;
    const int lane = tid & 31, wid = tid >> 5;
    const int wm = wid >> 2, wn = wid & 3;
    const int n0 = blockIdx.x * 128;
    const int N = Vdim;

    float c[4][4][4];
    #pragma unroll
    for (int i = 0; i < 4; i++)
        #pragma unroll
        for (int j = 0; j < 4; j++)
            { c[i][j][0]=0.f; c[i][j][1]=0.f; c[i][j][2]=0.f; c[i][j][3]=0.f; }

    if (m0 < g_Mc) {   // tiles entirely in pad region skip the GEMM
        auto load_stage = [&](int kc, int stage) {
            const int k0 = kc * 32;
            const uint32_t st = sbase + stage * FC_STAGE;
            #pragma unroll
            for (int i = 0; i < 2; i++) {
                int chunk = tid + 256*i;
                int r = chunk >> 2, q = chunk & 3;
                uint32_t off = sw_off(r, q);
                size_t ao = (size_t)(m0 + r)*Kdim + k0 + q*8;
                cp16(st + off, A + ao, true);
                int nr = n0 + r;
                bool bp = nr < N;
                size_t bo = (size_t)(bp ? nr : (N-1))*Kdim + k0 + q*8;
                cp16(st + FC_TILE + off, Bh + bo, bp);
            }
            CP_COMMIT();
        };

        const int NK = Kdim / 32;   // 16
        load_stage(0, 0);
        load_stage(1, 1);
        for (int kc = 0; kc < NK; kc++) {
            int stage = kc % 3;
            if (kc + 2 < NK)      { load_stage(kc + 2, (kc + 2) % 3); CP_WAIT2(); }
            else if (kc + 1 < NK) { CP_WAIT1(); }
            else                  { CP_WAIT0(); }
            __syncthreads();
            const uint32_t sa = sbase + stage * FC_STAGE;

            #pragma unroll
            for (int kh = 0; kh < 2; kh++) {
                uint32_t aH[4][4];
                #pragma unroll
                for (int mf = 0; mf < 4; mf++) {
                    int row  = wm*64 + mf*16 + (lane & 7) + ((lane >> 3) & 1)*8;
                    int kcol = kh*16 + ((lane >> 4) & 1)*8;
                    LDSM4(aH[mf], sa + sw_off(row, kcol >> 3));
                }
                uint32_t bH[4][2];
                #pragma unroll
                for (int np = 0; np < 2; np++) {
                    int row  = wn*32 + np*16 + (lane & 7) + ((lane >> 4) & 1)*8;
                    int kcol = ((lane >> 3) & 1)*8 + kh*16;
                    uint32_t r4[4];
                    LDSM4(r4, sa + FC_TILE + sw_off(row, kcol >> 3));
                    bH[np*2][0]=r4[0]; bH[np*2][1]=r4[1];
                    bH[np*2+1][0]=r4[2]; bH[np*2+1][1]=r4[3];
                }
                #pragma unroll
                for (int mf = 0; mf < 4; mf++)
                    #pragma unroll
                    for (int nf = 0; nf < 4; nf++)
                        mma16816h(c[mf][nf], aH[mf], bH[nf]);
            }
            __syncthreads();
        }
    }

    const float inv = 0.015625f;   // 1/64
    #pragma unroll
    for (int mf = 0; mf < 4; mf++) {
        #pragma unroll
        for (int nf = 0; nf < 4; nf++) {
            int m = m0 + wm*64 + mf*16 + (lane >> 2);
            int n = n0 + wn*32 + nf*8 + 2*(lane & 3);
            if (n >= N) continue;
            #pragma unroll
            for (int half = 0; half < 2; half++) {
                int mm = m + half*8;
                int v = g_map[mm];
                int t = (v >> 8) & 0xFF, b = v & 0xFF;
                float2 o;
                if (v & 0x10000) {
                    o = make_float2(0.f, 0.f);
                } else {
                    o = make_float2(c[mf][nf][half*2]*inv   + b1[n],
                                    c[mf][nf][half*2+1]*inv + b1[n+1]);
                }
                *(float2*)(C + ((size_t)(b*Tdim + t))*Vdim + n) = o;
            }
        }
    }
}

// ---------------------------------------------------------------------------
// Persistent recurrence: all 32 steps in one launch.
#define PK_WH    0
#define PK_WL    65536
#define PK_AST   131072          // + stage*8192; lo at +4096
#define PK_GATES 147456          // float[64*66]
#define PK_CST   164352          // float[1024]
#define PK_BYTES 168448

__global__ void __launch_bounds__(256)
persist_step_kernel() {
    extern __shared__ char sm[];
    const uint32_t sbase = smem_to_u32(sm);
    const int tid = threadIdx.x;
    const int lane = tid & 31, wid = tid >> 5;
    const int wm = wid >> 2, wn = wid & 3;
    const int nslice = blockIdx.x & 31;
    const int mtile = blockIdx.x >> 5;
    const int n0 = nslice * 64;
    const int m0 = mtile * 64;

    {
        int r = tid >> 2, q = tid & 3;
        #pragma unroll
        for (int kc = 0; kc < 16; kc++) {
            uint32_t off = (uint32_t)(kc*4096) + sw_off(r, q);
            size_t go = (size_t)(n0 + r)*Hdim + kc*32 + q*8;
            cp16(sbase + PK_WH + off, g_whhh + go, true);
            cp16(sbase + PK_WL + off, g_whhl + go, true);
        }
        CP_COMMIT();
    }
    float* cst = (float*)(sm + PK_CST);
    for (int i = tid; i < 1024; i += 256) {
        int r = i >> 4, u = i & 15;
        cst[i] = g_c[(m0 + r)*Hdim + (n0 >> 2) + u];
    }
    CP_WAIT0();
    __syncthreads();

    float* gs = (float*)(sm + PK_GATES);

    for (int t = 0; t < Tdim; t++) {
        const int nact = g_nact[t];
        const __nv_bfloat16* Ah = (t & 1) ? g_hh1 : g_hh0;
        const __nv_bfloat16* Al = (t & 1) ? g_hl1 : g_hl0;
        __nv_bfloat16* Oh = (t & 1) ? g_hh0 : g_hh1;
        __nv_bfloat16* Ol = (t & 1) ? g_hl0 : g_hl1;

        if (m0 < nact) {
            float acc[2][2][4];
            #pragma unroll
            for (int i = 0; i < 2; i++)
                #pragma unroll
                for (int j = 0; j < 2; j++)
                    { acc[i][j][0]=0.f; acc[i][j][1]=0.f; acc[i][j][2]=0.f; acc[i][j][3]=0.f; }

            auto loadA = [&](int kc, int stage) {
                const uint32_t st = sbase + PK_AST + stage*8192;
                int r = tid >> 2, q = tid & 3;
                uint32_t off = sw_off(r, q);
                size_t ao = (size_t)(m0 + r)*Hdim + kc*32 + q*8;
                cp16(st + off,        Ah + ao, true);
                cp16(st + 4096 + off, Al + ao, true);
                CP_COMMIT();
            };
            loadA(0, 0);
            for (int kc = 0; kc < 16; kc++) {
                int stage = kc & 1;
                if (kc + 1 < 16) { loadA(kc + 1, stage ^ 1); CP_WAIT1(); }
                else             { CP_WAIT0(); }
                __syncthreads();
                const uint32_t sa = sbase + PK_AST + stage*8192;
                const uint32_t wbH = sbase + PK_WH + (uint32_t)(kc*4096);
                const uint32_t wbL = sbase + PK_WL + (uint32_t)(kc*4096);
                #pragma unroll
                for (int kh = 0; kh < 2; kh++) {
                    uint32_t aH[2][4], aL[2][4];
                    #pragma unroll
                    for (int mf = 0; mf < 2; mf++) {
                        int row  = wm*32 + mf*16 + (lane & 7) + ((lane >> 3) & 1)*8;
                        int kcol = kh*16 + ((lane >> 4) & 1)*8;
                        uint32_t off = sw_off(row, kcol >> 3);
                        LDSM4(aH[mf], sa + off);
                        LDSM4(aL[mf], sa + 4096 + off);
                    }
                    uint32_t bH[2][2], bL[2][2];
                    {
                        int row  = wn*16 + (lane & 7) + ((lane >> 4) & 1)*8;
                        int kcol = ((lane >> 3) & 1)*8 + kh*16;
                        uint32_t off = sw_off(row, kcol >> 3);
                        uint32_t r4[4];
                        LDSM4(r4, wbH + off);
                        bH[0][0]=r4[0]; bH[0][1]=r4[1]; bH[1][0]=r4[2]; bH[1][1]=r4[3];
                        LDSM4(r4, wbL + off);
                        bL[0][0]=r4[0]; bL[0][1]=r4[1]; bL[1][0]=r4[2]; bL[1][1]=r4[3];
                    }
                    #pragma unroll
                    for (int mf = 0; mf < 2; mf++)
                        #pragma unroll
                        for (int nf = 0; nf < 2; nf++) {
                            mma16816(acc[mf][nf], aH[mf], bH[nf]);
                            mma16816(acc[mf][nf], aH[mf], bL[nf]);
                            mma16816(acc[mf][nf], aL[mf], bH[nf]);
                        }
                }
                __syncthreads();
            }

            const int goff = g_off[t];
            #pragma unroll
            for (int mf = 0; mf < 2; mf++) {
                #pragma unroll
                for (int nf = 0; nf < 2; nf++) {
                    int rl = wm*32 + mf*16 + (lane >> 2);
                    int nl = wn*16 + nf*8 + 2*(lane & 3);
                    #pragma unroll
                    for (int half = 0; half < 2; half++) {
                        int rr = rl + half*8;
                        float2 gx2 = *(const float2*)(g_gx + (size_t)(goff + m0 + rr)*G4 + n0 + nl);
                        gs[rr*66 + nl]     = acc[mf][nf][half*2]   + gx2.x;
                        gs[rr*66 + nl + 1] = acc[mf][nf][half*2+1] + gx2.y;
                    }
                }
            }
            __syncthreads();

            #pragma unroll
            for (int p = 0; p < 4; p++) {
                int idx = tid + 256*p;
                int row = idx >> 4, u = idx & 15;
                int rg = m0 + row;
                if (rg < nact) {
                    float gi = gs[row*66 + u*4 + 0];
                    float gf = gs[row*66 + u*4 + 1];
                    float gc = gs[row*66 + u*4 + 2];
                    float go = gs[row*66 + u*4 + 3];
                    float cc = cst[row*16 + u];
                    cc = sigf(gf)*cc + sigf(gi)*tanhf(gc);
                    float hv = sigf(go)*tanhf(cc);
                    cst[row*16 + u] = cc;
                    int jg = (n0 >> 2) + u;
                    __nv_bfloat16 hhi = __float2bfloat16(hv);
                    __nv_bfloat16 hlo = __float2bfloat16(hv - __bfloat162float(hhi));
                    Oh[rg*Hdim + jg] = hhi;
                    Ol[rg*Hdim + jg] = hlo;
                    g_hall16[(size_t)(goff + rg)*Hdim + jg] = __float2half_rn(hv);
                }
            }
        }

        __syncthreads();
        if (tid == 0) {
            __threadfence();
            atomicAdd(&g_sync, 1u);
            unsigned target = 64u * (unsigned)(t + 1);
            while (atomicAdd(&g_sync, 0u) < target) { __nanosleep(32); }
            __threadfence();
        }
        __syncthreads();
    }
}

// ---------------------------------------------------------------------------
extern "C" void kernel_launch(void* const* d_in, const int* in_sizes, int n_in,
                              void* d_out, int out_size) {
    const float* features  = (const float*)d_in[0];
    const int*   captions  = (const int*)  d_in[1];
    const int*   lengths   = (const int*)  d_in[2];
    const float* embedding = (const float*)d_in[3];
    const float* W_ih      = (const float*)d_in[4];
    const float* W_hh      = (const float*)d_in[5];
    const float* b_ih      = (const float*)d_in[6];
    const float* b_hh      = (const float*)d_in[7];
    const float* fc_w      = (const float*)d_in[8];
    const float* fc_b      = (const float*)d_in[9];
    const float* ihw       = (const float*)d_in[10];
    const float* ihb       = (const float*)d_in[11];
    const float* icw       = (const float*)d_in[12];
    const float* icb       = (const float*)d_in[13];
    float* out = (float*)d_out;

    float *gx, *pbias, *ib;
    __nv_bfloat16 *mfh, *mfl, *iwh, *iwl, *embh, *embl;
    __nv_bfloat16 *wihh, *wihl, *whhh, *whhl;
    __half *fwh16, *hall16;
    cudaGetSymbolAddress((void**)&gx, g_gx);
    cudaGetSymbolAddress((void**)&pbias, g_pbias);
    cudaGetSymbolAddress((void**)&ib, g_ib);
    cudaGetSymbolAddress((void**)&mfh, g_mfh); cudaGetSymbolAddress((void**)&mfl, g_mfl);
    cudaGetSymbolAddress((void**)&iwh, g_iwh); cudaGetSymbolAddress((void**)&iwl, g_iwl);
    cudaGetSymbolAddress((void**)&embh, g_embh); cudaGetSymbolAddress((void**)&embl, g_embl);
    cudaGetSymbolAddress((void**)&wihh, g_wihh); cudaGetSymbolAddress((void**)&wihl, g_wihl);
    cudaGetSymbolAddress((void**)&whhh, g_whhh); cudaGetSymbolAddress((void**)&whhl, g_whhl);
    cudaGetSymbolAddress((void**)&fwh16, g_fwh16);
    cudaGetSymbolAddress((void**)&hall16, g_hall16);

    cudaFuncSetAttribute(mma_gemm<0>, cudaFuncAttributeMaxDynamicSharedMemorySize, DSM_BYTES);
    cudaFuncSetAttribute(mma_gemm<1>, cudaFuncAttributeMaxDynamicSharedMemorySize, DSM_BYTES);
    cudaFuncSetAttribute(fc_gemm, cudaFuncAttributeMaxDynamicSharedMemorySize, FC_DSM);
    cudaFuncSetAttribute(persist_step_kernel, cudaFuncAttributeMaxDynamicSharedMemorySize, PK_BYTES);

    // 0. row map (active + masked pads) + biases + sync reset
    setup_kernel<<<1, 256>>>(lengths, b_ih, b_hh, ihb, icb);

    // 1. mean pool + init weights split + init GEMM (h0 split + c0)
    meanpool_kernel<<<Bdim, 512>>>(features);
    split4_bf16<<<(512*512/4+255)/256, 256>>>(ihw, iwh, iwl, 512*512/4);
    split4_bf16<<<(512*512/4+255)/256, 256>>>(icw, iwh + 512*512, iwl + 512*512, 512*512/4);
    mma_gemm<1><<<dim3(8, 1), 256, DSM_BYTES>>>(mfh, mfl, iwh, iwl, nullptr, Bdim, 1024, ib);

    // 2. fc_w convert (fp16 single-term, 64x prescale)
    conv4_f16s<<<((size_t)Vdim*Hdim/4+255)/256, 256>>>(fc_w, fwh16, Vdim*Hdim/4);

    // 3. remaining operand prep
    gather_split_kernel<<<MT, 128>>>(embedding, captions);
    split_permute_kernel<<<(G4*128)/256, 256>>>(W_ih, wihh, wihl);
    split_permute_kernel<<<(G4*128)/256, 256>>>(W_hh, whhh, whhl);

    // 4. gx = emb @ W_ih'^T + pbias (compact rows)
    {
        dim3 grid(G4/128, MT/128);
        mma_gemm<0><<<grid, 256, DSM_BYTES>>>(embh, embl, wihh, wihl, gx, MT, G4, pbias);
    }

    // 5. full recurrence in ONE persistent launch
    persist_step_kernel<<<64, 256, PK_BYTES>>>();

    // 6. fc projection (fp16 single-term, 1/64 scale) + masked zeros fused
    {
        dim3 grid((Vdim + 127)/128, MT/128);
        fc_gemm<<<grid, 256, FC_DSM>>>(hall16, fwh16, out, fc_b);
    }
}

// round 9
// speedup vs baseline: 4.6345x; 1.0293x over previous
#include <cuda_runtime.h>
#include <cuda_bf16.h>
#include <cuda_fp16.h>
#include <cstdint>
#include <math.h>

#define Bdim 128
#define Tdim 32
#define Edim 512
#define Hdim 512
#define Vdim 10000
#define LFdim 49
#define G4 2048
#define MT 4096
#define Kdim 512

// ---------------- scratch (__device__ globals; no allocs allowed) ----------
__device__ float g_c[Bdim*Hdim];
__device__ float g_gx[(size_t)MT*G4];          // compact rows
__device__ float g_pbias[G4];                  // permuted b_ih+b_hh
__device__ float g_ib[1024];                   // stacked ihb|icb

__device__ int g_nact[Tdim];
__device__ int g_off[Tdim+1];
__device__ int g_Mc;
__device__ int g_map[MT];   // row -> (t<<8)|b ; bit16 set = masked (zero output)
__device__ unsigned int g_sync2[64];           // [0]=mtile0, [32]=mtile1

__device__ __nv_bfloat16 g_mfh[Bdim*Edim], g_mfl[Bdim*Edim];
__device__ __nv_bfloat16 g_iwh[(size_t)1024*Edim], g_iwl[(size_t)1024*Edim];
__device__ __nv_bfloat16 g_hh0[Bdim*Hdim], g_hl0[Bdim*Hdim];
__device__ __nv_bfloat16 g_hh1[Bdim*Hdim], g_hl1[Bdim*Hdim];
__device__ __nv_bfloat16 g_embh[(size_t)MT*Edim], g_embl[(size_t)MT*Edim];
__device__ __nv_bfloat16 g_wihh[(size_t)G4*Edim], g_wihl[(size_t)G4*Edim]; // permuted
__device__ __nv_bfloat16 g_whhh[(size_t)G4*Hdim], g_whhl[(size_t)G4*Hdim]; // permuted
__device__ __half g_fwh16[(size_t)Vdim*Hdim];  // 64x prescaled fp16
__device__ __half g_hall16[(size_t)MT*Hdim];   // compact, fp16

// ---------------- PTX helpers (sm_80-era: legal on base sm_100) ------------
__device__ __forceinline__ uint32_t smem_to_u32(const void* p) {
    uint32_t a;
    asm("{ .reg .u64 t; cvta.to.shared.u64 t, %1; cvt.u32.u64 %0, t; }" : "=r"(a) : "l"(p));
    return a;
}
__device__ __forceinline__ void cp16(uint32_t dst, const void* src, bool pred) {
    int sz = pred ? 16 : 0;
    asm volatile("cp.async.cg.shared.global [%0], [%1], 16, %2;"
                 :: "r"(dst), "l"(src), "r"(sz) : "memory");
}
#define CP_COMMIT() asm volatile("cp.async.commit_group;" ::: "memory")
#define CP_WAIT2()  asm volatile("cp.async.wait_group 2;" ::: "memory")
#define CP_WAIT1()  asm volatile("cp.async.wait_group 1;" ::: "memory")
#define CP_WAIT0()  asm volatile("cp.async.wait_group 0;" ::: "memory")
#define LDSM4(r, addr) \
    asm volatile("ldmatrix.sync.aligned.m8n8.x4.shared.b16 {%0,%1,%2,%3}, [%4];" \
        : "=r"((r)[0]), "=r"((r)[1]), "=r"((r)[2]), "=r"((r)[3]) : "r"(addr))

__device__ __forceinline__ void mma16816(float* c, const uint32_t* a, const uint32_t* b) {
    asm volatile("mma.sync.aligned.m16n8k16.row.col.f32.bf16.bf16.f32 "
        "{%0,%1,%2,%3}, {%4,%5,%6,%7}, {%8,%9}, {%0,%1,%2,%3};"
        : "+f"(c[0]), "+f"(c[1]), "+f"(c[2]), "+f"(c[3])
        : "r"(a[0]), "r"(a[1]), "r"(a[2]), "r"(a[3]), "r"(b[0]), "r"(b[1]));
}
__device__ __forceinline__ void mma16816h(float* c, const uint32_t* a, const uint32_t* b) {
    asm volatile("mma.sync.aligned.m16n8k16.row.col.f32.f16.f16.f32 "
        "{%0,%1,%2,%3}, {%4,%5,%6,%7}, {%8,%9}, {%0,%1,%2,%3};"
        : "+f"(c[0]), "+f"(c[1]), "+f"(c[2]), "+f"(c[3])
        : "r"(a[0]), "r"(a[1]), "r"(a[2]), "r"(a[3]), "r"(b[0]), "r"(b[1]));
}

// XOR swizzle for 64B-row tiles: row r, 16B chunk q
__device__ __forceinline__ uint32_t sw_off(int r, int q) {
    return (uint32_t)(r*64 + ((q ^ ((r >> 1) & 3)) << 4));
}

__device__ __forceinline__ float sigf(float x) { return 1.0f / (1.0f + expf(-x)); }

__device__ __forceinline__ uint32_t pack_bf2(float a, float b) {
    __nv_bfloat162 v = __floats2bfloat162_rn(a, b);
    return *(uint32_t*)&v;
}
__device__ __forceinline__ uint32_t pack_h2(float a, float b) {
    __half2 v = __floats2half2_rn(a, b);
    return *(uint32_t*)&v;
}

// ---------------------------------------------------------------------------
// setup: n_active(t), offsets, full row map (active + masked pads), biases
__global__ void setup_kernel(const int* __restrict__ lengths,
                             const float* __restrict__ b_ih,
                             const float* __restrict__ b_hh,
                             const float* __restrict__ ihb,
                             const float* __restrict__ icb) {
    __shared__ int s_len[Bdim];
    __shared__ int s_moff[Bdim];     // prefix of masked counts per batch
    int tid = threadIdx.x;
    if (tid < 64) g_sync2[tid] = 0u;
    if (tid < Bdim) s_len[tid] = lengths[tid];
    __syncthreads();
    if (tid < Tdim) {
        int cnt = 0;
        for (int b = 0; b < Bdim; b++) cnt += (s_len[b] > tid) ? 1 : 0;
        g_nact[tid] = cnt;
    }
    __syncthreads();
    if (tid == 0) {
        int acc = 0;
        for (int t = 0; t < Tdim; t++) { g_off[t] = acc; acc += g_nact[t]; }
        g_off[Tdim] = acc;
        g_Mc = acc;
        int macc = 0;
        for (int b = 0; b < Bdim; b++) { s_moff[b] = macc; macc += Tdim - s_len[b]; }
    }
    __syncthreads();
    int Mc = g_Mc;
    for (int r = tid; r < Mc; r += 256) {
        int t = 0;
        while (t < Tdim - 1 && r >= g_off[t+1]) t++;
        g_map[r] = (t << 8) | (r - g_off[t]);
    }
    // parallel pad-map fill: every (b, t) with t >= len[b]
    for (int i = tid; i < MT; i += 256) {
        int b = i >> 5, t = i & 31;
        if (t >= s_len[b]) {
            int rp = Mc + s_moff[b] + (t - s_len[b]);
            g_map[rp] = (t << 8) | b | 0x10000;
        }
    }
    for (int i = tid; i < G4; i += 256) {
        int j = i >> 2, g = i & 3;
        g_pbias[i] = b_ih[g*512 + j] + b_hh[g*512 + j];
    }
    for (int i = tid; i < 1024; i += 256)
        g_ib[i] = (i < 512) ? ihb[i] : icb[i - 512];
}

// ---------------------------------------------------------------------------
// gather embeddings into compact rows (vectorized; zero pads emb & hall16)
__global__ void gather_split_kernel(const float* __restrict__ emb,
                                    const int* __restrict__ cap) {
    int r = blockIdx.x;
    int v = g_map[r];
    int c4 = threadIdx.x * 4;          // 128 threads x 4 = 512
    if (v & 0x10000) {
        uint2 z = make_uint2(0u, 0u);
        *(uint2*)(g_embh + (size_t)r*Edim + c4) = z;
        *(uint2*)(g_embl + (size_t)r*Edim + c4) = z;
        *(uint2*)(g_hall16 + (size_t)r*Hdim + c4) = z;
        return;
    }
    int t = (v >> 8) & 0xFF, b = v & 0xFF;
    int tok = cap[b*Tdim + t];
    float4 x = *(const float4*)(emb + (size_t)tok*Edim + c4);
    float hx = __bfloat162float(__float2bfloat16(x.x));
    float hy = __bfloat162float(__float2bfloat16(x.y));
    float hz = __bfloat162float(__float2bfloat16(x.z));
    float hw = __bfloat162float(__float2bfloat16(x.w));
    *(uint2*)(g_embh + (size_t)r*Edim + c4) = make_uint2(pack_bf2(x.x, x.y), pack_bf2(x.z, x.w));
    *(uint2*)(g_embl + (size_t)r*Edim + c4) =
        make_uint2(pack_bf2(x.x - hx, x.y - hy), pack_bf2(x.z - hz, x.w - hw));
}

// split BOTH recurrent weights with gate permutation: out row 4j+g <- in row g*512+j
// blocks [0,1024): W_ih -> g_wihh/l ; [1024,2048): W_hh -> g_whhh/l
__global__ void split_permute2_kernel(const float* __restrict__ Wih,
                                      const float* __restrict__ Whh) {
    int bi = blockIdx.x;
    const float* W = (bi < 1024) ? Wih : Whh;
    __nv_bfloat16* hi = (bi < 1024) ? g_wihh : g_whhh;
    __nv_bfloat16* lo = (bi < 1024) ? g_wihl : g_whhl;
    int idx = (bi & 1023)*256 + threadIdx.x;
    int r = idx >> 7, c4 = (idx & 127) * 4;
    int j = r >> 2, g = r & 3;
    float4 x = *(const float4*)(W + (size_t)(g*512 + j)*512 + c4);
    float hx = __bfloat162float(__float2bfloat16(x.x));
    float hy = __bfloat162float(__float2bfloat16(x.y));
    float hz = __bfloat162float(__float2bfloat16(x.z));
    float hw = __bfloat162float(__float2bfloat16(x.w));
    *(uint2*)(hi + (size_t)r*512 + c4) = make_uint2(pack_bf2(x.x, x.y), pack_bf2(x.z, x.w));
    *(uint2*)(lo + (size_t)r*512 + c4) =
        make_uint2(pack_bf2(x.x - hx, x.y - hy), pack_bf2(x.z - hz, x.w - hw));
}

// stacked init-weight split: [ihw | icw] -> g_iwh/g_iwl (1024 x 512)
__global__ void split_init_kernel(const float* __restrict__ ihw,
                                  const float* __restrict__ icw) {
    int i = blockIdx.x*256 + threadIdx.x;       // 131072 float4 groups
    const int half = 512*512/4;                 // 65536
    const float* s = (i < half) ? ihw : icw;
    int li = (i < half) ? i : i - half;
    float4 x = ((const float4*)s)[li];
    float hx = __bfloat162float(__float2bfloat16(x.x));
    float hy = __bfloat162float(__float2bfloat16(x.y));
    float hz = __bfloat162float(__float2bfloat16(x.z));
    float hw = __bfloat162float(__float2bfloat16(x.w));
    ((uint2*)g_iwh)[i] = make_uint2(pack_bf2(x.x, x.y), pack_bf2(x.z, x.w));
    ((uint2*)g_iwl)[i] = make_uint2(pack_bf2(x.x - hx, x.y - hy), pack_bf2(x.z - hz, x.w - hw));
}

// vectorized fp16 convert with 64x prescale (fc_w, single-term)
__global__ void conv4_f16s(const float* __restrict__ s,
                           __half* __restrict__ hi, int n4) {
    int i = blockIdx.x*256 + threadIdx.x;
    if (i >= n4) return;
    float4 x = ((const float4*)s)[i];
    ((uint2*)hi)[i] = make_uint2(pack_h2(x.x*64.f, x.y*64.f), pack_h2(x.z*64.f, x.w*64.f));
}

// mean pool -> bf16 hi/lo split directly
__global__ void meanpool_kernel(const float* __restrict__ features) {
    int b = blockIdx.x, k = threadIdx.x;
    const float* p = features + (size_t)b*LFdim*512 + k;
    float s = 0.f;
    #pragma unroll
    for (int l = 0; l < LFdim; l++) s += p[l*512];
    s *= (1.0f/LFdim);
    __nv_bfloat16 h = __float2bfloat16(s);
    g_mfh[b*512 + k] = h;
    g_mfl[b*512 + k] = __float2bfloat16(s - __bfloat162float(h));
}

// ---------------------------------------------------------------------------
// bf16x3 GEMM via mma.sync (gx + init). Block 128x128, BK=32, 8 warps.
// MODE 0: C[m*N+n] = acc + b1[n]                (gx; early-exit m0>=Mc)
// MODE 1: init h0/c0: n<512 -> split-write g_hh0/g_hl0; n>=512 -> g_c (fp32)
#define TILE_B 8192
#define STAGE_B (4*TILE_B)
#define DSM_BYTES (2*STAGE_B)

template<int MODE>
__global__ void __launch_bounds__(256)
mma_gemm(const __nv_bfloat16* __restrict__ Ah, const __nv_bfloat16* __restrict__ Al,
         const __nv_bfloat16* __restrict__ Bh, const __nv_bfloat16* __restrict__ Bl,
         float* __restrict__ C, int M, int N,
         const float* __restrict__ b1)
{
    const int m0 = blockIdx.y * 128;
    if (MODE != 1 && m0 >= g_Mc) return;
    extern __shared__ char smem[];
    const uint32_t sbase = smem_to_u32(smem);
    const int tid = threadIdx.x;
    const int lane = tid & 31, wid = tid >> 5;
    const int wm = wid >> 2, wn = wid & 3;
    const int n0 = blockIdx.x * 128;

    float c[4][4][4];
    #pragma unroll
    for (int i = 0; i < 4; i++)
        #pragma unroll
        for (int j = 0; j < 4; j++)
            { c[i][j][0]=0.f; c[i][j][1]=0.f; c[i][j][2]=0.f; c[i][j][3]=0.f; }

    auto load_stage = [&](int kc, int stage) {
        const int k0 = kc * 32;
        const uint32_t st = sbase + stage * STAGE_B;
        #pragma unroll
        for (int i = 0; i < 2; i++) {
            int chunk = tid + 256*i;
            int r = chunk >> 2, q = chunk & 3;
            uint32_t off = sw_off(r, q);
            int mr = m0 + r;
            bool ap = mr < M;
            size_t ao = (size_t)(ap ? mr : (M-1))*Kdim + k0 + q*8;
            cp16(st + off,            Ah + ao, ap);
            cp16(st + TILE_B + off,   Al + ao, ap);
            int nr = n0 + r;
            bool bp = nr < N;
            size_t bo = (size_t)(bp ? nr : (N-1))*Kdim + k0 + q*8;
            cp16(st + 2*TILE_B + off, Bh + bo, bp);
            cp16(st + 3*TILE_B + off, Bl + bo, bp);
        }
        CP_COMMIT();
    };

    const int NK = Kdim / 32;
    load_stage(0, 0);
    for (int kc = 0; kc < NK; kc++) {
        int stage = kc & 1;
        if (kc + 1 < NK) { load_stage(kc + 1, stage ^ 1); CP_WAIT1(); }
        else             { CP_WAIT0(); }
        __syncthreads();
        const uint32_t sa = sbase + stage * STAGE_B;

        #pragma unroll
        for (int kh = 0; kh < 2; kh++) {
            uint32_t aH[4][4], aL[4][4];
            #pragma unroll
            for (int mf = 0; mf < 4; mf++) {
                int row  = wm*64 + mf*16 + (lane & 7) + ((lane >> 3) & 1)*8;
                int kcol = kh*16 + ((lane >> 4) & 1)*8;
                uint32_t off = sw_off(row, kcol >> 3);
                LDSM4(aH[mf], sa + off);
                LDSM4(aL[mf], sa + TILE_B + off);
            }
            uint32_t bH[4][2], bL[4][2];
            #pragma unroll
            for (int np = 0; np < 2; np++) {
                int row  = wn*32 + np*16 + (lane & 7) + ((lane >> 4) & 1)*8;
                int kcol = ((lane >> 3) & 1)*8 + kh*16;
                uint32_t off = sw_off(row, kcol >> 3);
                uint32_t r4[4];
                LDSM4(r4, sa + 2*TILE_B + off);
                bH[np*2][0]=r4[0]; bH[np*2][1]=r4[1];
                bH[np*2+1][0]=r4[2]; bH[np*2+1][1]=r4[3];
                LDSM4(r4, sa + 3*TILE_B + off);
                bL[np*2][0]=r4[0]; bL[np*2][1]=r4[1];
                bL[np*2+1][0]=r4[2]; bL[np*2+1][1]=r4[3];
            }
            #pragma unroll
            for (int mf = 0; mf < 4; mf++)
                #pragma unroll
                for (int nf = 0; nf < 4; nf++) {
                    mma16816(c[mf][nf], aH[mf], bH[nf]);
                    mma16816(c[mf][nf], aH[mf], bL[nf]);
                    mma16816(c[mf][nf], aL[mf], bH[nf]);
                }
        }
        __syncthreads();
    }

    #pragma unroll
    for (int mf = 0; mf < 4; mf++) {
        #pragma unroll
        for (int nf = 0; nf < 4; nf++) {
            int m = m0 + wm*64 + mf*16 + (lane >> 2);
            int n = n0 + wn*32 + nf*8 + 2*(lane & 3);
            if (n >= N) continue;
            #pragma unroll
            for (int half = 0; half < 2; half++) {
                int mm = m + half*8;
                if (MODE == 1 && mm >= M) continue;
                float v0 = c[mf][nf][half*2], v1 = c[mf][nf][half*2+1];
                if (MODE == 0) {
                    v0 += b1[n]; v1 += b1[n+1];
                    *(float2*)(C + (size_t)mm*N + n) = make_float2(v0, v1);
                } else {
                    v0 += b1[n]; v1 += b1[n+1];
                    if (n < 512) {
                        __nv_bfloat16 h0 = __float2bfloat16(v0);
                        g_hh0[mm*512 + n] = h0;
                        g_hl0[mm*512 + n] = __float2bfloat16(v0 - __bfloat162float(h0));
                        __nv_bfloat16 h1 = __float2bfloat16(v1);
                        g_hh0[mm*512 + n + 1] = h1;
                        g_hl0[mm*512 + n + 1] = __float2bfloat16(v1 - __bfloat162float(h1));
                    } else {
                        g_c[mm*512 + n - 512] = v0;
                        g_c[mm*512 + n - 511] = v1;
                    }
                }
            }
        }
    }
}

// ---------------------------------------------------------------------------
// fc GEMM: fp16 single-term, 3-stage pipeline.
// D = hall16 @ fwh16^T / 64 + fc_b for active rows; zeros for masked rows.
#define FC_TILE 8192
#define FC_STAGE (2*FC_TILE)    // A + B
#define FC_DSM (3*FC_STAGE)     // 48 KB

__global__ void __launch_bounds__(256)
fc_gemm(const __half* __restrict__ A, const __half* __restrict__ Bh,
        float* __restrict__ C, const float* __restrict__ b1)
{
    const int m0 = blockIdx.y * 128;
    extern __shared__ char smem[];
    const uint32_t sbase = smem_to_u32(smem);
    const int tid = threadIdx.x;
    const int lane = tid & 31, wid = tid >> 5;
    const int wm = wid >> 2, wn = wid & 3;
    const int n0 = blockIdx.x * 128;
    const int N = Vdim;

    float c[4][4][4];
    #pragma unroll
    for (int i = 0; i < 4; i++)
        #pragma unroll
        for (int j = 0; j < 4; j++)
            { c[i][j][0]=0.f; c[i][j][1]=0.f; c[i][j][2]=0.f; c[i][j][3]=0.f; }

    if (m0 < g_Mc) {   // tiles entirely in pad region skip the GEMM
        auto load_stage = [&](int kc, int stage) {
            const int k0 = kc * 32;
            const uint32_t st = sbase + stage * FC_STAGE;
            #pragma unroll
            for (int i = 0; i < 2; i++) {
                int chunk = tid + 256*i;
                int r = chunk >> 2, q = chunk & 3;
                uint32_t off = sw_off(r, q);
                size_t ao = (size_t)(m0 + r)*Kdim + k0 + q*8;
                cp16(st + off, A + ao, true);
                int nr = n0 + r;
                bool bp = nr < N;
                size_t bo = (size_t)(bp ? nr : (N-1))*Kdim + k0 + q*8;
                cp16(st + FC_TILE + off, Bh + bo, bp);
            }
            CP_COMMIT();
        };

        const int NK = Kdim / 32;   // 16
        load_stage(0, 0);
        load_stage(1, 1);
        for (int kc = 0; kc < NK; kc++) {
            int stage = kc % 3;
            if (kc + 2 < NK)      { load_stage(kc + 2, (kc + 2) % 3); CP_WAIT2(); }
            else if (kc + 1 < NK) { CP_WAIT1(); }
            else                  { CP_WAIT0(); }
            __syncthreads();
            const uint32_t sa = sbase + stage * FC_STAGE;

            #pragma unroll
            for (int kh = 0; kh < 2; kh++) {
                uint32_t aH[4][4];
                #pragma unroll
                for (int mf = 0; mf < 4; mf++) {
                    int row  = wm*64 + mf*16 + (lane & 7) + ((lane >> 3) & 1)*8;
                    int kcol = kh*16 + ((lane >> 4) & 1)*8;
                    LDSM4(aH[mf], sa + sw_off(row, kcol >> 3));
                }
                uint32_t bH[4][2];
                #pragma unroll
                for (int np = 0; np < 2; np++) {
                    int row  = wn*32 + np*16 + (lane & 7) + ((lane >> 4) & 1)*8;
                    int kcol = ((lane >> 3) & 1)*8 + kh*16;
                    uint32_t r4[4];
                    LDSM4(r4, sa + FC_TILE + sw_off(row, kcol >> 3));
                    bH[np*2][0]=r4[0]; bH[np*2][1]=r4[1];
                    bH[np*2+1][0]=r4[2]; bH[np*2+1][1]=r4[3];
                }
                #pragma unroll
                for (int mf = 0; mf < 4; mf++)
                    #pragma unroll
                    for (int nf = 0; nf < 4; nf++)
                        mma16816h(c[mf][nf], aH[mf], bH[nf]);
            }
            __syncthreads();
        }
    }

    const float inv = 0.015625f;   // 1/64
    #pragma unroll
    for (int mf = 0; mf < 4; mf++) {
        #pragma unroll
        for (int nf = 0; nf < 4; nf++) {
            int m = m0 + wm*64 + mf*16 + (lane >> 2);
            int n = n0 + wn*32 + nf*8 + 2*(lane & 3);
            if (n >= N) continue;
            #pragma unroll
            for (int half = 0; half < 2; half++) {
                int mm = m + half*8;
                int v = g_map[mm];
                int t = (v >> 8) & 0xFF, b = v & 0xFF;
                float2 o;
                if (v & 0x10000) {
                    o = make_float2(0.f, 0.f);
                } else {
                    o = make_float2(c[mf][nf][half*2]*inv   + b1[n],
                                    c[mf][nf][half*2+1]*inv + b1[n+1]);
                }
                *(float2*)(C + ((size_t)(b*Tdim + t))*Vdim + n) = o;
            }
        }
    }
}

// ---------------------------------------------------------------------------
// Persistent recurrence: all 32 steps in one launch.
// Per-mtile sync groups (32 blocks each); mtile 1 exits once nact <= 64.
#define PK_WH    0
#define PK_WL    65536
#define PK_AST   131072          // + stage*8192; lo at +4096
#define PK_GATES 147456          // float[64*66]
#define PK_CST   164352          // float[1024]
#define PK_BYTES 168448

__global__ void __launch_bounds__(256)
persist_step_kernel() {
    extern __shared__ char sm[];
    const uint32_t sbase = smem_to_u32(sm);
    const int tid = threadIdx.x;
    const int lane = tid & 31, wid = tid >> 5;
    const int wm = wid >> 2, wn = wid & 3;
    const int nslice = blockIdx.x & 31;
    const int mtile = blockIdx.x >> 5;
    const int n0 = nslice * 64;
    const int m0 = mtile * 64;
    unsigned int* syncc = &g_sync2[mtile * 32];

    {
        int r = tid >> 2, q = tid & 3;
        #pragma unroll
        for (int kc = 0; kc < 16; kc++) {
            uint32_t off = (uint32_t)(kc*4096) + sw_off(r, q);
            size_t go = (size_t)(n0 + r)*Hdim + kc*32 + q*8;
            cp16(sbase + PK_WH + off, g_whhh + go, true);
            cp16(sbase + PK_WL + off, g_whhl + go, true);
        }
        CP_COMMIT();
    }
    float* cst = (float*)(sm + PK_CST);
    for (int i = tid; i < 1024; i += 256) {
        int r = i >> 4, u = i & 15;
        cst[i] = g_c[(m0 + r)*Hdim + (n0 >> 2) + u];
    }
    CP_WAIT0();
    __syncthreads();

    float* gs = (float*)(sm + PK_GATES);
    int scount = 0;

    for (int t = 0; t < Tdim; t++) {
        const int nact = g_nact[t];
        if (mtile == 1 && nact <= 64) break;   // nact non-increasing: done forever
        const __nv_bfloat16* Ah = (t & 1) ? g_hh1 : g_hh0;
        const __nv_bfloat16* Al = (t & 1) ? g_hl1 : g_hl0;
        __nv_bfloat16* Oh = (t & 1) ? g_hh0 : g_hh1;
        __nv_bfloat16* Ol = (t & 1) ? g_hl0 : g_hl1;

        if (m0 < nact) {
            float acc[2][2][4];
            #pragma unroll
            for (int i = 0; i < 2; i++)
                #pragma unroll
                for (int j = 0; j < 2; j++)
                    { acc[i][j][0]=0.f; acc[i][j][1]=0.f; acc[i][j][2]=0.f; acc[i][j][3]=0.f; }

            auto loadA = [&](int kc, int stage) {
                const uint32_t st = sbase + PK_AST + stage*8192;
                int r = tid >> 2, q = tid & 3;
                uint32_t off = sw_off(r, q);
                size_t ao = (size_t)(m0 + r)*Hdim + kc*32 + q*8;
                cp16(st + off,        Ah + ao, true);
                cp16(st + 4096 + off, Al + ao, true);
                CP_COMMIT();
            };
            loadA(0, 0);
            for (int kc = 0; kc < 16; kc++) {
                int stage = kc & 1;
                if (kc + 1 < 16) { loadA(kc + 1, stage ^ 1); CP_WAIT1(); }
                else             { CP_WAIT0(); }
                __syncthreads();
                const uint32_t sa = sbase + PK_AST + stage*8192;
                const uint32_t wbH = sbase + PK_WH + (uint32_t)(kc*4096);
                const uint32_t wbL = sbase + PK_WL + (uint32_t)(kc*4096);
                #pragma unroll
                for (int kh = 0; kh < 2; kh++) {
                    uint32_t aH[2][4], aL[2][4];
                    #pragma unroll
                    for (int mf = 0; mf < 2; mf++) {
                        int row  = wm*32 + mf*16 + (lane & 7) + ((lane >> 3) & 1)*8;
                        int kcol = kh*16 + ((lane >> 4) & 1)*8;
                        uint32_t off = sw_off(row, kcol >> 3);
                        LDSM4(aH[mf], sa + off);
                        LDSM4(aL[mf], sa + 4096 + off);
                    }
                    uint32_t bH[2][2], bL[2][2];
                    {
                        int row  = wn*16 + (lane & 7) + ((lane >> 4) & 1)*8;
                        int kcol = ((lane >> 3) & 1)*8 + kh*16;
                        uint32_t off = sw_off(row, kcol >> 3);
                        uint32_t r4[4];
                        LDSM4(r4, wbH + off);
                        bH[0][0]=r4[0]; bH[0][1]=r4[1]; bH[1][0]=r4[2]; bH[1][1]=r4[3];
                        LDSM4(r4, wbL + off);
                        bL[0][0]=r4[0]; bL[0][1]=r4[1]; bL[1][0]=r4[2]; bL[1][1]=r4[3];
                    }
                    #pragma unroll
                    for (int mf = 0; mf < 2; mf++)
                        #pragma unroll
                        for (int nf = 0; nf < 2; nf++) {
                            mma16816(acc[mf][nf], aH[mf], bH[nf]);
                            mma16816(acc[mf][nf], aH[mf], bL[nf]);
                            mma16816(acc[mf][nf], aL[mf], bH[nf]);
                        }
                }
                __syncthreads();
            }

            const int goff = g_off[t];
            #pragma unroll
            for (int mf = 0; mf < 2; mf++) {
                #pragma unroll
                for (int nf = 0; nf < 2; nf++) {
                    int rl = wm*32 + mf*16 + (lane >> 2);
                    int nl = wn*16 + nf*8 + 2*(lane & 3);
                    #pragma unroll
                    for (int half = 0; half < 2; half++) {
                        int rr = rl + half*8;
                        float2 gx2 = *(const float2*)(g_gx + (size_t)(goff + m0 + rr)*G4 + n0 + nl);
                        gs[rr*66 + nl]     = acc[mf][nf][half*2]   + gx2.x;
                        gs[rr*66 + nl + 1] = acc[mf][nf][half*2+1] + gx2.y;
                    }
                }
            }
            __syncthreads();

            #pragma unroll
            for (int p = 0; p < 4; p++) {
                int idx = tid + 256*p;
                int row = idx >> 4, u = idx & 15;
                int rg = m0 + row;
                if (rg < nact) {
                    float gi = gs[row*66 + u*4 + 0];
                    float gf = gs[row*66 + u*4 + 1];
                    float gc = gs[row*66 + u*4 + 2];
                    float go = gs[row*66 + u*4 + 3];
                    float cc = cst[row*16 + u];
                    cc = sigf(gf)*cc + sigf(gi)*tanhf(gc);
                    float hv = sigf(go)*tanhf(cc);
                    cst[row*16 + u] = cc;
                    int jg = (n0 >> 2) + u;
                    __nv_bfloat16 hhi = __float2bfloat16(hv);
                    __nv_bfloat16 hlo = __float2bfloat16(hv - __bfloat162float(hhi));
                    Oh[rg*Hdim + jg] = hhi;
                    Ol[rg*Hdim + jg] = hlo;
                    g_hall16[(size_t)(goff + rg)*Hdim + jg] = __float2half_rn(hv);
                }
            }
        }

        // per-mtile grid sync (32 blocks)
        scount++;
        __syncthreads();
        if (tid == 0) {
            __threadfence();
            atomicAdd(syncc, 1u);
            unsigned target = 32u * (unsigned)scount;
            while (atomicAdd(syncc, 0u) < target) { __nanosleep(32); }
            __threadfence();
        }
        __syncthreads();
    }
}

// ---------------------------------------------------------------------------
extern "C" void kernel_launch(void* const* d_in, const int* in_sizes, int n_in,
                              void* d_out, int out_size) {
    const float* features  = (const float*)d_in[0];
    const int*   captions  = (const int*)  d_in[1];
    const int*   lengths   = (const int*)  d_in[2];
    const float* embedding = (const float*)d_in[3];
    const float* W_ih      = (const float*)d_in[4];
    const float* W_hh      = (const float*)d_in[5];
    const float* b_ih      = (const float*)d_in[6];
    const float* b_hh      = (const float*)d_in[7];
    const float* fc_w      = (const float*)d_in[8];
    const float* fc_b      = (const float*)d_in[9];
    const float* ihw       = (const float*)d_in[10];
    const float* ihb       = (const float*)d_in[11];
    const float* icw       = (const float*)d_in[12];
    const float* icb       = (const float*)d_in[13];
    float* out = (float*)d_out;

    float *gx, *pbias, *ib;
    __nv_bfloat16 *mfh, *mfl, *iwh, *iwl, *embh, *embl;
    __nv_bfloat16 *wihh, *wihl;
    __half *fwh16, *hall16;
    cudaGetSymbolAddress((void**)&gx, g_gx);
    cudaGetSymbolAddress((void**)&pbias, g_pbias);
    cudaGetSymbolAddress((void**)&ib, g_ib);
    cudaGetSymbolAddress((void**)&mfh, g_mfh); cudaGetSymbolAddress((void**)&mfl, g_mfl);
    cudaGetSymbolAddress((void**)&iwh, g_iwh); cudaGetSymbolAddress((void**)&iwl, g_iwl);
    cudaGetSymbolAddress((void**)&embh, g_embh); cudaGetSymbolAddress((void**)&embl, g_embl);
    cudaGetSymbolAddress((void**)&wihh, g_wihh); cudaGetSymbolAddress((void**)&wihl, g_wihl);
    cudaGetSymbolAddress((void**)&fwh16, g_fwh16);
    cudaGetSymbolAddress((void**)&hall16, g_hall16);

    cudaFuncSetAttribute(mma_gemm<0>, cudaFuncAttributeMaxDynamicSharedMemorySize, DSM_BYTES);
    cudaFuncSetAttribute(mma_gemm<1>, cudaFuncAttributeMaxDynamicSharedMemorySize, DSM_BYTES);
    cudaFuncSetAttribute(fc_gemm, cudaFuncAttributeMaxDynamicSharedMemorySize, FC_DSM);
    cudaFuncSetAttribute(persist_step_kernel, cudaFuncAttributeMaxDynamicSharedMemorySize, PK_BYTES);

    // 0. row map (active + masked pads, parallel) + biases + sync reset
    setup_kernel<<<1, 256>>>(lengths, b_ih, b_hh, ihb, icb);

    // 1. mean pool + init weights split (one launch) + init GEMM (h0 split + c0)
    meanpool_kernel<<<Bdim, 512>>>(features);
    split_init_kernel<<<(2*512*512/4)/256, 256>>>(ihw, icw);
    mma_gemm<1><<<dim3(8, 1), 256, DSM_BYTES>>>(mfh, mfl, iwh, iwl, nullptr, Bdim, 1024, ib);

    // 2. fc_w convert (fp16 single-term, 64x prescale)
    conv4_f16s<<<((size_t)Vdim*Hdim/4+255)/256, 256>>>(fc_w, fwh16, Vdim*Hdim/4);

    // 3. remaining operand prep (W_ih + W_hh in one launch)
    gather_split_kernel<<<MT, 128>>>(embedding, captions);
    split_permute2_kernel<<<2048, 256>>>(W_ih, W_hh);

    // 4. gx = emb @ W_ih'^T + pbias (compact rows)
    {
        dim3 grid(G4/128, MT/128);
        mma_gemm<0><<<grid, 256, DSM_BYTES>>>(embh, embl, wihh, wihl, gx, MT, G4, pbias);
    }

    // 5. full recurrence in ONE persistent launch
    persist_step_kernel<<<64, 256, PK_BYTES>>>();

    // 6. fc projection (fp16 single-term, 1/64 scale) + masked zeros fused
    {
        dim3 grid((Vdim + 127)/128, MT/128);
        fc_gemm<<<grid, 256, FC_DSM>>>(hall16, fwh16, out, fc_b);
    }
}

// round 10
// speedup vs baseline: 4.6864x; 1.0112x over previous
#include <cuda_runtime.h>
#include <cuda_bf16.h>
#include <cuda_fp16.h>
#include <cstdint>
#include <math.h>

#define Bdim 128
#define Tdim 32
#define Edim 512
#define Hdim 512
#define Vdim 10000
#define LFdim 49
#define G4 2048
#define MT 4096
#define Kdim 512

// ---------------- scratch (__device__ globals; no allocs allowed) ----------
__device__ float g_mf[Bdim*Edim];              // fp32 mean-pooled features
__device__ float g_c[Bdim*Hdim];
__device__ float g_gx[(size_t)MT*G4];          // compact rows
__device__ float g_pbias[G4];                  // permuted b_ih+b_hh

__device__ int g_nact[Tdim];
__device__ int g_off[Tdim+1];
__device__ int g_Mc;
__device__ int g_map[MT];   // row -> (t<<8)|b ; bit16 set = masked (zero output)
__device__ unsigned int g_sync2[64];           // [0]=mtile0, [32]=mtile1

__device__ __nv_bfloat16 g_hh0[Bdim*Hdim], g_hl0[Bdim*Hdim];
__device__ __nv_bfloat16 g_hh1[Bdim*Hdim], g_hl1[Bdim*Hdim];
__device__ __nv_bfloat16 g_embh[(size_t)MT*Edim], g_embl[(size_t)MT*Edim];
__device__ __nv_bfloat16 g_wihh[(size_t)G4*Edim], g_wihl[(size_t)G4*Edim]; // permuted
__device__ __nv_bfloat16 g_whhh[(size_t)G4*Hdim], g_whhl[(size_t)G4*Hdim]; // permuted
__device__ __half g_fwh16[(size_t)Vdim*Hdim];  // 64x prescaled fp16
__device__ __half g_hall16[(size_t)MT*Hdim];   // compact, fp16

// ---------------- PTX helpers (sm_80-era: legal on base sm_100) ------------
__device__ __forceinline__ uint32_t smem_to_u32(const void* p) {
    uint32_t a;
    asm("{ .reg .u64 t; cvta.to.shared.u64 t, %1; cvt.u32.u64 %0, t; }" : "=r"(a) : "l"(p));
    return a;
}
__device__ __forceinline__ void cp16(uint32_t dst, const void* src, bool pred) {
    int sz = pred ? 16 : 0;
    asm volatile("cp.async.cg.shared.global [%0], [%1], 16, %2;"
                 :: "r"(dst), "l"(src), "r"(sz) : "memory");
}
#define CP_COMMIT() asm volatile("cp.async.commit_group;" ::: "memory")
#define CP_WAIT2()  asm volatile("cp.async.wait_group 2;" ::: "memory")
#define CP_WAIT1()  asm volatile("cp.async.wait_group 1;" ::: "memory")
#define CP_WAIT0()  asm volatile("cp.async.wait_group 0;" ::: "memory")
#define LDSM4(r, addr) \
    asm volatile("ldmatrix.sync.aligned.m8n8.x4.shared.b16 {%0,%1,%2,%3}, [%4];" \
        : "=r"((r)[0]), "=r"((r)[1]), "=r"((r)[2]), "=r"((r)[3]) : "r"(addr))

__device__ __forceinline__ void mma16816(float* c, const uint32_t* a, const uint32_t* b) {
    asm volatile("mma.sync.aligned.m16n8k16.row.col.f32.bf16.bf16.f32 "
        "{%0,%1,%2,%3}, {%4,%5,%6,%7}, {%8,%9}, {%0,%1,%2,%3};"
        : "+f"(c[0]), "+f"(c[1]), "+f"(c[2]), "+f"(c[3])
        : "r"(a[0]), "r"(a[1]), "r"(a[2]), "r"(a[3]), "r"(b[0]), "r"(b[1]));
}
__device__ __forceinline__ void mma16816h(float* c, const uint32_t* a, const uint32_t* b) {
    asm volatile("mma.sync.aligned.m16n8k16.row.col.f32.f16.f16.f32 "
        "{%0,%1,%2,%3}, {%4,%5,%6,%7}, {%8,%9}, {%0,%1,%2,%3};"
        : "+f"(c[0]), "+f"(c[1]), "+f"(c[2]), "+f"(c[3])
        : "r"(a[0]), "r"(a[1]), "r"(a[2]), "r"(a[3]), "r"(b[0]), "r"(b[1]));
}

// XOR swizzle for 64B-row tiles: row r, 16B chunk q
__device__ __forceinline__ uint32_t sw_off(int r, int q) {
    return (uint32_t)(r*64 + ((q ^ ((r >> 1) & 3)) << 4));
}

__device__ __forceinline__ float sigf(float x) { return 1.0f / (1.0f + expf(-x)); }

__device__ __forceinline__ uint32_t pack_bf2(float a, float b) {
    __nv_bfloat162 v = __floats2bfloat162_rn(a, b);
    return *(uint32_t*)&v;
}
__device__ __forceinline__ uint32_t pack_h2(float a, float b) {
    __half2 v = __floats2half2_rn(a, b);
    return *(uint32_t*)&v;
}

// ---------------------------------------------------------------------------
// setup: n_active(t), offsets, full row map (active + masked pads), biases
__global__ void setup_kernel(const int* __restrict__ lengths,
                             const float* __restrict__ b_ih,
                             const float* __restrict__ b_hh) {
    __shared__ int s_len[Bdim];
    __shared__ int s_moff[Bdim];     // prefix of masked counts per batch
    int tid = threadIdx.x;
    if (tid < 64) g_sync2[tid] = 0u;
    if (tid < Bdim) s_len[tid] = lengths[tid];
    __syncthreads();
    if (tid < Tdim) {
        int cnt = 0;
        for (int b = 0; b < Bdim; b++) cnt += (s_len[b] > tid) ? 1 : 0;
        g_nact[tid] = cnt;
    }
    __syncthreads();
    if (tid == 0) {
        int acc = 0;
        for (int t = 0; t < Tdim; t++) { g_off[t] = acc; acc += g_nact[t]; }
        g_off[Tdim] = acc;
        g_Mc = acc;
        int macc = 0;
        for (int b = 0; b < Bdim; b++) { s_moff[b] = macc; macc += Tdim - s_len[b]; }
    }
    __syncthreads();
    int Mc = g_Mc;
    for (int r = tid; r < Mc; r += 256) {
        int t = 0;
        while (t < Tdim - 1 && r >= g_off[t+1]) t++;
        g_map[r] = (t << 8) | (r - g_off[t]);
    }
    // parallel pad-map fill: every (b, t) with t >= len[b]
    for (int i = tid; i < MT; i += 256) {
        int b = i >> 5, t = i & 31;
        if (t >= s_len[b]) {
            int rp = Mc + s_moff[b] + (t - s_len[b]);
            g_map[rp] = (t << 8) | b | 0x10000;
        }
    }
    for (int i = tid; i < G4; i += 256) {
        int j = i >> 2, g = i & 3;
        g_pbias[i] = b_ih[g*512 + j] + b_hh[g*512 + j];
    }
}

// ---------------------------------------------------------------------------
// mean pool -> fp32
__global__ void meanpool_kernel(const float* __restrict__ features) {
    int b = blockIdx.x, k = threadIdx.x;
    const float* p = features + (size_t)b*LFdim*512 + k;
    float s = 0.f;
    #pragma unroll
    for (int l = 0; l < LFdim; l++) s += p[l*512];
    g_mf[b*512 + k] = s * (1.0f/LFdim);
}

// exact fp32 init: h0 = mf@ihw^T+ihb (split to bf16), c0 = mf@icw^T+icb.
// 128 blocks x 8 stacked units; 256 threads: u=tid&7, 32 batch-groups x 4.
__global__ void __launch_bounds__(256)
init_kernel(const float* __restrict__ ihw, const float* __restrict__ icw,
            const float* __restrict__ ihb, const float* __restrict__ icb) {
    __shared__ float ws[8*512];      // 16 KB: this block's 8 weight rows
    const int nb = blockIdx.x * 8;   // stacked unit base (0..1016)
    const int tid = threadIdx.x;
    for (int i = tid; i < 8*128; i += 256) {    // 1024 float4 groups
        int rr = i >> 7, c4 = (i & 127) * 4;
        int n = nb + rr;
        const float* src = (n < 512) ? (ihw + (size_t)n*512 + c4)
                                     : (icw + (size_t)(n-512)*512 + c4);
        *(float4*)(ws + rr*512 + c4) = *(const float4*)src;
    }
    __syncthreads();

    const int u = tid & 7;
    const int bg = tid >> 3;         // 0..31, 4 batches each
    const int n = nb + u;
    const float bias = (n < 512) ? ihb[n] : icb[n - 512];
    const float* w = ws + u*512;
    const float* m0 = g_mf + (bg*4 + 0)*512;
    const float* m1 = g_mf + (bg*4 + 1)*512;
    const float* m2 = g_mf + (bg*4 + 2)*512;
    const float* m3 = g_mf + (bg*4 + 3)*512;
    float a0 = 0.f, a1 = 0.f, a2 = 0.f, a3 = 0.f;
    #pragma unroll 8
    for (int k = 0; k < 512; k += 4) {
        float4 wv = *(const float4*)(w + k);
        float4 x0 = *(const float4*)(m0 + k);
        float4 x1 = *(const float4*)(m1 + k);
        float4 x2 = *(const float4*)(m2 + k);
        float4 x3 = *(const float4*)(m3 + k);
        a0 = fmaf(wv.x, x0.x, fmaf(wv.y, x0.y, fmaf(wv.z, x0.z, fmaf(wv.w, x0.w, a0))));
        a1 = fmaf(wv.x, x1.x, fmaf(wv.y, x1.y, fmaf(wv.z, x1.z, fmaf(wv.w, x1.w, a1))));
        a2 = fmaf(wv.x, x2.x, fmaf(wv.y, x2.y, fmaf(wv.z, x2.z, fmaf(wv.w, x2.w, a2))));
        a3 = fmaf(wv.x, x3.x, fmaf(wv.y, x3.y, fmaf(wv.z, x3.z, fmaf(wv.w, x3.w, a3))));
    }
    float acc[4] = {a0 + bias, a1 + bias, a2 + bias, a3 + bias};
    #pragma unroll
    for (int i = 0; i < 4; i++) {
        int b = bg*4 + i;
        if (n < 512) {
            __nv_bfloat16 h = __float2bfloat16(acc[i]);
            g_hh0[b*512 + n] = h;
            g_hl0[b*512 + n] = __float2bfloat16(acc[i] - __bfloat162float(h));
        } else {
            g_c[b*512 + n - 512] = acc[i];
        }
    }
}

// ---------------------------------------------------------------------------
// gather embeddings into compact rows (vectorized; zero pads emb & hall16)
__global__ void gather_split_kernel(const float* __restrict__ emb,
                                    const int* __restrict__ cap) {
    int r = blockIdx.x;
    int v = g_map[r];
    int c4 = threadIdx.x * 4;          // 128 threads x 4 = 512
    if (v & 0x10000) {
        uint2 z = make_uint2(0u, 0u);
        *(uint2*)(g_embh + (size_t)r*Edim + c4) = z;
        *(uint2*)(g_embl + (size_t)r*Edim + c4) = z;
        *(uint2*)(g_hall16 + (size_t)r*Hdim + c4) = z;
        return;
    }
    int t = (v >> 8) & 0xFF, b = v & 0xFF;
    int tok = cap[b*Tdim + t];
    float4 x = *(const float4*)(emb + (size_t)tok*Edim + c4);
    float hx = __bfloat162float(__float2bfloat16(x.x));
    float hy = __bfloat162float(__float2bfloat16(x.y));
    float hz = __bfloat162float(__float2bfloat16(x.z));
    float hw = __bfloat162float(__float2bfloat16(x.w));
    *(uint2*)(g_embh + (size_t)r*Edim + c4) = make_uint2(pack_bf2(x.x, x.y), pack_bf2(x.z, x.w));
    *(uint2*)(g_embl + (size_t)r*Edim + c4) =
        make_uint2(pack_bf2(x.x - hx, x.y - hy), pack_bf2(x.z - hz, x.w - hw));
}

// split BOTH recurrent weights with gate permutation: out row 4j+g <- in row g*512+j
// blocks [0,1024): W_ih -> g_wihh/l ; [1024,2048): W_hh -> g_whhh/l
__global__ void split_permute2_kernel(const float* __restrict__ Wih,
                                      const float* __restrict__ Whh) {
    int bi = blockIdx.x;
    const float* W = (bi < 1024) ? Wih : Whh;
    __nv_bfloat16* hi = (bi < 1024) ? g_wihh : g_whhh;
    __nv_bfloat16* lo = (bi < 1024) ? g_wihl : g_whhl;
    int idx = (bi & 1023)*256 + threadIdx.x;
    int r = idx >> 7, c4 = (idx & 127) * 4;
    int j = r >> 2, g = r & 3;
    float4 x = *(const float4*)(W + (size_t)(g*512 + j)*512 + c4);
    float hx = __bfloat162float(__float2bfloat16(x.x));
    float hy = __bfloat162float(__float2bfloat16(x.y));
    float hz = __bfloat162float(__float2bfloat16(x.z));
    float hw = __bfloat162float(__float2bfloat16(x.w));
    *(uint2*)(hi + (size_t)r*512 + c4) = make_uint2(pack_bf2(x.x, x.y), pack_bf2(x.z, x.w));
    *(uint2*)(lo + (size_t)r*512 + c4) =
        make_uint2(pack_bf2(x.x - hx, x.y - hy), pack_bf2(x.z - hz, x.w - hw));
}

// vectorized fp16 convert with 64x prescale (fc_w, single-term)
__global__ void conv4_f16s(const float* __restrict__ s,
                           __half* __restrict__ hi, int n4) {
    int i = blockIdx.x*256 + threadIdx.x;
    if (i >= n4) return;
    float4 x = ((const float4*)s)[i];
    ((uint2*)hi)[i] = make_uint2(pack_h2(x.x*64.f, x.y*64.f), pack_h2(x.z*64.f, x.w*64.f));
}

// ---------------------------------------------------------------------------
// bf16x3 GEMM via mma.sync (gx). Block 128x128, BK=32, 8 warps.
// C[m*N+n] = acc + b1[n]; early-exit m0>=Mc.
#define TILE_B 8192
#define STAGE_B (4*TILE_B)
#define DSM_BYTES (2*STAGE_B)

__global__ void __launch_bounds__(256)
gx_gemm(const __nv_bfloat16* __restrict__ Ah, const __nv_bfloat16* __restrict__ Al,
        const __nv_bfloat16* __restrict__ Bh, const __nv_bfloat16* __restrict__ Bl,
        float* __restrict__ C, const float* __restrict__ b1)
{
    const int m0 = blockIdx.y * 128;
    if (m0 >= g_Mc) return;
    extern __shared__ char smem[];
    const uint32_t sbase = smem_to_u32(smem);
    const int tid = threadIdx.x;
    const int lane = tid & 31, wid = tid >> 5;
    const int wm = wid >> 2, wn = wid & 3;
    const int n0 = blockIdx.x * 128;
    const int N = G4;

    float c[4][4][4];
    #pragma unroll
    for (int i = 0; i < 4; i++)
        #pragma unroll
        for (int j = 0; j < 4; j++)
            { c[i][j][0]=0.f; c[i][j][1]=0.f; c[i][j][2]=0.f; c[i][j][3]=0.f; }

    auto load_stage = [&](int kc, int stage) {
        const int k0 = kc * 32;
        const uint32_t st = sbase + stage * STAGE_B;
        #pragma unroll
        for (int i = 0; i < 2; i++) {
            int chunk = tid + 256*i;
            int r = chunk >> 2, q = chunk & 3;
            uint32_t off = sw_off(r, q);
            size_t ao = (size_t)(m0 + r)*Kdim + k0 + q*8;
            cp16(st + off,            Ah + ao, true);
            cp16(st + TILE_B + off,   Al + ao, true);
            size_t bo = (size_t)(n0 + r)*Kdim + k0 + q*8;
            cp16(st + 2*TILE_B + off, Bh + bo, true);
            cp16(st + 3*TILE_B + off, Bl + bo, true);
        }
        CP_COMMIT();
    };

    const int NK = Kdim / 32;
    load_stage(0, 0);
    for (int kc = 0; kc < NK; kc++) {
        int stage = kc & 1;
        if (kc + 1 < NK) { load_stage(kc + 1, stage ^ 1); CP_WAIT1(); }
        else             { CP_WAIT0(); }
        __syncthreads();
        const uint32_t sa = sbase + stage * STAGE_B;

        #pragma unroll
        for (int kh = 0; kh < 2; kh++) {
            uint32_t aH[4][4], aL[4][4];
            #pragma unroll
            for (int mf = 0; mf < 4; mf++) {
                int row  = wm*64 + mf*16 + (lane & 7) + ((lane >> 3) & 1)*8;
                int kcol = kh*16 + ((lane >> 4) & 1)*8;
                uint32_t off = sw_off(row, kcol >> 3);
                LDSM4(aH[mf], sa + off);
                LDSM4(aL[mf], sa + TILE_B + off);
            }
            uint32_t bH[4][2], bL[4][2];
            #pragma unroll
            for (int np = 0; np < 2; np++) {
                int row  = wn*32 + np*16 + (lane & 7) + ((lane >> 4) & 1)*8;
                int kcol = ((lane >> 3) & 1)*8 + kh*16;
                uint32_t off = sw_off(row, kcol >> 3);
                uint32_t r4[4];
                LDSM4(r4, sa + 2*TILE_B + off);
                bH[np*2][0]=r4[0]; bH[np*2][1]=r4[1];
                bH[np*2+1][0]=r4[2]; bH[np*2+1][1]=r4[3];
                LDSM4(r4, sa + 3*TILE_B + off);
                bL[np*2][0]=r4[0]; bL[np*2][1]=r4[1];
                bL[np*2+1][0]=r4[2]; bL[np*2+1][1]=r4[3];
            }
            #pragma unroll
            for (int mf = 0; mf < 4; mf++)
                #pragma unroll
                for (int nf = 0; nf < 4; nf++) {
                    mma16816(c[mf][nf], aH[mf], bH[nf]);
                    mma16816(c[mf][nf], aH[mf], bL[nf]);
                    mma16816(c[mf][nf], aL[mf], bH[nf]);
                }
        }
        __syncthreads();
    }

    #pragma unroll
    for (int mf = 0; mf < 4; mf++) {
        #pragma unroll
        for (int nf = 0; nf < 4; nf++) {
            int m = m0 + wm*64 + mf*16 + (lane >> 2);
            int n = n0 + wn*32 + nf*8 + 2*(lane & 3);
            #pragma unroll
            for (int half = 0; half < 2; half++) {
                int mm = m + half*8;
                float v0 = c[mf][nf][half*2]   + b1[n];
                float v1 = c[mf][nf][half*2+1] + b1[n+1];
                *(float2*)(C + (size_t)mm*N + n) = make_float2(v0, v1);
            }
        }
    }
}

// ---------------------------------------------------------------------------
// fc GEMM: fp16 single-term, 3-stage pipeline.
// D = hall16 @ fwh16^T / 64 + fc_b for active rows; zeros for masked rows.
#define FC_TILE 8192
#define FC_STAGE (2*FC_TILE)    // A + B
#define FC_DSM (3*FC_STAGE)     // 48 KB

__global__ void __launch_bounds__(256)
fc_gemm(const __half* __restrict__ A, const __half* __restrict__ Bh,
        float* __restrict__ C, const float* __restrict__ b1)
{
    const int m0 = blockIdx.y * 128;
    extern __shared__ char smem[];
    const uint32_t sbase = smem_to_u32(smem);
    const int tid = threadIdx.x;
    const int lane = tid & 31, wid = tid >> 5;
    const int wm = wid >> 2, wn = wid & 3;
    const int n0 = blockIdx.x * 128;
    const int N = Vdim;

    float c[4][4][4];
    #pragma unroll
    for (int i = 0; i < 4; i++)
        #pragma unroll
        for (int j = 0; j < 4; j++)
            { c[i][j][0]=0.f; c[i][j][1]=0.f; c[i][j][2]=0.f; c[i][j][3]=0.f; }

    if (m0 < g_Mc) {   // tiles entirely in pad region skip the GEMM
        auto load_stage = [&](int kc, int stage) {
            const int k0 = kc * 32;
            const uint32_t st = sbase + stage * FC_STAGE;
            #pragma unroll
            for (int i = 0; i < 2; i++) {
                int chunk = tid + 256*i;
                int r = chunk >> 2, q = chunk & 3;
                uint32_t off = sw_off(r, q);
                size_t ao = (size_t)(m0 + r)*Kdim + k0 + q*8;
                cp16(st + off, A + ao, true);
                int nr = n0 + r;
                bool bp = nr < N;
                size_t bo = (size_t)(bp ? nr : (N-1))*Kdim + k0 + q*8;
                cp16(st + FC_TILE + off, Bh + bo, bp);
            }
            CP_COMMIT();
        };

        const int NK = Kdim / 32;   // 16
        load_stage(0, 0);
        load_stage(1, 1);
        for (int kc = 0; kc < NK; kc++) {
            int stage = kc % 3;
            if (kc + 2 < NK)      { load_stage(kc + 2, (kc + 2) % 3); CP_WAIT2(); }
            else if (kc + 1 < NK) { CP_WAIT1(); }
            else                  { CP_WAIT0(); }
            __syncthreads();
            const uint32_t sa = sbase + stage * FC_STAGE;

            #pragma unroll
            for (int kh = 0; kh < 2; kh++) {
                uint32_t aH[4][4];
                #pragma unroll
                for (int mf = 0; mf < 4; mf++) {
                    int row  = wm*64 + mf*16 + (lane & 7) + ((lane >> 3) & 1)*8;
                    int kcol = kh*16 + ((lane >> 4) & 1)*8;
                    LDSM4(aH[mf], sa + sw_off(row, kcol >> 3));
                }
                uint32_t bH[4][2];
                #pragma unroll
                for (int np = 0; np < 2; np++) {
                    int row  = wn*32 + np*16 + (lane & 7) + ((lane >> 4) & 1)*8;
                    int kcol = ((lane >> 3) & 1)*8 + kh*16;
                    uint32_t r4[4];
                    LDSM4(r4, sa + FC_TILE + sw_off(row, kcol >> 3));
                    bH[np*2][0]=r4[0]; bH[np*2][1]=r4[1];
                    bH[np*2+1][0]=r4[2]; bH[np*2+1][1]=r4[3];
                }
                #pragma unroll
                for (int mf = 0; mf < 4; mf++)
                    #pragma unroll
                    for (int nf = 0; nf < 4; nf++)
                        mma16816h(c[mf][nf], aH[mf], bH[nf]);
            }
            __syncthreads();
        }
    }

    const float inv = 0.015625f;   // 1/64
    #pragma unroll
    for (int mf = 0; mf < 4; mf++) {
        #pragma unroll
        for (int nf = 0; nf < 4; nf++) {
            int m = m0 + wm*64 + mf*16 + (lane >> 2);
            int n = n0 + wn*32 + nf*8 + 2*(lane & 3);
            if (n >= N) continue;
            #pragma unroll
            for (int half = 0; half < 2; half++) {
                int mm = m + half*8;
                int v = g_map[mm];
                int t = (v >> 8) & 0xFF, b = v & 0xFF;
                float2 o;
                if (v & 0x10000) {
                    o = make_float2(0.f, 0.f);
                } else {
                    o = make_float2(c[mf][nf][half*2]*inv   + b1[n],
                                    c[mf][nf][half*2+1]*inv + b1[n+1]);
                }
                *(float2*)(C + ((size_t)(b*Tdim + t))*Vdim + n) = o;
            }
        }
    }
}

// ---------------------------------------------------------------------------
// Persistent recurrence: all 32 steps in one launch.
// Per-mtile sync groups (32 blocks each); mtile 1 exits once nact <= 64.
#define PK_WH    0
#define PK_WL    65536
#define PK_AST   131072          // + stage*8192; lo at +4096
#define PK_GATES 147456          // float[64*66]
#define PK_CST   164352          // float[1024]
#define PK_BYTES 168448

__global__ void __launch_bounds__(256)
persist_step_kernel() {
    extern __shared__ char sm[];
    const uint32_t sbase = smem_to_u32(sm);
    const int tid = threadIdx.x;
    const int lane = tid & 31, wid = tid >> 5;
    const int wm = wid >> 2, wn = wid & 3;
    const int nslice = blockIdx.x & 31;
    const int mtile = blockIdx.x >> 5;
    const int n0 = nslice * 64;
    const int m0 = mtile * 64;
    unsigned int* syncc = &g_sync2[mtile * 32];

    {
        int r = tid >> 2, q = tid & 3;
        #pragma unroll
        for (int kc = 0; kc < 16; kc++) {
            uint32_t off = (uint32_t)(kc*4096) + sw_off(r, q);
            size_t go = (size_t)(n0 + r)*Hdim + kc*32 + q*8;
            cp16(sbase + PK_WH + off, g_whhh + go, true);
            cp16(sbase + PK_WL + off, g_whhl + go, true);
        }
        CP_COMMIT();
    }
    float* cst = (float*)(sm + PK_CST);
    for (int i = tid; i < 1024; i += 256) {
        int r = i >> 4, u = i & 15;
        cst[i] = g_c[(m0 + r)*Hdim + (n0 >> 2) + u];
    }
    CP_WAIT0();
    __syncthreads();

    float* gs = (float*)(sm + PK_GATES);
    int scount = 0;

    for (int t = 0; t < Tdim; t++) {
        const int nact = g_nact[t];
        if (mtile == 1 && nact <= 64) break;   // nact non-increasing: done forever
        const __nv_bfloat16* Ah = (t & 1) ? g_hh1 : g_hh0;
        const __nv_bfloat16* Al = (t & 1) ? g_hl1 : g_hl0;
        __nv_bfloat16* Oh = (t & 1) ? g_hh0 : g_hh1;
        __nv_bfloat16* Ol = (t & 1) ? g_hl0 : g_hl1;

        if (m0 < nact) {
            float acc[2][2][4];
            #pragma unroll
            for (int i = 0; i < 2; i++)
                #pragma unroll
                for (int j = 0; j < 2; j++)
                    { acc[i][j][0]=0.f; acc[i][j][1]=0.f; acc[i][j][2]=0.f; acc[i][j][3]=0.f; }

            auto loadA = [&](int kc, int stage) {
                const uint32_t st = sbase + PK_AST + stage*8192;
                int r = tid >> 2, q = tid & 3;
                uint32_t off = sw_off(r, q);
                size_t ao = (size_t)(m0 + r)*Hdim + kc*32 + q*8;
                cp16(st + off,        Ah + ao, true);
                cp16(st + 4096 + off, Al + ao, true);
                CP_COMMIT();
            };
            loadA(0, 0);
            for (int kc = 0; kc < 16; kc++) {
                int stage = kc & 1;
                if (kc + 1 < 16) { loadA(kc + 1, stage ^ 1); CP_WAIT1(); }
                else             { CP_WAIT0(); }
                __syncthreads();
                const uint32_t sa = sbase + PK_AST + stage*8192;
                const uint32_t wbH = sbase + PK_WH + (uint32_t)(kc*4096);
                const uint32_t wbL = sbase + PK_WL + (uint32_t)(kc*4096);
                #pragma unroll
                for (int kh = 0; kh < 2; kh++) {
                    uint32_t aH[2][4], aL[2][4];
                    #pragma unroll
                    for (int mf = 0; mf < 2; mf++) {
                        int row  = wm*32 + mf*16 + (lane & 7) + ((lane >> 3) & 1)*8;
                        int kcol = kh*16 + ((lane >> 4) & 1)*8;
                        uint32_t off = sw_off(row, kcol >> 3);
                        LDSM4(aH[mf], sa + off);
                        LDSM4(aL[mf], sa + 4096 + off);
                    }
                    uint32_t bH[2][2], bL[2][2];
                    {
                        int row  = wn*16 + (lane & 7) + ((lane >> 4) & 1)*8;
                        int kcol = ((lane >> 3) & 1)*8 + kh*16;
                        uint32_t off = sw_off(row, kcol >> 3);
                        uint32_t r4[4];
                        LDSM4(r4, wbH + off);
                        bH[0][0]=r4[0]; bH[0][1]=r4[1]; bH[1][0]=r4[2]; bH[1][1]=r4[3];
                        LDSM4(r4, wbL + off);
                        bL[0][0]=r4[0]; bL[0][1]=r4[1]; bL[1][0]=r4[2]; bL[1][1]=r4[3];
                    }
                    #pragma unroll
                    for (int mf = 0; mf < 2; mf++)
                        #pragma unroll
                        for (int nf = 0; nf < 2; nf++) {
                            mma16816(acc[mf][nf], aH[mf], bH[nf]);
                            mma16816(acc[mf][nf], aH[mf], bL[nf]);
                            mma16816(acc[mf][nf], aL[mf], bH[nf]);
                        }
                }
                __syncthreads();
            }

            const int goff = g_off[t];
            #pragma unroll
            for (int mf = 0; mf < 2; mf++) {
                #pragma unroll
                for (int nf = 0; nf < 2; nf++) {
                    int rl = wm*32 + mf*16 + (lane >> 2);
                    int nl = wn*16 + nf*8 + 2*(lane & 3);
                    #pragma unroll
                    for (int half = 0; half < 2; half++) {
                        int rr = rl + half*8;
                        float2 gx2 = *(const float2*)(g_gx + (size_t)(goff + m0 + rr)*G4 + n0 + nl);
                        gs[rr*66 + nl]     = acc[mf][nf][half*2]   + gx2.x;
                        gs[rr*66 + nl + 1] = acc[mf][nf][half*2+1] + gx2.y;
                    }
                }
            }
            __syncthreads();

            #pragma unroll
            for (int p = 0; p < 4; p++) {
                int idx = tid + 256*p;
                int row = idx >> 4, u = idx & 15;
                int rg = m0 + row;
                if (rg < nact) {
                    float gi = gs[row*66 + u*4 + 0];
                    float gf = gs[row*66 + u*4 + 1];
                    float gc = gs[row*66 + u*4 + 2];
                    float go = gs[row*66 + u*4 + 3];
                    float cc = cst[row*16 + u];
                    cc = sigf(gf)*cc + sigf(gi)*tanhf(gc);
                    float hv = sigf(go)*tanhf(cc);
                    cst[row*16 + u] = cc;
                    int jg = (n0 >> 2) + u;
                    __nv_bfloat16 hhi = __float2bfloat16(hv);
                    __nv_bfloat16 hlo = __float2bfloat16(hv - __bfloat162float(hhi));
                    Oh[rg*Hdim + jg] = hhi;
                    Ol[rg*Hdim + jg] = hlo;
                    g_hall16[(size_t)(goff + rg)*Hdim + jg] = __float2half_rn(hv);
                }
            }
        }

        // per-mtile grid sync (32 blocks)
        scount++;
        __syncthreads();
        if (tid == 0) {
            __threadfence();
            atomicAdd(syncc, 1u);
            unsigned target = 32u * (unsigned)scount;
            while (atomicAdd(syncc, 0u) < target) { __nanosleep(32); }
            __threadfence();
        }
        __syncthreads();
    }
}

// ---------------------------------------------------------------------------
extern "C" void kernel_launch(void* const* d_in, const int* in_sizes, int n_in,
                              void* d_out, int out_size) {
    const float* features  = (const float*)d_in[0];
    const int*   captions  = (const int*)  d_in[1];
    const int*   lengths   = (const int*)  d_in[2];
    const float* embedding = (const float*)d_in[3];
    const float* W_ih      = (const float*)d_in[4];
    const float* W_hh      = (const float*)d_in[5];
    const float* b_ih      = (const float*)d_in[6];
    const float* b_hh      = (const float*)d_in[7];
    const float* fc_w      = (const float*)d_in[8];
    const float* fc_b      = (const float*)d_in[9];
    const float* ihw       = (const float*)d_in[10];
    const float* ihb       = (const float*)d_in[11];
    const float* icw       = (const float*)d_in[12];
    const float* icb       = (const float*)d_in[13];
    float* out = (float*)d_out;

    float *gx, *pbias;
    __nv_bfloat16 *embh, *embl, *wihh, *wihl;
    __half *fwh16, *hall16;
    cudaGetSymbolAddress((void**)&gx, g_gx);
    cudaGetSymbolAddress((void**)&pbias, g_pbias);
    cudaGetSymbolAddress((void**)&embh, g_embh); cudaGetSymbolAddress((void**)&embl, g_embl);
    cudaGetSymbolAddress((void**)&wihh, g_wihh); cudaGetSymbolAddress((void**)&wihl, g_wihl);
    cudaGetSymbolAddress((void**)&fwh16, g_fwh16);
    cudaGetSymbolAddress((void**)&hall16, g_hall16);

    cudaFuncSetAttribute(gx_gemm, cudaFuncAttributeMaxDynamicSharedMemorySize, DSM_BYTES);
    cudaFuncSetAttribute(fc_gemm, cudaFuncAttributeMaxDynamicSharedMemorySize, FC_DSM);
    cudaFuncSetAttribute(persist_step_kernel, cudaFuncAttributeMaxDynamicSharedMemorySize, PK_BYTES);

    // 0. row map (active + masked pads, parallel) + biases + sync reset
    setup_kernel<<<1, 256>>>(lengths, b_ih, b_hh);

    // 1. mean pool + exact fp32 init (h0 split-to-bf16 + c0)
    meanpool_kernel<<<Bdim, 512>>>(features);
    init_kernel<<<128, 256>>>(ihw, icw, ihb, icb);

    // 2. fc_w convert (fp16 single-term, 64x prescale)
    conv4_f16s<<<((size_t)Vdim*Hdim/4+255)/256, 256>>>(fc_w, fwh16, Vdim*Hdim/4);

    // 3. remaining operand prep (W_ih + W_hh in one launch)
    gather_split_kernel<<<MT, 128>>>(embedding, captions);
    split_permute2_kernel<<<2048, 256>>>(W_ih, W_hh);

    // 4. gx = emb @ W_ih'^T + pbias (compact rows)
    {
        dim3 grid(G4/128, MT/128);
        gx_gemm<<<grid, 256, DSM_BYTES>>>(embh, embl, wihh, wihl, gx, pbias);
    }

    // 5. full recurrence in ONE persistent launch
    persist_step_kernel<<<64, 256, PK_BYTES>>>();

    // 6. fc projection (fp16 single-term, 1/64 scale) + masked zeros fused
    {
        dim3 grid((Vdim + 127)/128, MT/128);
        fc_gemm<<<grid, 256, FC_DSM>>>(hall16, fwh16, out, fc_b);
    }
}

// round 11
// speedup vs baseline: 5.7304x; 1.2228x over previous
#include <cuda_runtime.h>
#include <cuda_bf16.h>
#include <cuda_fp16.h>
#include <cstdint>
#include <math.h>

#define Bdim 128
#define Tdim 32
#define Edim 512
#define Hdim 512
#define Vdim 10000
#define LFdim 49
#define G4 2048
#define MT 4096
#define Kdim 512

// ---------------- scratch (__device__ globals; no allocs allowed) ----------
__device__ float g_mf[Bdim*Edim];              // fp32 mean-pooled features
__device__ float g_c[Bdim*Hdim];
__device__ float g_gx[(size_t)MT*G4];          // compact rows
__device__ float g_pbias[G4];                  // permuted b_ih+b_hh

__device__ int g_nact[Tdim];
__device__ int g_off[Tdim+1];
__device__ int g_Mc;
__device__ int g_map[MT];   // row -> (t<<8)|b ; bit16 set = masked (zero output)
__device__ unsigned int g_sync2[128];          // per-mtile counters at [mtile*32]

__device__ __nv_bfloat16 g_hh0[Bdim*Hdim], g_hl0[Bdim*Hdim];
__device__ __nv_bfloat16 g_hh1[Bdim*Hdim], g_hl1[Bdim*Hdim];
__device__ __nv_bfloat16 g_embh[(size_t)MT*Edim], g_embl[(size_t)MT*Edim];
__device__ __nv_bfloat16 g_wihh[(size_t)G4*Edim], g_wihl[(size_t)G4*Edim]; // permuted
__device__ __nv_bfloat16 g_whhh[(size_t)G4*Hdim], g_whhl[(size_t)G4*Hdim]; // permuted
__device__ __half g_fwh16[(size_t)Vdim*Hdim];  // 64x prescaled fp16
__device__ __half g_hall16[(size_t)MT*Hdim];   // compact, fp16

// ---------------- PTX helpers (sm_80-era: legal on base sm_100) ------------
__device__ __forceinline__ uint32_t smem_to_u32(const void* p) {
    uint32_t a;
    asm("{ .reg .u64 t; cvta.to.shared.u64 t, %1; cvt.u32.u64 %0, t; }" : "=r"(a) : "l"(p));
    return a;
}
__device__ __forceinline__ void cp16(uint32_t dst, const void* src, bool pred) {
    int sz = pred ? 16 : 0;
    asm volatile("cp.async.cg.shared.global [%0], [%1], 16, %2;"
                 :: "r"(dst), "l"(src), "r"(sz) : "memory");
}
#define CP_COMMIT() asm volatile("cp.async.commit_group;" ::: "memory")
#define CP_WAIT2()  asm volatile("cp.async.wait_group 2;" ::: "memory")
#define CP_WAIT1()  asm volatile("cp.async.wait_group 1;" ::: "memory")
#define CP_WAIT0()  asm volatile("cp.async.wait_group 0;" ::: "memory")
#define LDSM4(r, addr) \
    asm volatile("ldmatrix.sync.aligned.m8n8.x4.shared.b16 {%0,%1,%2,%3}, [%4];" \
        : "=r"((r)[0]), "=r"((r)[1]), "=r"((r)[2]), "=r"((r)[3]) : "r"(addr))

__device__ __forceinline__ void mma16816(float* c, const uint32_t* a, const uint32_t* b) {
    asm volatile("mma.sync.aligned.m16n8k16.row.col.f32.bf16.bf16.f32 "
        "{%0,%1,%2,%3}, {%4,%5,%6,%7}, {%8,%9}, {%0,%1,%2,%3};"
        : "+f"(c[0]), "+f"(c[1]), "+f"(c[2]), "+f"(c[3])
        : "r"(a[0]), "r"(a[1]), "r"(a[2]), "r"(a[3]), "r"(b[0]), "r"(b[1]));
}
__device__ __forceinline__ void mma16816h(float* c, const uint32_t* a, const uint32_t* b) {
    asm volatile("mma.sync.aligned.m16n8k16.row.col.f32.f16.f16.f32 "
        "{%0,%1,%2,%3}, {%4,%5,%6,%7}, {%8,%9}, {%0,%1,%2,%3};"
        : "+f"(c[0]), "+f"(c[1]), "+f"(c[2]), "+f"(c[3])
        : "r"(a[0]), "r"(a[1]), "r"(a[2]), "r"(a[3]), "r"(b[0]), "r"(b[1]));
}

// XOR swizzle for 64B-row tiles: row r, 16B chunk q
__device__ __forceinline__ uint32_t sw_off(int r, int q) {
    return (uint32_t)(r*64 + ((q ^ ((r >> 1) & 3)) << 4));
}

__device__ __forceinline__ float sigf(float x) { return 1.0f / (1.0f + expf(-x)); }

__device__ __forceinline__ uint32_t pack_bf2(float a, float b) {
    __nv_bfloat162 v = __floats2bfloat162_rn(a, b);
    return *(uint32_t*)&v;
}
__device__ __forceinline__ uint32_t pack_h2(float a, float b) {
    __half2 v = __floats2half2_rn(a, b);
    return *(uint32_t*)&v;
}

// ---------------------------------------------------------------------------
// setup: n_active(t), offsets, full row map (active + masked pads), biases
__global__ void setup_kernel(const int* __restrict__ lengths,
                             const float* __restrict__ b_ih,
                             const float* __restrict__ b_hh) {
    __shared__ int s_len[Bdim];
    __shared__ int s_moff[Bdim];     // prefix of masked counts per batch
    int tid = threadIdx.x;
    if (tid < 128) g_sync2[tid] = 0u;
    if (tid < Bdim) s_len[tid] = lengths[tid];
    __syncthreads();
    if (tid < Tdim) {
        int cnt = 0;
        for (int b = 0; b < Bdim; b++) cnt += (s_len[b] > tid) ? 1 : 0;
        g_nact[tid] = cnt;
    }
    __syncthreads();
    if (tid == 0) {
        int acc = 0;
        for (int t = 0; t < Tdim; t++) { g_off[t] = acc; acc += g_nact[t]; }
        g_off[Tdim] = acc;
        g_Mc = acc;
        int macc = 0;
        for (int b = 0; b < Bdim; b++) { s_moff[b] = macc; macc += Tdim - s_len[b]; }
    }
    __syncthreads();
    int Mc = g_Mc;
    for (int r = tid; r < Mc; r += 256) {
        int t = 0;
        while (t < Tdim - 1 && r >= g_off[t+1]) t++;
        g_map[r] = (t << 8) | (r - g_off[t]);
    }
    // parallel pad-map fill: every (b, t) with t >= len[b]
    for (int i = tid; i < MT; i += 256) {
        int b = i >> 5, t = i & 31;
        if (t >= s_len[b]) {
            int rp = Mc + s_moff[b] + (t - s_len[b]);
            g_map[rp] = (t << 8) | b | 0x10000;
        }
    }
    for (int i = tid; i < G4; i += 256) {
        int j = i >> 2, g = i & 3;
        g_pbias[i] = b_ih[g*512 + j] + b_hh[g*512 + j];
    }
}

// ---------------------------------------------------------------------------
// mean pool -> fp32
__global__ void meanpool_kernel(const float* __restrict__ features) {
    int b = blockIdx.x, k = threadIdx.x;
    const float* p = features + (size_t)b*LFdim*512 + k;
    float s = 0.f;
    #pragma unroll
    for (int l = 0; l < LFdim; l++) s += p[l*512];
    g_mf[b*512 + k] = s * (1.0f/LFdim);
}

// exact fp32 init: h0 = mf@ihw^T+ihb (split to bf16), c0 = mf@icw^T+icb.
// 128 blocks x 8 stacked units; 256 threads: u=tid&7, 32 batch-groups x 4.
__global__ void __launch_bounds__(256)
init_kernel(const float* __restrict__ ihw, const float* __restrict__ icw,
            const float* __restrict__ ihb, const float* __restrict__ icb) {
    __shared__ float ws[8*512];      // 16 KB: this block's 8 weight rows
    const int nb = blockIdx.x * 8;   // stacked unit base (0..1016)
    const int tid = threadIdx.x;
    for (int i = tid; i < 8*128; i += 256) {    // 1024 float4 groups
        int rr = i >> 7, c4 = (i & 127) * 4;
        int n = nb + rr;
        const float* src = (n < 512) ? (ihw + (size_t)n*512 + c4)
                                     : (icw + (size_t)(n-512)*512 + c4);
        *(float4*)(ws + rr*512 + c4) = *(const float4*)src;
    }
    __syncthreads();

    const int u = tid & 7;
    const int bg = tid >> 3;         // 0..31, 4 batches each
    const int n = nb + u;
    const float bias = (n < 512) ? ihb[n] : icb[n - 512];
    const float* w = ws + u*512;
    const float* m0 = g_mf + (bg*4 + 0)*512;
    const float* m1 = g_mf + (bg*4 + 1)*512;
    const float* m2 = g_mf + (bg*4 + 2)*512;
    const float* m3 = g_mf + (bg*4 + 3)*512;
    float a0 = 0.f, a1 = 0.f, a2 = 0.f, a3 = 0.f;
    #pragma unroll 8
    for (int k = 0; k < 512; k += 4) {
        float4 wv = *(const float4*)(w + k);
        float4 x0 = *(const float4*)(m0 + k);
        float4 x1 = *(const float4*)(m1 + k);
        float4 x2 = *(const float4*)(m2 + k);
        float4 x3 = *(const float4*)(m3 + k);
        a0 = fmaf(wv.x, x0.x, fmaf(wv.y, x0.y, fmaf(wv.z, x0.z, fmaf(wv.w, x0.w, a0))));
        a1 = fmaf(wv.x, x1.x, fmaf(wv.y, x1.y, fmaf(wv.z, x1.z, fmaf(wv.w, x1.w, a1))));
        a2 = fmaf(wv.x, x2.x, fmaf(wv.y, x2.y, fmaf(wv.z, x2.z, fmaf(wv.w, x2.w, a2))));
        a3 = fmaf(wv.x, x3.x, fmaf(wv.y, x3.y, fmaf(wv.z, x3.z, fmaf(wv.w, x3.w, a3))));
    }
    float acc[4] = {a0 + bias, a1 + bias, a2 + bias, a3 + bias};
    #pragma unroll
    for (int i = 0; i < 4; i++) {
        int b = bg*4 + i;
        if (n < 512) {
            __nv_bfloat16 h = __float2bfloat16(acc[i]);
            g_hh0[b*512 + n] = h;
            g_hl0[b*512 + n] = __float2bfloat16(acc[i] - __bfloat162float(h));
        } else {
            g_c[b*512 + n - 512] = acc[i];
        }
    }
}

// ---------------------------------------------------------------------------
// gather embeddings into compact rows (vectorized; zero pads emb & hall16)
__global__ void gather_split_kernel(const float* __restrict__ emb,
                                    const int* __restrict__ cap) {
    int r = blockIdx.x;
    int v = g_map[r];
    int c4 = threadIdx.x * 4;          // 128 threads x 4 = 512
    if (v & 0x10000) {
        uint2 z = make_uint2(0u, 0u);
        *(uint2*)(g_embh + (size_t)r*Edim + c4) = z;
        *(uint2*)(g_embl + (size_t)r*Edim + c4) = z;
        *(uint2*)(g_hall16 + (size_t)r*Hdim + c4) = z;
        return;
    }
    int t = (v >> 8) & 0xFF, b = v & 0xFF;
    int tok = cap[b*Tdim + t];
    float4 x = *(const float4*)(emb + (size_t)tok*Edim + c4);
    float hx = __bfloat162float(__float2bfloat16(x.x));
    float hy = __bfloat162float(__float2bfloat16(x.y));
    float hz = __bfloat162float(__float2bfloat16(x.z));
    float hw = __bfloat162float(__float2bfloat16(x.w));
    *(uint2*)(g_embh + (size_t)r*Edim + c4) = make_uint2(pack_bf2(x.x, x.y), pack_bf2(x.z, x.w));
    *(uint2*)(g_embl + (size_t)r*Edim + c4) =
        make_uint2(pack_bf2(x.x - hx, x.y - hy), pack_bf2(x.z - hz, x.w - hw));
}

// split BOTH recurrent weights with gate permutation: out row 4j+g <- in row g*512+j
// blocks [0,1024): W_ih -> g_wihh/l ; [1024,2048): W_hh -> g_whhh/l
__global__ void split_permute2_kernel(const float* __restrict__ Wih,
                                      const float* __restrict__ Whh) {
    int bi = blockIdx.x;
    const float* W = (bi < 1024) ? Wih : Whh;
    __nv_bfloat16* hi = (bi < 1024) ? g_wihh : g_whhh;
    __nv_bfloat16* lo = (bi < 1024) ? g_wihl : g_whhl;
    int idx = (bi & 1023)*256 + threadIdx.x;
    int r = idx >> 7, c4 = (idx & 127) * 4;
    int j = r >> 2, g = r & 3;
    float4 x = *(const float4*)(W + (size_t)(g*512 + j)*512 + c4);
    float hx = __bfloat162float(__float2bfloat16(x.x));
    float hy = __bfloat162float(__float2bfloat16(x.y));
    float hz = __bfloat162float(__float2bfloat16(x.z));
    float hw = __bfloat162float(__float2bfloat16(x.w));
    *(uint2*)(hi + (size_t)r*512 + c4) = make_uint2(pack_bf2(x.x, x.y), pack_bf2(x.z, x.w));
    *(uint2*)(lo + (size_t)r*512 + c4) =
        make_uint2(pack_bf2(x.x - hx, x.y - hy), pack_bf2(x.z - hz, x.w - hw));
}

// vectorized fp16 convert with 64x prescale (fc_w, single-term)
__global__ void conv4_f16s(const float* __restrict__ s,
                           __half* __restrict__ hi, int n4) {
    int i = blockIdx.x*256 + threadIdx.x;
    if (i >= n4) return;
    float4 x = ((const float4*)s)[i];
    ((uint2*)hi)[i] = make_uint2(pack_h2(x.x*64.f, x.y*64.f), pack_h2(x.z*64.f, x.w*64.f));
}

// ---------------------------------------------------------------------------
// bf16x3 GEMM via mma.sync (gx). Block 128x128, BK=32, 8 warps.
// C[m*N+n] = acc + b1[n]; early-exit m0>=Mc.
#define TILE_B 8192
#define STAGE_B (4*TILE_B)
#define DSM_BYTES (2*STAGE_B)

__global__ void __launch_bounds__(256)
gx_gemm(const __nv_bfloat16* __restrict__ Ah, const __nv_bfloat16* __restrict__ Al,
        const __nv_bfloat16* __restrict__ Bh, const __nv_bfloat16* __restrict__ Bl,
        float* __restrict__ C, const float* __restrict__ b1)
{
    const int m0 = blockIdx.y * 128;
    if (m0 >= g_Mc) return;
    extern __shared__ char smem[];
    const uint32_t sbase = smem_to_u32(smem);
    const int tid = threadIdx.x;
    const int lane = tid & 31, wid = tid >> 5;
    const int wm = wid >> 2, wn = wid & 3;
    const int n0 = blockIdx.x * 128;
    const int N = G4;

    float c[4][4][4];
    #pragma unroll
    for (int i = 0; i < 4; i++)
        #pragma unroll
        for (int j = 0; j < 4; j++)
            { c[i][j][0]=0.f; c[i][j][1]=0.f; c[i][j][2]=0.f; c[i][j][3]=0.f; }

    auto load_stage = [&](int kc, int stage) {
        const int k0 = kc * 32;
        const uint32_t st = sbase + stage * STAGE_B;
        #pragma unroll
        for (int i = 0; i < 2; i++) {
            int chunk = tid + 256*i;
            int r = chunk >> 2, q = chunk & 3;
            uint32_t off = sw_off(r, q);
            size_t ao = (size_t)(m0 + r)*Kdim + k0 + q*8;
            cp16(st + off,            Ah + ao, true);
            cp16(st + TILE_B + off,   Al + ao, true);
            size_t bo = (size_t)(n0 + r)*Kdim + k0 + q*8;
            cp16(st + 2*TILE_B + off, Bh + bo, true);
            cp16(st + 3*TILE_B + off, Bl + bo, true);
        }
        CP_COMMIT();
    };

    const int NK = Kdim / 32;
    load_stage(0, 0);
    for (int kc = 0; kc < NK; kc++) {
        int stage = kc & 1;
        if (kc + 1 < NK) { load_stage(kc + 1, stage ^ 1); CP_WAIT1(); }
        else             { CP_WAIT0(); }
        __syncthreads();
        const uint32_t sa = sbase + stage * STAGE_B;

        #pragma unroll
        for (int kh = 0; kh < 2; kh++) {
            uint32_t aH[4][4], aL[4][4];
            #pragma unroll
            for (int mf = 0; mf < 4; mf++) {
                int row  = wm*64 + mf*16 + (lane & 7) + ((lane >> 3) & 1)*8;
                int kcol = kh*16 + ((lane >> 4) & 1)*8;
                uint32_t off = sw_off(row, kcol >> 3);
                LDSM4(aH[mf], sa + off);
                LDSM4(aL[mf], sa + TILE_B + off);
            }
            uint32_t bH[4][2], bL[4][2];
            #pragma unroll
            for (int np = 0; np < 2; np++) {
                int row  = wn*32 + np*16 + (lane & 7) + ((lane >> 4) & 1)*8;
                int kcol = ((lane >> 3) & 1)*8 + kh*16;
                uint32_t off = sw_off(row, kcol >> 3);
                uint32_t r4[4];
                LDSM4(r4, sa + 2*TILE_B + off);
                bH[np*2][0]=r4[0]; bH[np*2][1]=r4[1];
                bH[np*2+1][0]=r4[2]; bH[np*2+1][1]=r4[3];
                LDSM4(r4, sa + 3*TILE_B + off);
                bL[np*2][0]=r4[0]; bL[np*2][1]=r4[1];
                bL[np*2+1][0]=r4[2]; bL[np*2+1][1]=r4[3];
            }
            #pragma unroll
            for (int mf = 0; mf < 4; mf++)
                #pragma unroll
                for (int nf = 0; nf < 4; nf++) {
                    mma16816(c[mf][nf], aH[mf], bH[nf]);
                    mma16816(c[mf][nf], aH[mf], bL[nf]);
                    mma16816(c[mf][nf], aL[mf], bH[nf]);
                }
        }
        __syncthreads();
    }

    #pragma unroll
    for (int mf = 0; mf < 4; mf++) {
        #pragma unroll
        for (int nf = 0; nf < 4; nf++) {
            int m = m0 + wm*64 + mf*16 + (lane >> 2);
            int n = n0 + wn*32 + nf*8 + 2*(lane & 3);
            #pragma unroll
            for (int half = 0; half < 2; half++) {
                int mm = m + half*8;
                float v0 = c[mf][nf][half*2]   + b1[n];
                float v1 = c[mf][nf][half*2+1] + b1[n+1];
                *(float2*)(C + (size_t)mm*N + n) = make_float2(v0, v1);
            }
        }
    }
}

// ---------------------------------------------------------------------------
// fc GEMM: fp16 single-term, 3-stage pipeline.
// D = hall16 @ fwh16^T / 64 + fc_b for active rows; zeros for masked rows.
#define FC_TILE 8192
#define FC_STAGE (2*FC_TILE)    // A + B
#define FC_DSM (3*FC_STAGE)     // 48 KB

__global__ void __launch_bounds__(256)
fc_gemm(const __half* __restrict__ A, const __half* __restrict__ Bh,
        float* __restrict__ C, const float* __restrict__ b1)
{
    const int m0 = blockIdx.y * 128;
    extern __shared__ char smem[];
    const uint32_t sbase = smem_to_u32(smem);
    const int tid = threadIdx.x;
    const int lane = tid & 31, wid = tid >> 5;
    const int wm = wid >> 2, wn = wid & 3;
    const int n0 = blockIdx.x * 128;
    const int N = Vdim;

    float c[4][4][4];
    #pragma unroll
    for (int i = 0; i < 4; i++)
        #pragma unroll
        for (int j = 0; j < 4; j++)
            { c[i][j][0]=0.f; c[i][j][1]=0.f; c[i][j][2]=0.f; c[i][j][3]=0.f; }

    if (m0 < g_Mc) {   // tiles entirely in pad region skip the GEMM
        auto load_stage = [&](int kc, int stage) {
            const int k0 = kc * 32;
            const uint32_t st = sbase + stage * FC_STAGE;
            #pragma unroll
            for (int i = 0; i < 2; i++) {
                int chunk = tid + 256*i;
                int r = chunk >> 2, q = chunk & 3;
                uint32_t off = sw_off(r, q);
                size_t ao = (size_t)(m0 + r)*Kdim + k0 + q*8;
                cp16(st + off, A + ao, true);
                int nr = n0 + r;
                bool bp = nr < N;
                size_t bo = (size_t)(bp ? nr : (N-1))*Kdim + k0 + q*8;
                cp16(st + FC_TILE + off, Bh + bo, bp);
            }
            CP_COMMIT();
        };

        const int NK = Kdim / 32;   // 16
        load_stage(0, 0);
        load_stage(1, 1);
        for (int kc = 0; kc < NK; kc++) {
            int stage = kc % 3;
            if (kc + 2 < NK)      { load_stage(kc + 2, (kc + 2) % 3); CP_WAIT2(); }
            else if (kc + 1 < NK) { CP_WAIT1(); }
            else                  { CP_WAIT0(); }
            __syncthreads();
            const uint32_t sa = sbase + stage * FC_STAGE;

            #pragma unroll
            for (int kh = 0; kh < 2; kh++) {
                uint32_t aH[4][4];
                #pragma unroll
                for (int mf = 0; mf < 4; mf++) {
                    int row  = wm*64 + mf*16 + (lane & 7) + ((lane >> 3) & 1)*8;
                    int kcol = kh*16 + ((lane >> 4) & 1)*8;
                    LDSM4(aH[mf], sa + sw_off(row, kcol >> 3));
                }
                uint32_t bH[4][2];
                #pragma unroll
                for (int np = 0; np < 2; np++) {
                    int row  = wn*32 + np*16 + (lane & 7) + ((lane >> 4) & 1)*8;
                    int kcol = ((lane >> 3) & 1)*8 + kh*16;
                    uint32_t r4[4];
                    LDSM4(r4, sa + FC_TILE + sw_off(row, kcol >> 3));
                    bH[np*2][0]=r4[0]; bH[np*2][1]=r4[1];
                    bH[np*2+1][0]=r4[2]; bH[np*2+1][1]=r4[3];
                }
                #pragma unroll
                for (int mf = 0; mf < 4; mf++)
                    #pragma unroll
                    for (int nf = 0; nf < 4; nf++)
                        mma16816h(c[mf][nf], aH[mf], bH[nf]);
            }
            __syncthreads();
        }
    }

    const float inv = 0.015625f;   // 1/64
    #pragma unroll
    for (int mf = 0; mf < 4; mf++) {
        #pragma unroll
        for (int nf = 0; nf < 4; nf++) {
            int m = m0 + wm*64 + mf*16 + (lane >> 2);
            int n = n0 + wn*32 + nf*8 + 2*(lane & 3);
            if (n >= N) continue;
            #pragma unroll
            for (int half = 0; half < 2; half++) {
                int mm = m + half*8;
                int v = g_map[mm];
                int t = (v >> 8) & 0xFF, b = v & 0xFF;
                float2 o;
                if (v & 0x10000) {
                    o = make_float2(0.f, 0.f);
                } else {
                    o = make_float2(c[mf][nf][half*2]*inv   + b1[n],
                                    c[mf][nf][half*2+1]*inv + b1[n+1]);
                }
                *(float2*)(C + ((size_t)(b*Tdim + t))*Vdim + n) = o;
            }
        }
    }
}

// ---------------------------------------------------------------------------
// Persistent recurrence: all 32 steps in one launch.
// Grid 128 = 32 nslices x 4 mtiles of 32 rows. W slice resident (128 KB).
// Per-mtile sync groups (32 blocks each); mtile k exits once nact <= 32k.
#define PK_WH    0
#define PK_WL    65536
#define PK_AST   131072          // + stage*4096; lo at +2048
#define PK_GATES 139264          // float[32*66] = 8448 B
#define PK_CST   147712          // float[512]   = 2048 B
#define PK_BYTES 149760

__global__ void __launch_bounds__(256)
persist_step_kernel() {
    extern __shared__ char sm[];
    const uint32_t sbase = smem_to_u32(sm);
    const int tid = threadIdx.x;
    const int lane = tid & 31, wid = tid >> 5;
    const int wm = wid >> 2, wn = wid & 3;   // 2m x 4n warp grid (32 x 64 tile)
    const int nslice = blockIdx.x & 31;
    const int mtile = blockIdx.x >> 5;       // 0..3
    const int n0 = nslice * 64;
    const int m0 = mtile * 32;
    unsigned int* syncc = &g_sync2[mtile * 32];

    // preload W slice: 16 chunks of [64 rows x 32 k], hi+lo (resident)
    {
        int r = tid >> 2, q = tid & 3;
        #pragma unroll
        for (int kc = 0; kc < 16; kc++) {
            uint32_t off = (uint32_t)(kc*4096) + sw_off(r, q);
            size_t go = (size_t)(n0 + r)*Hdim + kc*32 + q*8;
            cp16(sbase + PK_WH + off, g_whhh + go, true);
            cp16(sbase + PK_WL + off, g_whhl + go, true);
        }
        CP_COMMIT();
    }
    float* cst = (float*)(sm + PK_CST);      // [32 rows x 16 units]
    for (int i = tid; i < 512; i += 256) {
        int r = i >> 4, u = i & 15;
        cst[i] = g_c[(m0 + r)*Hdim + (n0 >> 2) + u];
    }
    CP_WAIT0();
    __syncthreads();

    float* gs = (float*)(sm + PK_GATES);
    int scount = 0;

    for (int t = 0; t < Tdim; t++) {
        const int nact = g_nact[t];
        if (mtile > 0 && nact <= m0) break;  // nact non-increasing: done forever
        const __nv_bfloat16* Ah = (t & 1) ? g_hh1 : g_hh0;
        const __nv_bfloat16* Al = (t & 1) ? g_hl1 : g_hl0;
        __nv_bfloat16* Oh = (t & 1) ? g_hh0 : g_hh1;
        __nv_bfloat16* Ol = (t & 1) ? g_hl0 : g_hl1;

        {
            float acc[2][4];                 // nf x 4 (warp tile 16 x 16)
            #pragma unroll
            for (int j = 0; j < 2; j++)
                { acc[j][0]=0.f; acc[j][1]=0.f; acc[j][2]=0.f; acc[j][3]=0.f; }

            // A tile per kc: 32 rows x 32 k, hi (2KB) + lo (2KB)
            auto loadA = [&](int kc, int stage) {
                const uint32_t st = sbase + PK_AST + stage*4096;
                int r = (tid & 127) >> 2, q = tid & 3;
                bool low = tid >= 128;
                const __nv_bfloat16* src = low ? Al : Ah;
                uint32_t doff = low ? 2048u : 0u;
                cp16(st + doff + sw_off(r, q),
                     src + (size_t)(m0 + r)*Hdim + kc*32 + q*8, true);
                CP_COMMIT();
            };
            loadA(0, 0);
            for (int kc = 0; kc < 16; kc++) {
                int stage = kc & 1;
                if (kc + 1 < 16) { loadA(kc + 1, stage ^ 1); CP_WAIT1(); }
                else             { CP_WAIT0(); }
                __syncthreads();
                const uint32_t sa = sbase + PK_AST + stage*4096;
                const uint32_t wbH = sbase + PK_WH + (uint32_t)(kc*4096);
                const uint32_t wbL = sbase + PK_WL + (uint32_t)(kc*4096);
                #pragma unroll
                for (int kh = 0; kh < 2; kh++) {
                    uint32_t aH[4], aL[4];
                    {
                        int row  = wm*16 + (lane & 7) + ((lane >> 3) & 1)*8;
                        int kcol = kh*16 + ((lane >> 4) & 1)*8;
                        uint32_t off = sw_off(row, kcol >> 3);
                        LDSM4(aH, sa + off);
                        LDSM4(aL, sa + 2048 + off);
                    }
                    uint32_t bH[2][2], bL[2][2];
                    {
                        int row  = wn*16 + (lane & 7) + ((lane >> 4) & 1)*8;
                        int kcol = ((lane >> 3) & 1)*8 + kh*16;
                        uint32_t off = sw_off(row, kcol >> 3);
                        uint32_t r4[4];
                        LDSM4(r4, wbH + off);
                        bH[0][0]=r4[0]; bH[0][1]=r4[1]; bH[1][0]=r4[2]; bH[1][1]=r4[3];
                        LDSM4(r4, wbL + off);
                        bL[0][0]=r4[0]; bL[0][1]=r4[1]; bL[1][0]=r4[2]; bL[1][1]=r4[3];
                    }
                    #pragma unroll
                    for (int nf = 0; nf < 2; nf++) {
                        mma16816(acc[nf], aH, bH[nf]);
                        mma16816(acc[nf], aH, bL[nf]);
                        mma16816(acc[nf], aL, bH[nf]);
                    }
                }
                __syncthreads();
            }

            // gates + gx -> smem (stride 66)
            const int goff = g_off[t];
            #pragma unroll
            for (int nf = 0; nf < 2; nf++) {
                int rl = wm*16 + (lane >> 2);
                int nl = wn*16 + nf*8 + 2*(lane & 3);
                #pragma unroll
                for (int half = 0; half < 2; half++) {
                    int rr = rl + half*8;
                    float2 gx2 = *(const float2*)(g_gx + (size_t)(goff + m0 + rr)*G4 + n0 + nl);
                    gs[rr*66 + nl]     = acc[nf][half*2]   + gx2.x;
                    gs[rr*66 + nl + 1] = acc[nf][half*2+1] + gx2.y;
                }
            }
            __syncthreads();

            // cell update: 32 rows x 16 units = 512 items, 2/thread
            #pragma unroll
            for (int p = 0; p < 2; p++) {
                int idx = tid + 256*p;
                int row = idx >> 4, u = idx & 15;
                int rg = m0 + row;
                if (rg < nact) {
                    float gi = gs[row*66 + u*4 + 0];
                    float gf = gs[row*66 + u*4 + 1];
                    float gc = gs[row*66 + u*4 + 2];
                    float go = gs[row*66 + u*4 + 3];
                    float cc = cst[row*16 + u];
                    cc = sigf(gf)*cc + sigf(gi)*tanhf(gc);
                    float hv = sigf(go)*tanhf(cc);
                    cst[row*16 + u] = cc;
                    int jg = (n0 >> 2) + u;
                    __nv_bfloat16 hhi = __float2bfloat16(hv);
                    __nv_bfloat16 hlo = __float2bfloat16(hv - __bfloat162float(hhi));
                    Oh[rg*Hdim + jg] = hhi;
                    Ol[rg*Hdim + jg] = hlo;
                    g_hall16[(size_t)(goff + rg)*Hdim + jg] = __float2half_rn(hv);
                }
            }
        }

        // per-mtile grid sync (32 blocks)
        scount++;
        __syncthreads();
        if (tid == 0) {
            __threadfence();
            atomicAdd(syncc, 1u);
            unsigned target = 32u * (unsigned)scount;
            while (atomicAdd(syncc, 0u) < target) { __nanosleep(32); }
            __threadfence();
        }
        __syncthreads();
    }
}

// ---------------------------------------------------------------------------
extern "C" void kernel_launch(void* const* d_in, const int* in_sizes, int n_in,
                              void* d_out, int out_size) {
    const float* features  = (const float*)d_in[0];
    const int*   captions  = (const int*)  d_in[1];
    const int*   lengths   = (const int*)  d_in[2];
    const float* embedding = (const float*)d_in[3];
    const float* W_ih      = (const float*)d_in[4];
    const float* W_hh      = (const float*)d_in[5];
    const float* b_ih      = (const float*)d_in[6];
    const float* b_hh      = (const float*)d_in[7];
    const float* fc_w      = (const float*)d_in[8];
    const float* fc_b      = (const float*)d_in[9];
    const float* ihw       = (const float*)d_in[10];
    const float* ihb       = (const float*)d_in[11];
    const float* icw       = (const float*)d_in[12];
    const float* icb       = (const float*)d_in[13];
    float* out = (float*)d_out;

    float *gx, *pbias;
    __nv_bfloat16 *embh, *embl, *wihh, *wihl;
    __half *fwh16, *hall16;
    cudaGetSymbolAddress((void**)&gx, g_gx);
    cudaGetSymbolAddress((void**)&pbias, g_pbias);
    cudaGetSymbolAddress((void**)&embh, g_embh); cudaGetSymbolAddress((void**)&embl, g_embl);
    cudaGetSymbolAddress((void**)&wihh, g_wihh); cudaGetSymbolAddress((void**)&wihl, g_wihl);
    cudaGetSymbolAddress((void**)&fwh16, g_fwh16);
    cudaGetSymbolAddress((void**)&hall16, g_hall16);

    cudaFuncSetAttribute(gx_gemm, cudaFuncAttributeMaxDynamicSharedMemorySize, DSM_BYTES);
    cudaFuncSetAttribute(fc_gemm, cudaFuncAttributeMaxDynamicSharedMemorySize, FC_DSM);
    cudaFuncSetAttribute(persist_step_kernel, cudaFuncAttributeMaxDynamicSharedMemorySize, PK_BYTES);

    // 0. row map (active + masked pads, parallel) + biases + sync reset
    setup_kernel<<<1, 256>>>(lengths, b_ih, b_hh);

    // 1. mean pool + exact fp32 init (h0 split-to-bf16 + c0)
    meanpool_kernel<<<Bdim, 512>>>(features);
    init_kernel<<<128, 256>>>(ihw, icw, ihb, icb);

    // 2. fc_w convert (fp16 single-term, 64x prescale)
    conv4_f16s<<<((size_t)Vdim*Hdim/4+255)/256, 256>>>(fc_w, fwh16, Vdim*Hdim/4);

    // 3. remaining operand prep (W_ih + W_hh in one launch)
    gather_split_kernel<<<MT, 128>>>(embedding, captions);
    split_permute2_kernel<<<2048, 256>>>(W_ih, W_hh);

    // 4. gx = emb @ W_ih'^T + pbias (compact rows)
    {
        dim3 grid(G4/128, MT/128);
        gx_gemm<<<grid, 256, DSM_BYTES>>>(embh, embl, wihh, wihl, gx, pbias);
    }

    // 5. full recurrence in ONE persistent launch (128 blocks, 4 mtiles)
    persist_step_kernel<<<128, 256, PK_BYTES>>>();

    // 6. fc projection (fp16 single-term, 1/64 scale) + masked zeros fused
    {
        dim3 grid((Vdim + 127)/128, MT/128);
        fc_gemm<<<grid, 256, FC_DSM>>>(hall16, fwh16, out, fc_b);
    }
}

// round 13
// speedup vs baseline: 6.0980x; 1.0641x over previous
#include <cuda_runtime.h>
#include <cuda_bf16.h>
#include <cuda_fp16.h>
#include <cstdint>
#include <math.h>

#define Bdim 128
#define Tdim 32
#define Edim 512
#define Hdim 512
#define Vdim 10000
#define LFdim 49
#define G4 2048
#define MT 4096
#define Kdim 512

// ---------------- scratch (__device__ globals; no allocs allowed) ----------
__device__ float g_mf[Bdim*Edim];              // fp32 mean-pooled features
__device__ float g_c[Bdim*Hdim];
__device__ float g_gx[(size_t)MT*G4];          // compact rows (bias folded)
__device__ float g_pbias[G4];                  // permuted b_ih+b_hh

__device__ int g_nact[Tdim];
__device__ int g_off[Tdim+1];
__device__ int g_Mc;
__device__ int g_map[MT];   // row -> (t<<8)|b ; bit16 set = masked (zero output)
__device__ unsigned int g_sync2[128];          // per-mtile counters at [mtile*32]

__device__ __half g_h016[Bdim*Hdim];           // initial hidden state (fp16)
__device__ __half g_emb16[(size_t)MT*Edim];    // gathered embeddings (fp16)
__device__ __half g_wih16h[(size_t)G4*Edim], g_wih16l[(size_t)G4*Edim]; // perm, x64
__device__ __half g_whh16h[(size_t)G4*Hdim], g_whh16l[(size_t)G4*Hdim]; // perm, x64
__device__ __half g_fwh16[(size_t)Vdim*Hdim];  // 64x prescaled fp16
__device__ __half g_hall16[(size_t)MT*Hdim];   // compact hidden states, fp16

// ---------------- PTX helpers (sm_80-era: legal on base sm_100) ------------
__device__ __forceinline__ uint32_t smem_to_u32(const void* p) {
    uint32_t a;
    asm("{ .reg .u64 t; cvta.to.shared.u64 t, %1; cvt.u32.u64 %0, t; }" : "=r"(a) : "l"(p));
    return a;
}
__device__ __forceinline__ void cp16(uint32_t dst, const void* src, bool pred) {
    int sz = pred ? 16 : 0;
    asm volatile("cp.async.cg.shared.global [%0], [%1], 16, %2;"
                 :: "r"(dst), "l"(src), "r"(sz) : "memory");
}
#define CP_COMMIT() asm volatile("cp.async.commit_group;" ::: "memory")
#define CP_WAIT2()  asm volatile("cp.async.wait_group 2;" ::: "memory")
#define CP_WAIT1()  asm volatile("cp.async.wait_group 1;" ::: "memory")
#define CP_WAIT0()  asm volatile("cp.async.wait_group 0;" ::: "memory")
#define LDSM4(r, addr) \
    asm volatile("ldmatrix.sync.aligned.m8n8.x4.shared.b16 {%0,%1,%2,%3}, [%4];" \
        : "=r"((r)[0]), "=r"((r)[1]), "=r"((r)[2]), "=r"((r)[3]) : "r"(addr))

__device__ __forceinline__ void mma16816h(float* c, const uint32_t* a, const uint32_t* b) {
    asm volatile("mma.sync.aligned.m16n8k16.row.col.f32.f16.f16.f32 "
        "{%0,%1,%2,%3}, {%4,%5,%6,%7}, {%8,%9}, {%0,%1,%2,%3};"
        : "+f"(c[0]), "+f"(c[1]), "+f"(c[2]), "+f"(c[3])
        : "r"(a[0]), "r"(a[1]), "r"(a[2]), "r"(a[3]), "r"(b[0]), "r"(b[1]));
}

// XOR swizzle for 64B-row tiles: row r, 16B chunk q
__device__ __forceinline__ uint32_t sw_off(int r, int q) {
    return (uint32_t)(r*64 + ((q ^ ((r >> 1) & 3)) << 4));
}

__device__ __forceinline__ float sigf(float x) { return 1.0f / (1.0f + expf(-x)); }

__device__ __forceinline__ uint32_t pack_h2(float a, float b) {
    __half2 v = __floats2half2_rn(a, b);
    return *(uint32_t*)&v;
}

#define INV64 0.015625f

// ---------------------------------------------------------------------------
// setup: n_active(t), offsets, full row map (active + masked pads), biases
__global__ void setup_kernel(const int* __restrict__ lengths,
                             const float* __restrict__ b_ih,
                             const float* __restrict__ b_hh) {
    __shared__ int s_len[Bdim];
    __shared__ int s_moff[Bdim];     // prefix of masked counts per batch
    int tid = threadIdx.x;
    if (tid < 128) g_sync2[tid] = 0u;
    if (tid < Bdim) s_len[tid] = lengths[tid];
    __syncthreads();
    if (tid < Tdim) {
        int cnt = 0;
        for (int b = 0; b < Bdim; b++) cnt += (s_len[b] > tid) ? 1 : 0;
        g_nact[tid] = cnt;
    }
    __syncthreads();
    if (tid == 0) {
        int acc = 0;
        for (int t = 0; t < Tdim; t++) { g_off[t] = acc; acc += g_nact[t]; }
        g_off[Tdim] = acc;
        g_Mc = acc;
        int macc = 0;
        for (int b = 0; b < Bdim; b++) { s_moff[b] = macc; macc += Tdim - s_len[b]; }
    }
    __syncthreads();
    int Mc = g_Mc;
    for (int r = tid; r < Mc; r += 256) {
        int t = 0;
        while (t < Tdim - 1 && r >= g_off[t+1]) t++;
        g_map[r] = (t << 8) | (r - g_off[t]);
    }
    for (int i = tid; i < MT; i += 256) {
        int b = i >> 5, t = i & 31;
        if (t >= s_len[b]) {
            int rp = Mc + s_moff[b] + (t - s_len[b]);
            g_map[rp] = (t << 8) | b | 0x10000;
        }
    }
    for (int i = tid; i < G4; i += 256) {
        int j = i >> 2, g = i & 3;
        g_pbias[i] = b_ih[g*512 + j] + b_hh[g*512 + j];
    }
}

// ---------------------------------------------------------------------------
// mean pool -> fp32
__global__ void meanpool_kernel(const float* __restrict__ features) {
    int b = blockIdx.x, k = threadIdx.x;
    const float* p = features + (size_t)b*LFdim*512 + k;
    float s = 0.f;
    #pragma unroll
    for (int l = 0; l < LFdim; l++) s += p[l*512];
    g_mf[b*512 + k] = s * (1.0f/LFdim);
}

// exact fp32 init GEMM: h0 (-> fp16) and c0 (fp32).
__global__ void __launch_bounds__(256)
init_kernel(const float* __restrict__ ihw, const float* __restrict__ icw,
            const float* __restrict__ ihb, const float* __restrict__ icb) {
    __shared__ float ws[8*512];      // 16 KB: this block's 8 weight rows
    const int nb = blockIdx.x * 8;   // stacked unit base (0..1016)
    const int tid = threadIdx.x;
    for (int i = tid; i < 8*128; i += 256) {
        int rr = i >> 7, c4 = (i & 127) * 4;
        int n = nb + rr;
        const float* src = (n < 512) ? (ihw + (size_t)n*512 + c4)
                                     : (icw + (size_t)(n-512)*512 + c4);
        *(float4*)(ws + rr*512 + c4) = *(const float4*)src;
    }
    __syncthreads();

    const int u = tid & 7;
    const int bg = tid >> 3;
    const int n = nb + u;
    const float bias = (n < 512) ? ihb[n] : icb[n - 512];
    const float* w = ws + u*512;
    const float* m0 = g_mf + (bg*4 + 0)*512;
    const float* m1 = g_mf + (bg*4 + 1)*512;
    const float* m2 = g_mf + (bg*4 + 2)*512;
    const float* m3 = g_mf + (bg*4 + 3)*512;
    float a0 = 0.f, a1 = 0.f, a2 = 0.f, a3 = 0.f;
    #pragma unroll 8
    for (int k = 0; k < 512; k += 4) {
        float4 wv = *(const float4*)(w + k);
        float4 x0 = *(const float4*)(m0 + k);
        float4 x1 = *(const float4*)(m1 + k);
        float4 x2 = *(const float4*)(m2 + k);
        float4 x3 = *(const float4*)(m3 + k);
        a0 = fmaf(wv.x, x0.x, fmaf(wv.y, x0.y, fmaf(wv.z, x0.z, fmaf(wv.w, x0.w, a0))));
        a1 = fmaf(wv.x, x1.x, fmaf(wv.y, x1.y, fmaf(wv.z, x1.z, fmaf(wv.w, x1.w, a1))));
        a2 = fmaf(wv.x, x2.x, fmaf(wv.y, x2.y, fmaf(wv.z, x2.z, fmaf(wv.w, x2.w, a2))));
        a3 = fmaf(wv.x, x3.x, fmaf(wv.y, x3.y, fmaf(wv.z, x3.z, fmaf(wv.w, x3.w, a3))));
    }
    float acc[4] = {a0 + bias, a1 + bias, a2 + bias, a3 + bias};
    #pragma unroll
    for (int i = 0; i < 4; i++) {
        int b = bg*4 + i;
        if (n < 512) g_h016[b*512 + n] = __float2half_rn(acc[i]);
        else         g_c[b*512 + n - 512] = acc[i];
    }
}

// ---------------------------------------------------------------------------
// gather embeddings into compact rows as fp16 (zero pads emb & hall16)
__global__ void gather16_kernel(const float* __restrict__ emb,
                                const int* __restrict__ cap) {
    int r = blockIdx.x;
    int v = g_map[r];
    int c4 = threadIdx.x * 4;          // 128 threads x 4 = 512
    if (v & 0x10000) {
        uint2 z = make_uint2(0u, 0u);
        *(uint2*)(g_emb16 + (size_t)r*Edim + c4) = z;
        *(uint2*)(g_hall16 + (size_t)r*Hdim + c4) = z;
        return;
    }
    int t = (v >> 8) & 0xFF, b = v & 0xFF;
    int tok = cap[b*Tdim + t];
    float4 x = *(const float4*)(emb + (size_t)tok*Edim + c4);
    *(uint2*)(g_emb16 + (size_t)r*Edim + c4) =
        make_uint2(pack_h2(x.x, x.y), pack_h2(x.z, x.w));
}

// split BOTH recurrent weights: gate-permuted, fp16 2-term, x64 prescale
// blocks [0,1024): W_ih ; [1024,2048): W_hh
__global__ void split_permute2_kernel(const float* __restrict__ Wih,
                                      const float* __restrict__ Whh) {
    int bi = blockIdx.x;
    const float* W = (bi < 1024) ? Wih : Whh;
    __half* hi = (bi < 1024) ? g_wih16h : g_whh16h;
    __half* lo = (bi < 1024) ? g_wih16l : g_whh16l;
    int idx = (bi & 1023)*256 + threadIdx.x;
    int r = idx >> 7, c4 = (idx & 127) * 4;
    int j = r >> 2, g = r & 3;
    float4 x = *(const float4*)(W + (size_t)(g*512 + j)*512 + c4);
    x.x *= 64.f; x.y *= 64.f; x.z *= 64.f; x.w *= 64.f;
    float hx = __half2float(__float2half_rn(x.x));
    float hy = __half2float(__float2half_rn(x.y));
    float hz = __half2float(__float2half_rn(x.z));
    float hw = __half2float(__float2half_rn(x.w));
    *(uint2*)(hi + (size_t)r*512 + c4) = make_uint2(pack_h2(x.x, x.y), pack_h2(x.z, x.w));
    *(uint2*)(lo + (size_t)r*512 + c4) =
        make_uint2(pack_h2(x.x - hx, x.y - hy), pack_h2(x.z - hz, x.w - hw));
}

// vectorized fp16 convert with 64x prescale (fc_w, single-term)
__global__ void conv4_f16s(const float* __restrict__ s,
                           __half* __restrict__ hi, int n4) {
    int i = blockIdx.x*256 + threadIdx.x;
    if (i >= n4) return;
    float4 x = ((const float4*)s)[i];
    ((uint2*)hi)[i] = make_uint2(pack_h2(x.x*64.f, x.y*64.f), pack_h2(x.z*64.f, x.w*64.f));
}

// ---------------------------------------------------------------------------
// gx GEMM: fp16 A-single + W-double (x64). C = (A@(Wh+Wl)^T)/64 + pbias.
// Block 128x128, BK=32, 8 warps, double-buffered 3-tile stages.
#define GX_TILE 8192
#define GX_STAGE (3*GX_TILE)
#define GX_DSM (2*GX_STAGE)     // 48 KB

__global__ void __launch_bounds__(256)
gx_gemm(const __half* __restrict__ A, const __half* __restrict__ Bh,
        const __half* __restrict__ Bl, float* __restrict__ C,
        const float* __restrict__ b1)
{
    const int m0 = blockIdx.y * 128;
    if (m0 >= g_Mc) return;
    extern __shared__ char smem[];
    const uint32_t sbase = smem_to_u32(smem);
    const int tid = threadIdx.x;
    const int lane = tid & 31, wid = tid >> 5;
    const int wm = wid >> 2, wn = wid & 3;
    const int n0 = blockIdx.x * 128;
    const int N = G4;

    float c[4][4][4];
    #pragma unroll
    for (int i = 0; i < 4; i++)
        #pragma unroll
        for (int j = 0; j < 4; j++)
            { c[i][j][0]=0.f; c[i][j][1]=0.f; c[i][j][2]=0.f; c[i][j][3]=0.f; }

    auto load_stage = [&](int kc, int stage) {
        const int k0 = kc * 32;
        const uint32_t st = sbase + stage * GX_STAGE;
        #pragma unroll
        for (int i = 0; i < 2; i++) {
            int chunk = tid + 256*i;
            int r = chunk >> 2, q = chunk & 3;
            uint32_t off = sw_off(r, q);
            cp16(st + off, A + (size_t)(m0 + r)*Kdim + k0 + q*8, true);
            size_t bo = (size_t)(n0 + r)*Kdim + k0 + q*8;
            cp16(st + GX_TILE + off,   Bh + bo, true);
            cp16(st + 2*GX_TILE + off, Bl + bo, true);
        }
        CP_COMMIT();
    };

    const int NK = Kdim / 32;
    load_stage(0, 0);
    for (int kc = 0; kc < NK; kc++) {
        int stage = kc & 1;
        if (kc + 1 < NK) { load_stage(kc + 1, stage ^ 1); CP_WAIT1(); }
        else             { CP_WAIT0(); }
        __syncthreads();
        const uint32_t sa = sbase + stage * GX_STAGE;

        #pragma unroll
        for (int kh = 0; kh < 2; kh++) {
            uint32_t aH[4][4];
            #pragma unroll
            for (int mf = 0; mf < 4; mf++) {
                int row  = wm*64 + mf*16 + (lane & 7) + ((lane >> 3) & 1)*8;
                int kcol = kh*16 + ((lane >> 4) & 1)*8;
                LDSM4(aH[mf], sa + sw_off(row, kcol >> 3));
            }
            uint32_t bH[4][2], bL[4][2];
            #pragma unroll
            for (int np = 0; np < 2; np++) {
                int row  = wn*32 + np*16 + (lane & 7) + ((lane >> 4) & 1)*8;
                int kcol = ((lane >> 3) & 1)*8 + kh*16;
                uint32_t off = sw_off(row, kcol >> 3);
                uint32_t r4[4];
                LDSM4(r4, sa + GX_TILE + off);
                bH[np*2][0]=r4[0]; bH[np*2][1]=r4[1];
                bH[np*2+1][0]=r4[2]; bH[np*2+1][1]=r4[3];
                LDSM4(r4, sa + 2*GX_TILE + off);
                bL[np*2][0]=r4[0]; bL[np*2][1]=r4[1];
                bL[np*2+1][0]=r4[2]; bL[np*2+1][1]=r4[3];
            }
            #pragma unroll
            for (int mf = 0; mf < 4; mf++)
                #pragma unroll
                for (int nf = 0; nf < 4; nf++) {
                    mma16816h(c[mf][nf], aH[mf], bH[nf]);
                    mma16816h(c[mf][nf], aH[mf], bL[nf]);
                }
        }
        __syncthreads();
    }

    #pragma unroll
    for (int mf = 0; mf < 4; mf++) {
        #pragma unroll
        for (int nf = 0; nf < 4; nf++) {
            int m = m0 + wm*64 + mf*16 + (lane >> 2);
            int n = n0 + wn*32 + nf*8 + 2*(lane & 3);
            #pragma unroll
            for (int half = 0; half < 2; half++) {
                int mm = m + half*8;
                float v0 = c[mf][nf][half*2]*INV64   + b1[n];
                float v1 = c[mf][nf][half*2+1]*INV64 + b1[n+1];
                *(float2*)(C + (size_t)mm*N + n) = make_float2(v0, v1);
            }
        }
    }
}

// ---------------------------------------------------------------------------
// fc GEMM: fp16 single-term, 3-stage pipeline.
#define FC_TILE 8192
#define FC_STAGE (2*FC_TILE)
#define FC_DSM (3*FC_STAGE)     // 48 KB

__global__ void __launch_bounds__(256)
fc_gemm(const __half* __restrict__ A, const __half* __restrict__ Bh,
        float* __restrict__ C, const float* __restrict__ b1)
{
    const int m0 = blockIdx.y * 128;
    extern __shared__ char smem[];
    const uint32_t sbase = smem_to_u32(smem);
    const int tid = threadIdx.x;
    const int lane = tid & 31, wid = tid >> 5;
    const int wm = wid >> 2, wn = wid & 3;
    const int n0 = blockIdx.x * 128;
    const int N = Vdim;

    float c[4][4][4];
    #pragma unroll
    for (int i = 0; i < 4; i++)
        #pragma unroll
        for (int j = 0; j < 4; j++)
            { c[i][j][0]=0.f; c[i][j][1]=0.f; c[i][j][2]=0.f; c[i][j][3]=0.f; }

    if (m0 < g_Mc) {
        auto load_stage = [&](int kc, int stage) {
            const int k0 = kc * 32;
            const uint32_t st = sbase + stage * FC_STAGE;
            #pragma unroll
            for (int i = 0; i < 2; i++) {
                int chunk = tid + 256*i;
                int r = chunk >> 2, q = chunk & 3;
                uint32_t off = sw_off(r, q);
                cp16(st + off, A + (size_t)(m0 + r)*Kdim + k0 + q*8, true);
                int nr = n0 + r;
                bool bp = nr < N;
                size_t bo = (size_t)(bp ? nr : (N-1))*Kdim + k0 + q*8;
                cp16(st + FC_TILE + off, Bh + bo, bp);
            }
            CP_COMMIT();
        };

        const int NK = Kdim / 32;
        load_stage(0, 0);
        load_stage(1, 1);
        for (int kc = 0; kc < NK; kc++) {
            int stage = kc % 3;
            if (kc + 2 < NK)      { load_stage(kc + 2, (kc + 2) % 3); CP_WAIT2(); }
            else if (kc + 1 < NK) { CP_WAIT1(); }
            else                  { CP_WAIT0(); }
            __syncthreads();
            const uint32_t sa = sbase + stage * FC_STAGE;

            #pragma unroll
            for (int kh = 0; kh < 2; kh++) {
                uint32_t aH[4][4];
                #pragma unroll
                for (int mf = 0; mf < 4; mf++) {
                    int row  = wm*64 + mf*16 + (lane & 7) + ((lane >> 3) & 1)*8;
                    int kcol = kh*16 + ((lane >> 4) & 1)*8;
                    LDSM4(aH[mf], sa + sw_off(row, kcol >> 3));
                }
                uint32_t bH[4][2];
                #pragma unroll
                for (int np = 0; np < 2; np++) {
                    int row  = wn*32 + np*16 + (lane & 7) + ((lane >> 4) & 1)*8;
                    int kcol = ((lane >> 3) & 1)*8 + kh*16;
                    uint32_t r4[4];
                    LDSM4(r4, sa + FC_TILE + sw_off(row, kcol >> 3));
                    bH[np*2][0]=r4[0]; bH[np*2][1]=r4[1];
                    bH[np*2+1][0]=r4[2]; bH[np*2+1][1]=r4[3];
                }
                #pragma unroll
                for (int mf = 0; mf < 4; mf++)
                    #pragma unroll
                    for (int nf = 0; nf < 4; nf++)
                        mma16816h(c[mf][nf], aH[mf], bH[nf]);
            }
            __syncthreads();
        }
    }

    #pragma unroll
    for (int mf = 0; mf < 4; mf++) {
        #pragma unroll
        for (int nf = 0; nf < 4; nf++) {
            int m = m0 + wm*64 + mf*16 + (lane >> 2);
            int n = n0 + wn*32 + nf*8 + 2*(lane & 3);
            if (n >= N) continue;
            #pragma unroll
            for (int half = 0; half < 2; half++) {
                int mm = m + half*8;
                int v = g_map[mm];
                int t = (v >> 8) & 0xFF, b = v & 0xFF;
                float2 o;
                if (v & 0x10000) {
                    o = make_float2(0.f, 0.f);
                } else {
                    o = make_float2(c[mf][nf][half*2]*INV64   + b1[n],
                                    c[mf][nf][half*2+1]*INV64 + b1[n+1]);
                }
                *(float2*)(C + ((size_t)(b*Tdim + t))*Vdim + n) = o;
            }
        }
    }
}

// ---------------------------------------------------------------------------
// Persistent recurrence, fp16: A = h (1-term), W = whh16 hi+lo (x64, resident).
// Grid 128 = 32 nslices x 4 mtiles of 32 rows. Reads prev h from hall16.
#define PK_WH    0
#define PK_WL    65536
#define PK_AST   131072          // + stage*2048 (A hi only, 2 KB/stage)
#define PK_GATES 135424          // float[32*66] = 8448 B
#define PK_CST   143872          // float[512]   = 2048 B
#define PK_BYTES 145920

__global__ void __launch_bounds__(256)
persist_step_kernel() {
    extern __shared__ char sm[];
    const uint32_t sbase = smem_to_u32(sm);
    const int tid = threadIdx.x;
    const int lane = tid & 31, wid = tid >> 5;
    const int wm = wid >> 2, wn = wid & 3;   // 2m x 4n warp grid (32 x 64 tile)
    const int nslice = blockIdx.x & 31;
    const int mtile = blockIdx.x >> 5;       // 0..3
    const int n0 = nslice * 64;
    const int m0 = mtile * 32;
    unsigned int* syncc = &g_sync2[mtile * 32];

    // preload W slice: 16 chunks of [64 rows x 32 k], hi+lo (resident)
    {
        int r = tid >> 2, q = tid & 3;
        #pragma unroll
        for (int kc = 0; kc < 16; kc++) {
            uint32_t off = (uint32_t)(kc*4096) + sw_off(r, q);
            size_t go = (size_t)(n0 + r)*Hdim + kc*32 + q*8;
            cp16(sbase + PK_WH + off, g_whh16h + go, true);
            cp16(sbase + PK_WL + off, g_whh16l + go, true);
        }
        CP_COMMIT();
    }
    float* cst = (float*)(sm + PK_CST);      // [32 rows x 16 units]
    for (int i = tid; i < 512; i += 256) {
        int r = i >> 4, u = i & 15;
        cst[i] = g_c[(m0 + r)*Hdim + (n0 >> 2) + u];
    }
    CP_WAIT0();
    __syncthreads();

    float* gs = (float*)(sm + PK_GATES);
    int scount = 0;

    for (int t = 0; t < Tdim; t++) {
        const int nact = g_nact[t];
        if (mtile > 0 && nact <= m0) break;  // nact non-increasing: done forever
        const __half* Ah = (t == 0) ? g_h016 : (g_hall16 + (size_t)g_off[t-1]*Hdim);

        {
            float acc[2][4];
            #pragma unroll
            for (int j = 0; j < 2; j++)
                { acc[j][0]=0.f; acc[j][1]=0.f; acc[j][2]=0.f; acc[j][3]=0.f; }

            // A tile per kc: 32 rows x 32 k fp16 = 2 KB; 128 threads load
            auto loadA = [&](int kc, int stage) {
                const uint32_t st = sbase + PK_AST + stage*2048;
                if (tid < 128) {
                    int r = tid >> 2, q = tid & 3;
                    cp16(st + sw_off(r, q),
                         Ah + (size_t)(m0 + r)*Hdim + kc*32 + q*8, true);
                }
                CP_COMMIT();
            };
            loadA(0, 0);
            for (int kc = 0; kc < 16; kc++) {
                int stage = kc & 1;
                if (kc + 1 < 16) { loadA(kc + 1, stage ^ 1); CP_WAIT1(); }
                else             { CP_WAIT0(); }
                __syncthreads();
                const uint32_t sa = sbase + PK_AST + stage*2048;
                const uint32_t wbH = sbase + PK_WH + (uint32_t)(kc*4096);
                const uint32_t wbL = sbase + PK_WL + (uint32_t)(kc*4096);
                #pragma unroll
                for (int kh = 0; kh < 2; kh++) {
                    uint32_t aH[4];
                    {
                        int row  = wm*16 + (lane & 7) + ((lane >> 3) & 1)*8;
                        int kcol = kh*16 + ((lane >> 4) & 1)*8;
                        LDSM4(aH, sa + sw_off(row, kcol >> 3));
                    }
                    uint32_t bH[2][2], bL[2][2];
                    {
                        int row  = wn*16 + (lane & 7) + ((lane >> 4) & 1)*8;
                        int kcol = ((lane >> 3) & 1)*8 + kh*16;
                        uint32_t off = sw_off(row, kcol >> 3);
                        uint32_t r4[4];
                        LDSM4(r4, wbH + off);
                        bH[0][0]=r4[0]; bH[0][1]=r4[1]; bH[1][0]=r4[2]; bH[1][1]=r4[3];
                        LDSM4(r4, wbL + off);
                        bL[0][0]=r4[0]; bL[0][1]=r4[1]; bL[1][0]=r4[2]; bL[1][1]=r4[3];
                    }
                    #pragma unroll
                    for (int nf = 0; nf < 2; nf++) {
                        mma16816h(acc[nf], aH, bH[nf]);
                        mma16816h(acc[nf], aH, bL[nf]);
                    }
                }
                __syncthreads();
            }

            // gates*(1/64) + gx -> smem (stride 66)
            const int goff = g_off[t];
            #pragma unroll
            for (int nf = 0; nf < 2; nf++) {
                int rl = wm*16 + (lane >> 2);
                int nl = wn*16 + nf*8 + 2*(lane & 3);
                #pragma unroll
                for (int half = 0; half < 2; half++) {
                    int rr = rl + half*8;
                    float2 gx2 = *(const float2*)(g_gx + (size_t)(goff + m0 + rr)*G4 + n0 + nl);
                    gs[rr*66 + nl]     = acc[nf][half*2]*INV64   + gx2.x;
                    gs[rr*66 + nl + 1] = acc[nf][half*2+1]*INV64 + gx2.y;
                }
            }
            __syncthreads();

            // cell update: 32 rows x 16 units = 512 items, 2/thread
            #pragma unroll
            for (int p = 0; p < 2; p++) {
                int idx = tid + 256*p;
                int row = idx >> 4, u = idx & 15;
                int rg = m0 + row;
                if (rg < nact) {
                    float gi = gs[row*66 + u*4 + 0];
                    float gf = gs[row*66 + u*4 + 1];
                    float gc = gs[row*66 + u*4 + 2];
                    float go = gs[row*66 + u*4 + 3];
                    float cc = cst[row*16 + u];
                    cc = sigf(gf)*cc + sigf(gi)*tanhf(gc);
                    float hv = sigf(go)*tanhf(cc);
                    cst[row*16 + u] = cc;
                    int jg = (n0 >> 2) + u;
                    g_hall16[(size_t)(goff + rg)*Hdim + jg] = __float2half_rn(hv);
                }
            }
        }

        // per-mtile grid sync (32 blocks)
        scount++;
        __syncthreads();
        if (tid == 0) {
            __threadfence();
            atomicAdd(syncc, 1u);
            unsigned target = 32u * (unsigned)scount;
            while (atomicAdd(syncc, 0u) < target) { __nanosleep(32); }
            __threadfence();
        }
        __syncthreads();
    }
}

// ---------------------------------------------------------------------------
extern "C" void kernel_launch(void* const* d_in, const int* in_sizes, int n_in,
                              void* d_out, int out_size) {
    const float* features  = (const float*)d_in[0];
    const int*   captions  = (const int*)  d_in[1];
    const int*   lengths   = (const int*)  d_in[2];
    const float* embedding = (const float*)d_in[3];
    const float* W_ih      = (const float*)d_in[4];
    const float* W_hh      = (const float*)d_in[5];
    const float* b_ih      = (const float*)d_in[6];
    const float* b_hh      = (const float*)d_in[7];
    const float* fc_w      = (const float*)d_in[8];
    const float* fc_b      = (const float*)d_in[9];
    const float* ihw       = (const float*)d_in[10];
    const float* ihb       = (const float*)d_in[11];
    const float* icw       = (const float*)d_in[12];
    const float* icb       = (const float*)d_in[13];
    float* out = (float*)d_out;

    float *gx, *pbias;
    __half *emb16, *wih16h, *wih16l, *fwh16, *hall16;
    cudaGetSymbolAddress((void**)&gx, g_gx);
    cudaGetSymbolAddress((void**)&pbias, g_pbias);
    cudaGetSymbolAddress((void**)&emb16, g_emb16);
    cudaGetSymbolAddress((void**)&wih16h, g_wih16h);
    cudaGetSymbolAddress((void**)&wih16l, g_wih16l);
    cudaGetSymbolAddress((void**)&fwh16, g_fwh16);
    cudaGetSymbolAddress((void**)&hall16, g_hall16);

    cudaFuncSetAttribute(gx_gemm, cudaFuncAttributeMaxDynamicSharedMemorySize, GX_DSM);
    cudaFuncSetAttribute(fc_gemm, cudaFuncAttributeMaxDynamicSharedMemorySize, FC_DSM);
    cudaFuncSetAttribute(persist_step_kernel, cudaFuncAttributeMaxDynamicSharedMemorySize, PK_BYTES);

    // 0. row map + biases + sync reset
    setup_kernel<<<1, 256>>>(lengths, b_ih, b_hh);

    // 1. mean pool + exact fp32 init (h0 -> fp16, c0 fp32)
    meanpool_kernel<<<Bdim, 512>>>(features);
    init_kernel<<<128, 256>>>(ihw, icw, ihb, icb);

    // 2. fc_w convert (fp16 single-term, 64x prescale)
    conv4_f16s<<<((size_t)Vdim*Hdim/4+255)/256, 256>>>(fc_w, fwh16, Vdim*Hdim/4);

    // 3. remaining operand prep
    gather16_kernel<<<MT, 128>>>(embedding, captions);
    split_permute2_kernel<<<2048, 256>>>(W_ih, W_hh);

    // 4. gx = (emb16 @ Wih16'^T)/64 + pbias (compact rows)
    {
        dim3 grid(G4/128, MT/128);
        gx_gemm<<<grid, 256, GX_DSM>>>(emb16, wih16h, wih16l, gx, pbias);
    }

    // 5. full recurrence in ONE persistent launch (128 blocks, 4 mtiles)
    persist_step_kernel<<<128, 256, PK_BYTES>>>();

    // 6. fc projection (fp16 single-term, 1/64 scale) + masked zeros fused
    {
        dim3 grid((Vdim + 127)/128, MT/128);
        fc_gemm<<<grid, 256, FC_DSM>>>(hall16, fwh16, out, fc_b);
    }
}